// round 3
// baseline (speedup 1.0000x reference)
#include <cuda_runtime.h>
#include <cuda_bf16.h>

// Problem constants (fixed by the reference)
#define T_MAX  8192
#define D_DIM  1024
#define E_NUM  8
#define IMOE   1024
#define ISH    4096

// ---------------------------------------------------------------------------
// Device scratch (allocation-free rule: __device__ globals)
// ---------------------------------------------------------------------------
__device__ __align__(256) float g_bufA [2u * T_MAX * IMOE]; // gathered gate-preact -> h (in place)
__device__ __align__(256) float g_y    [2u * T_MAX * IMOE]; // gathered down-proj outputs
__device__ __align__(256) float g_bufSh[(size_t)T_MAX * ISH]; // shared gate-preact -> h (in place)
__device__ __align__(256) float g_ysh  [(size_t)T_MAX * D_DIM]; // shared down-proj output

__device__ int   g_counts[E_NUM];
__device__ int   g_fill[E_NUM];
__device__ int   g_offs[E_NUM];
__device__ int   g_topE[2 * T_MAX];
__device__ float g_topW[2 * T_MAX];
__device__ float g_sgate[T_MAX];
__device__ int   g_gatherTok[2 * T_MAX];
__device__ int   g_slotRow[2 * T_MAX];

// ---------------------------------------------------------------------------
// Packed f32x2 helpers (FFMA2 — 2x fp32 FMA throughput vs 3-reg FFMA on B300)
// ---------------------------------------------------------------------------
__device__ __forceinline__ void fma2(unsigned long long& d, unsigned long long a,
                                     unsigned long long b) {
    asm("fma.rn.f32x2 %0, %1, %2, %0;" : "+l"(d) : "l"(a), "l"(b));
}
__device__ __forceinline__ unsigned long long rep2(float a) {
    unsigned long long r;
    asm("mov.b64 %0, {%1, %1};" : "=l"(r) : "f"(a));
    return r;
}
__device__ __forceinline__ float2 unpack2(unsigned long long v) {
    float2 f;
    asm("mov.b64 {%0, %1}, %2;" : "=f"(f.x), "=f"(f.y) : "l"(v));
    return f;
}

// ---------------------------------------------------------------------------
// 1) zero per-call metadata (graph replays must be stateless)
// ---------------------------------------------------------------------------
__global__ void zero_meta_kernel() {
    int i = threadIdx.x;
    if (i < E_NUM) { g_counts[i] = 0; g_fill[i] = 0; }
}

// ---------------------------------------------------------------------------
// 2) router: logits, softmax, top-2, renorm weights, shared gate, counts
//    one warp per token
// ---------------------------------------------------------------------------
__global__ void router_kernel(const float* __restrict__ x,
                              const float* __restrict__ gw,
                              const float* __restrict__ sgw,
                              float* __restrict__ logits_out,
                              int write_logits, int T) {
    int gwarp = (blockIdx.x * blockDim.x + threadIdx.x) >> 5;
    int lane  = threadIdx.x & 31;
    if (gwarp >= T) return;
    const float* xr = x + (size_t)gwarp * D_DIM;

    float acc[9];
#pragma unroll
    for (int i = 0; i < 9; ++i) acc[i] = 0.f;

    for (int d = lane; d < D_DIM; d += 32) {
        float xv = xr[d];
        const float4* g4 = (const float4*)(gw + (size_t)d * E_NUM);
        float4 w0 = g4[0], w1 = g4[1];
        acc[0] += xv * w0.x; acc[1] += xv * w0.y;
        acc[2] += xv * w0.z; acc[3] += xv * w0.w;
        acc[4] += xv * w1.x; acc[5] += xv * w1.y;
        acc[6] += xv * w1.z; acc[7] += xv * w1.w;
        acc[8] += xv * sgw[d];
    }
#pragma unroll
    for (int o = 16; o; o >>= 1)
#pragma unroll
        for (int i = 0; i < 9; ++i) acc[i] += __shfl_xor_sync(0xffffffffu, acc[i], o);

    if (lane == 0) {
        float mx = acc[0];
#pragma unroll
        for (int e = 1; e < E_NUM; ++e) mx = fmaxf(mx, acc[e]);
        float p[E_NUM], s = 0.f;
#pragma unroll
        for (int e = 0; e < E_NUM; ++e) { p[e] = expf(acc[e] - mx); s += p[e]; }
        float inv = 1.f / s;
#pragma unroll
        for (int e = 0; e < E_NUM; ++e) p[e] *= inv;

        int i0 = 0;
#pragma unroll
        for (int e = 1; e < E_NUM; ++e) if (p[e] > p[i0]) i0 = e;
        int i1 = (i0 == 0) ? 1 : 0;
#pragma unroll
        for (int e = 0; e < E_NUM; ++e) if (e != i0 && p[e] > p[i1]) i1 = e;

        float w0 = p[i0], w1 = p[i1];
        float invs = 1.f / fmaxf(w0 + w1, 1e-6f);
        g_topE[2 * gwarp]     = i0;
        g_topE[2 * gwarp + 1] = i1;
        g_topW[2 * gwarp]     = w0 * invs;
        g_topW[2 * gwarp + 1] = w1 * invs;
        g_sgate[gwarp] = 1.f / (1.f + expf(-acc[8]));
        atomicAdd(&g_counts[i0], 1);
        atomicAdd(&g_counts[i1], 1);
        if (write_logits) {
#pragma unroll
            for (int e = 0; e < E_NUM; ++e)
                logits_out[(size_t)gwarp * E_NUM + e] = acc[e];
        }
    }
}

// ---------------------------------------------------------------------------
// 3) exclusive scan of counts (tiny)
// ---------------------------------------------------------------------------
__global__ void scan_kernel() {
    if (threadIdx.x == 0) {
        int s = 0;
        for (int e = 0; e < E_NUM; ++e) { g_offs[e] = s; s += g_counts[e]; }
    }
}

// ---------------------------------------------------------------------------
// 4) gather: token -> expert-sorted row, and inverse slot map
// ---------------------------------------------------------------------------
__global__ void gather_kernel(int T) {
    int t = blockIdx.x * blockDim.x + threadIdx.x;
    if (t >= T) return;
#pragma unroll
    for (int k = 0; k < 2; ++k) {
        int e = g_topE[2 * t + k];
        int p = atomicAdd(&g_fill[e], 1);
        int row = g_offs[e] + p;
        g_gatherTok[row] = t;
        g_slotRow[2 * t + k] = row;
    }
}

// ---------------------------------------------------------------------------
// 5) SGEMM: 128x128x8 tile, 256 threads, 8x8/thread, double-buffered smem,
//    packed f32x2 FMAs. Supports: gathered A rows, per-expert (blockIdx.z)
//    weights/row-ranges, and fused silu(gate)*up epilogue (MODE==1).
// ---------------------------------------------------------------------------
template <int MODE> // 0: C = acc   1: C = silu(C_old) * acc
__global__ __launch_bounds__(256)
void sgemm_kernel(const float* __restrict__ A, const float* __restrict__ B,
                  float* __restrict__ C,
                  const int* __restrict__ gatherIdx, // may be null
                  const int* __restrict__ counts,    // null => M = Mfixed
                  const int* __restrict__ offs,
                  int Mfixed, int N, int K, long long bStride) {
    int e = blockIdx.z;
    int M, rowbase;
    if (counts) { M = counts[e]; rowbase = offs[e]; }
    else        { M = Mfixed;    rowbase = 0; }

    int bm = blockIdx.y * 128;
    if (bm >= M) return;
    int bn = blockIdx.x * 128;
    const float* Bp = B + (long long)e * bStride;

    __shared__ __align__(16) float As[2][8][128];
    __shared__ __align__(16) float Bs[2][8][128];

    int tid  = threadIdx.x;
    int arow = tid >> 1, acol = (tid & 1) * 4;
    int brow = tid >> 5, bcol = (tid & 31) * 4;

    int r = bm + arow;
    bool avalid = r < M;
    long long aoff = 0;
    if (avalid) {
        int grow = gatherIdx ? gatherIdx[rowbase + r] : (rowbase + r);
        aoff = (long long)grow * K + acol;
    }
    long long boff = (long long)brow * N + bn + bcol;

    float4 av = avalid ? *(const float4*)(A + aoff) : make_float4(0.f, 0.f, 0.f, 0.f);
    float4 bv = *(const float4*)(Bp + boff);
    As[0][acol + 0][arow] = av.x; As[0][acol + 1][arow] = av.y;
    As[0][acol + 2][arow] = av.z; As[0][acol + 3][arow] = av.w;
    *(float4*)&Bs[0][brow][bcol] = bv;
    __syncthreads();

    unsigned long long acc2[8][4];
#pragma unroll
    for (int i = 0; i < 8; ++i)
#pragma unroll
        for (int j = 0; j < 4; ++j) acc2[i][j] = 0ull;

    int tm = (tid >> 4) * 8;
    int tn = (tid & 15) * 8;
    int nt = K / 8;

    for (int kt = 0; kt < nt; ++kt) {
        int cur = kt & 1;
        float4 avn, bvn;
        bool more = (kt + 1) < nt;
        if (more) {
            avn = avalid ? *(const float4*)(A + aoff + (long long)(kt + 1) * 8)
                         : make_float4(0.f, 0.f, 0.f, 0.f);
            bvn = *(const float4*)(Bp + boff + (long long)(kt + 1) * 8 * N);
        }
#pragma unroll
        for (int k = 0; k < 8; ++k) {
            const float* asrc = &As[cur][k][tm];
            float4 a0 = *(const float4*)(asrc);
            float4 a1 = *(const float4*)(asrc + 4);
            const unsigned long long* bsrc =
                (const unsigned long long*)&Bs[cur][k][tn];
            unsigned long long b2[4] = {bsrc[0], bsrc[1], bsrc[2], bsrc[3]};
            float a[8] = {a0.x, a0.y, a0.z, a0.w, a1.x, a1.y, a1.z, a1.w};
#pragma unroll
            for (int i = 0; i < 8; ++i) {
                unsigned long long aa = rep2(a[i]);
#pragma unroll
                for (int j = 0; j < 4; ++j) fma2(acc2[i][j], aa, b2[j]);
            }
        }
        if (more) {
            int nxt = cur ^ 1;
            As[nxt][acol + 0][arow] = avn.x; As[nxt][acol + 1][arow] = avn.y;
            As[nxt][acol + 2][arow] = avn.z; As[nxt][acol + 3][arow] = avn.w;
            *(float4*)&Bs[nxt][brow][bcol] = bvn;
            __syncthreads();
        }
    }

    // epilogue
#pragma unroll
    for (int i = 0; i < 8; ++i) {
        int rr = bm + tm + i;
        if (rr >= M) break;
        float* crow = C + (long long)(rowbase + rr) * N + bn + tn;
#pragma unroll
        for (int j2 = 0; j2 < 4; ++j2) {
            float2 v = unpack2(acc2[i][j2]);
            if (MODE == 0) {
                *(float2*)(crow + 2 * j2) = v;
            } else {
                float2 g = *(const float2*)(crow + 2 * j2);
                float sx = g.x / (1.f + expf(-g.x));
                float sy = g.y / (1.f + expf(-g.y));
                float2 o;
                o.x = sx * v.x;
                o.y = sy * v.y;
                *(float2*)(crow + 2 * j2) = o;
            }
        }
    }
}

// ---------------------------------------------------------------------------
// 6) combine: out[t] = w0*y[r0] + w1*y[r1] + sgate*ysh[t]
// ---------------------------------------------------------------------------
__global__ void combine_kernel(float* __restrict__ out, int T) {
    int idx = blockIdx.x * blockDim.x + threadIdx.x;
    int total = T * (D_DIM / 4);
    if (idx >= total) return;
    int t = idx >> 8;  // D_DIM/4 = 256
    int c = idx & 255;
    int r0 = g_slotRow[2 * t], r1 = g_slotRow[2 * t + 1];
    float w0 = g_topW[2 * t], w1 = g_topW[2 * t + 1];
    float sgt = g_sgate[t];
    const float4* y4 = (const float4*)g_y;
    const float4* s4 = (const float4*)g_ysh;
    float4 a  = y4[(size_t)r0 * 256 + c];
    float4 b  = y4[(size_t)r1 * 256 + c];
    float4 sh = s4[(size_t)t * 256 + c];
    float4 o;
    o.x = w0 * a.x + w1 * b.x + sgt * sh.x;
    o.y = w0 * a.y + w1 * b.y + sgt * sh.y;
    o.z = w0 * a.z + w1 * b.z + sgt * sh.z;
    o.w = w0 * a.w + w1 * b.w + sgt * sh.w;
    ((float4*)out)[idx] = o;
}

// ---------------------------------------------------------------------------
// host launcher — graph-capturable, allocation-free
// ---------------------------------------------------------------------------
extern "C" void kernel_launch(void* const* d_in, const int* in_sizes, int n_in,
                              void* d_out, int out_size) {
    const float* x   = (const float*)d_in[0]; // [T, D]
    const float* gw  = (const float*)d_in[1]; // [D, E]
    const float* eg  = (const float*)d_in[2]; // [E, D, IMOE]
    const float* eu  = (const float*)d_in[3]; // [E, D, IMOE]
    const float* ed  = (const float*)d_in[4]; // [E, IMOE, D]
    const float* sg  = (const float*)d_in[5]; // [D, ISH]
    const float* su  = (const float*)d_in[6]; // [D, ISH]
    const float* sd  = (const float*)d_in[7]; // [ISH, D]
    const float* sgw = (const float*)d_in[8]; // [D, 1]
    float* out = (float*)d_out;

    int T = in_sizes[0] / D_DIM;

    float *bufA, *yb, *bufSh, *ysh;
    int *gtok, *cnts, *offs;
    cudaGetSymbolAddress((void**)&bufA,  g_bufA);
    cudaGetSymbolAddress((void**)&yb,    g_y);
    cudaGetSymbolAddress((void**)&bufSh, g_bufSh);
    cudaGetSymbolAddress((void**)&ysh,   g_ysh);
    cudaGetSymbolAddress((void**)&gtok,  g_gatherTok);
    cudaGetSymbolAddress((void**)&cnts,  g_counts);
    cudaGetSymbolAddress((void**)&offs,  g_offs);

    int write_logits = (out_size > T * D_DIM) ? 1 : 0;
    float* logits_out = out + (size_t)T * D_DIM;

    zero_meta_kernel<<<1, 32>>>();
    router_kernel<<<(T * 32 + 255) / 256, 256>>>(x, gw, sgw, logits_out,
                                                 write_logits, T);
    scan_kernel<<<1, 32>>>();
    gather_kernel<<<(T + 255) / 256, 256>>>(T);

    int mt = (T + 127) / 128;

    // MoE experts: gate -> bufA ; up (silu fuse) -> bufA ; down -> y
    dim3 gMoE(IMOE / 128, mt, E_NUM);
    sgemm_kernel<0><<<gMoE, 256>>>(x, eg, bufA, gtok, cnts, offs,
                                   0, IMOE, D_DIM, (long long)D_DIM * IMOE);
    sgemm_kernel<1><<<gMoE, 256>>>(x, eu, bufA, gtok, cnts, offs,
                                   0, IMOE, D_DIM, (long long)D_DIM * IMOE);
    dim3 gMoED(D_DIM / 128, mt, E_NUM);
    sgemm_kernel<0><<<gMoED, 256>>>(bufA, ed, yb, nullptr, cnts, offs,
                                    0, D_DIM, IMOE, (long long)IMOE * D_DIM);

    // Shared expert: gate -> bufSh ; up (silu fuse) -> bufSh ; down -> ysh
    dim3 gShGU(ISH / 128, mt, 1);
    sgemm_kernel<0><<<gShGU, 256>>>(x, sg, bufSh, nullptr, nullptr, nullptr,
                                    T, ISH, D_DIM, 0);
    sgemm_kernel<1><<<gShGU, 256>>>(x, su, bufSh, nullptr, nullptr, nullptr,
                                    T, ISH, D_DIM, 0);
    dim3 gShD(D_DIM / 128, mt, 1);
    sgemm_kernel<0><<<gShD, 256>>>(bufSh, sd, ysh, nullptr, nullptr, nullptr,
                                   T, D_DIM, ISH, 0);

    combine_kernel<<<(T * (D_DIM / 4) + 255) / 256, 256>>>(out, T);
}

// round 5
// speedup vs baseline: 2.7990x; 2.7990x over previous
#include <cuda_runtime.h>
#include <cuda_bf16.h>
#include <cstdint>

#define TKN      8192
#define D_DIM    1024
#define E_NUM    8
#define IMOE     1024
#define ISH      4096
#define MAXROWS  17408
#define MAXTILES 136
#define NSTAGE   4
#define STAGE_SZ 32768
#define SMEM_SZ  (NSTAGE * STAGE_SZ)

// ---------------- helpers ----------------
__device__ __forceinline__ uint32_t smem_u32(const void* p) {
    uint32_t a;
    asm("{ .reg .u64 t; cvta.to.shared.u64 t, %1; cvt.u32.u64 %0, t; }" : "=r"(a) : "l"(p));
    return a;
}
__device__ __forceinline__ void cpa16(uint32_t s, const void* g) {
    asm volatile("cp.async.cg.shared.global [%0], [%1], 16;" :: "r"(s), "l"(g));
}
#define CP_COMMIT() asm volatile("cp.async.commit_group;" ::: "memory")
#define CP_WAIT2()  asm volatile("cp.async.wait_group 2;" ::: "memory")

#define LDSM4(R, addr) \
    asm volatile("ldmatrix.sync.aligned.m8n8.x4.shared.b16 {%0,%1,%2,%3}, [%4];" \
        : "=r"((R)[0]), "=r"((R)[1]), "=r"((R)[2]), "=r"((R)[3]) : "r"(addr))

#define MMA16816(C, A, B0, B1) \
    asm volatile("mma.sync.aligned.m16n8k16.row.col.f32.bf16.bf16.f32 " \
        "{%0,%1,%2,%3},{%4,%5,%6,%7},{%8,%9},{%0,%1,%2,%3};" \
        : "+f"((C)[0]), "+f"((C)[1]), "+f"((C)[2]), "+f"((C)[3]) \
        : "r"((A)[0]), "r"((A)[1]), "r"((A)[2]), "r"((A)[3]), "r"(B0), "r"(B1))

// swizzled byte offset of 16B chunk (row r in [0,128), k8-group c8 in [0,4))
__device__ __forceinline__ uint32_t swz(int r, int c8) {
    return (uint32_t)(((r >> 1) * 128) + (((((r & 1) * 4 + c8) ^ ((r >> 1) & 7))) << 4));
}

// ---------------- device scratch ----------------
__device__ __align__(256) __nv_bfloat16 g_xs_hi[(size_t)TKN * D_DIM];
__device__ __align__(256) __nv_bfloat16 g_xs_lo[(size_t)TKN * D_DIM];
__device__ __align__(256) __nv_bfloat16 g_h_hi [(size_t)MAXROWS * IMOE];
__device__ __align__(256) __nv_bfloat16 g_h_lo [(size_t)MAXROWS * IMOE];
__device__ __align__(256) __nv_bfloat16 g_hs_hi[(size_t)TKN * ISH];
__device__ __align__(256) __nv_bfloat16 g_hs_lo[(size_t)TKN * ISH];
__device__ __align__(256) float g_y  [(size_t)MAXROWS * D_DIM];
__device__ __align__(256) float g_ysh[(size_t)TKN * D_DIM];
__device__ __align__(256) __nv_bfloat16 g_Bgu_hi [(size_t)E_NUM * 2 * IMOE * D_DIM];
__device__ __align__(256) __nv_bfloat16 g_Bgu_lo [(size_t)E_NUM * 2 * IMOE * D_DIM];
__device__ __align__(256) __nv_bfloat16 g_Bd_hi  [(size_t)E_NUM * D_DIM * IMOE];
__device__ __align__(256) __nv_bfloat16 g_Bd_lo  [(size_t)E_NUM * D_DIM * IMOE];
__device__ __align__(256) __nv_bfloat16 g_Bgsh_hi[(size_t)2 * ISH * D_DIM];
__device__ __align__(256) __nv_bfloat16 g_Bgsh_lo[(size_t)2 * ISH * D_DIM];
__device__ __align__(256) __nv_bfloat16 g_Bdsh_hi[(size_t)D_DIM * ISH];
__device__ __align__(256) __nv_bfloat16 g_Bdsh_lo[(size_t)D_DIM * ISH];

__device__ int   g_counts[E_NUM];
__device__ int   g_fill[E_NUM];
__device__ int   g_offs[E_NUM];
__device__ int   g_topE[2 * TKN];
__device__ float g_topW[2 * TKN];
__device__ float g_sgate[TKN];
__device__ int   g_gatherTok[MAXROWS];
__device__ int   g_slotRow[2 * TKN];
__device__ int   g_tileExpert[MAXTILES];

// ---------------- small kernels ----------------
__global__ void zero_meta_kernel() {
    int i = blockIdx.x * blockDim.x + threadIdx.x;
    if (i < MAXROWS) g_gatherTok[i] = 0;
    if (i < E_NUM) { g_counts[i] = 0; g_fill[i] = 0; }
    if (i < MAXTILES) g_tileExpert[i] = -1;
}

__global__ void router_kernel(const float* __restrict__ x, const float* __restrict__ gw,
                              const float* __restrict__ sgw, float* __restrict__ logits_out,
                              int write_logits, int T) {
    int gwarp = (blockIdx.x * blockDim.x + threadIdx.x) >> 5;
    int lane  = threadIdx.x & 31;
    if (gwarp >= T) return;
    const float* xr = x + (size_t)gwarp * D_DIM;
    float acc[9];
#pragma unroll
    for (int i = 0; i < 9; ++i) acc[i] = 0.f;
    for (int d = lane; d < D_DIM; d += 32) {
        float xv = xr[d];
        const float4* g4 = (const float4*)(gw + (size_t)d * E_NUM);
        float4 w0 = g4[0], w1 = g4[1];
        acc[0] += xv * w0.x; acc[1] += xv * w0.y; acc[2] += xv * w0.z; acc[3] += xv * w0.w;
        acc[4] += xv * w1.x; acc[5] += xv * w1.y; acc[6] += xv * w1.z; acc[7] += xv * w1.w;
        acc[8] += xv * sgw[d];
    }
#pragma unroll
    for (int o = 16; o; o >>= 1)
#pragma unroll
        for (int i = 0; i < 9; ++i) acc[i] += __shfl_xor_sync(0xffffffffu, acc[i], o);
    if (lane == 0) {
        float mx = acc[0];
#pragma unroll
        for (int e = 1; e < E_NUM; ++e) mx = fmaxf(mx, acc[e]);
        float p[E_NUM], s = 0.f;
#pragma unroll
        for (int e = 0; e < E_NUM; ++e) { p[e] = expf(acc[e] - mx); s += p[e]; }
        float inv = 1.f / s;
#pragma unroll
        for (int e = 0; e < E_NUM; ++e) p[e] *= inv;
        int i0 = 0;
#pragma unroll
        for (int e = 1; e < E_NUM; ++e) if (p[e] > p[i0]) i0 = e;
        int i1 = (i0 == 0) ? 1 : 0;
#pragma unroll
        for (int e = 0; e < E_NUM; ++e) if (e != i0 && p[e] > p[i1]) i1 = e;
        float w0 = p[i0], w1 = p[i1];
        float invs = 1.f / fmaxf(w0 + w1, 1e-6f);
        g_topE[2 * gwarp] = i0; g_topE[2 * gwarp + 1] = i1;
        g_topW[2 * gwarp] = w0 * invs; g_topW[2 * gwarp + 1] = w1 * invs;
        g_sgate[gwarp] = 1.f / (1.f + expf(-acc[8]));
        atomicAdd(&g_counts[i0], 1);
        atomicAdd(&g_counts[i1], 1);
        if (write_logits) {
#pragma unroll
            for (int e = 0; e < E_NUM; ++e)
                logits_out[(size_t)gwarp * E_NUM + e] = acc[e];
        }
    }
}

__global__ void scan_kernel() {
    if (threadIdx.x == 0) {
        int s = 0;
        for (int e = 0; e < E_NUM; ++e) {
            g_offs[e] = s;
            int tl = (g_counts[e] + 127) >> 7;
            for (int t = 0; t < tl; ++t) g_tileExpert[(s >> 7) + t] = e;
            s += tl << 7;
        }
    }
}

__global__ void gather_kernel(int T) {
    int t = blockIdx.x * blockDim.x + threadIdx.x;
    if (t >= T) return;
#pragma unroll
    for (int k = 0; k < 2; ++k) {
        int e = g_topE[2 * t + k];
        int p = atomicAdd(&g_fill[e], 1);
        int row = g_offs[e] + p;
        g_gatherTok[row] = t;
        g_slotRow[2 * t + k] = row;
    }
}

__global__ void convx_kernel(const float* __restrict__ x, __nv_bfloat16* __restrict__ hi,
                             __nv_bfloat16* __restrict__ lo, int n2) {
    int i = blockIdx.x * blockDim.x + threadIdx.x;
    if (i >= n2) return;
    float2 v = ((const float2*)x)[i];
    __nv_bfloat16 h0 = __float2bfloat16(v.x), h1 = __float2bfloat16(v.y);
    __nv_bfloat16 l0 = __float2bfloat16(v.x - __bfloat162float(h0));
    __nv_bfloat16 l1 = __float2bfloat16(v.y - __bfloat162float(h1));
    ((unsigned*)hi)[i] = ((unsigned)__bfloat16_as_ushort(h1) << 16) | __bfloat16_as_ushort(h0);
    ((unsigned*)lo)[i] = ((unsigned)__bfloat16_as_ushort(l1) << 16) | __bfloat16_as_ushort(l0);
}

// weights: src[e][k][n] fp32 -> dst[e][n*rowMul+rowAdd][k] split bf16 (k-major rows)
__global__ __launch_bounds__(256)
void wtrans_kernel(const float* __restrict__ src, __nv_bfloat16* __restrict__ dhi,
                   __nv_bfloat16* __restrict__ dlo, int Ks, int Ns,
                   long long srcE, long long dstE, int rowMul, int rowAdd) {
    src += (long long)blockIdx.z * srcE;
    dhi += (long long)blockIdx.z * dstE;
    dlo += (long long)blockIdx.z * dstE;
    int tk0 = blockIdx.y * 32, tn0 = blockIdx.x * 32;
    __shared__ float tile[32][33];
    int tx = threadIdx.x & 31, ty = threadIdx.x >> 5;
#pragma unroll
    for (int r = 0; r < 4; ++r) {
        int k = ty + r * 8;
        tile[k][tx] = src[(long long)(tk0 + k) * Ns + tn0 + tx];
    }
    __syncthreads();
    int kk = (threadIdx.x & 7) * 4;
    int nn = threadIdx.x >> 3;
    long long drow = (long long)((tn0 + nn) * rowMul + rowAdd) * Ks + tk0 + kk;
    __align__(8) unsigned short hv[4], lv[4];
#pragma unroll
    for (int q = 0; q < 4; ++q) {
        float v = tile[kk + q][nn];
        __nv_bfloat16 h = __float2bfloat16(v);
        __nv_bfloat16 l = __float2bfloat16(v - __bfloat162float(h));
        hv[q] = __bfloat16_as_ushort(h);
        lv[q] = __bfloat16_as_ushort(l);
    }
    *(uint2*)(dhi + drow) = *(uint2*)hv;
    *(uint2*)(dlo + drow) = *(uint2*)lv;
}

// ---------------- HMMA split-bf16 GEMM ----------------
// CTA tile 128x128, BK=32, 4-stage cp.async pipeline, 256 threads (2x4 warps,
// warp tile 64x32). 3 MMA passes: Ah*Bh + Ah*Bl + Al*Bh (fp32 accum).
// Stage layout: Ah @0, Al @8192, Bh @16384, Bl @24576 (each 128x32 bf16 swizzled).
// MODE 0: Cf[(rowbase+m)*Nout + bn+n] = acc
// MODE 1: adjacent cols (even=gate, odd=up) -> silu(g)*u -> split-bf16 planes
//         H*[(rowbase+m)*Nout + (bn+n)/2]
template <int MODE>
__global__ __launch_bounds__(256, 1)
void hgemm(const __nv_bfloat16* __restrict__ Ahi, const __nv_bfloat16* __restrict__ Alo,
           const __nv_bfloat16* __restrict__ Bhi, const __nv_bfloat16* __restrict__ Blo,
           long long bStride, float* __restrict__ Cf,
           __nv_bfloat16* __restrict__ Hhi, __nv_bfloat16* __restrict__ Hlo,
           const int* __restrict__ gTok, const int* __restrict__ tileE,
           int K, int Nout) {
    int e = 0;
    if (tileE) { e = tileE[blockIdx.y]; if (e < 0) return; }
    int rowbase = blockIdx.y * 128;
    int bn = blockIdx.x * 128;
    const char* pAh = (const char*)Ahi;
    const char* pAl = (const char*)Alo;
    const char* pBh = (const char*)(Bhi + (long long)e * bStride);
    const char* pBl = (const char*)(Blo + (long long)e * bStride);

    extern __shared__ __align__(1024) char smem[];
    uint32_t sb = smem_u32(smem);
    int tid = threadIdx.x;

    // -------- loader precompute: 2 chunks/thread/plane --------
    size_t aB[2], bB[2];
    uint32_t dS[2];
#pragma unroll
    for (int i = 0; i < 2; ++i) {
        int q = tid + 256 * i, r = q >> 2, c8 = q & 3;
        int ar = rowbase + r;
        int tok = gTok ? gTok[ar] : ar;
        aB[i] = ((size_t)tok * K + c8 * 8) * 2;
        bB[i] = ((size_t)(bn + r) * K + c8 * 8) * 2;
        dS[i] = swz(r, c8);
    }
    auto issue = [&](int s, int c) {
        uint32_t st = sb + s * STAGE_SZ;
        size_t off = (size_t)c * 64;
#pragma unroll
        for (int i = 0; i < 2; ++i) cpa16(st + dS[i],         pAh + aB[i] + off);
#pragma unroll
        for (int i = 0; i < 2; ++i) cpa16(st + 8192  + dS[i], pAl + aB[i] + off);
#pragma unroll
        for (int i = 0; i < 2; ++i) cpa16(st + 16384 + dS[i], pBh + bB[i] + off);
#pragma unroll
        for (int i = 0; i < 2; ++i) cpa16(st + 24576 + dS[i], pBl + bB[i] + off);
    };

    // -------- compute precompute --------
    int lane = tid & 31, w = tid >> 5;
    int wm = (w & 1) * 64, wn = (w >> 1) * 32;
    uint32_t aAd[4][2], aBd[2][2];
#pragma unroll
    for (int mi = 0; mi < 4; ++mi)
#pragma unroll
        for (int h = 0; h < 2; ++h) {
            int row = wm + mi * 16 + (lane & 15);
            int c8 = 2 * h + (lane >> 4);
            aAd[mi][h] = swz(row, c8);
        }
#pragma unroll
    for (int np = 0; np < 2; ++np)
#pragma unroll
        for (int h = 0; h < 2; ++h) {
            int row = wn + np * 16 + (lane & 7) + ((lane >> 4) << 3);
            int c8 = 2 * h + ((lane >> 3) & 1);
            aBd[np][h] = swz(row, c8);
        }

    float acc[4][4][4];
#pragma unroll
    for (int mi = 0; mi < 4; ++mi)
#pragma unroll
        for (int nj = 0; nj < 4; ++nj)
#pragma unroll
            for (int q = 0; q < 4; ++q) acc[mi][nj][q] = 0.f;

    int NC = K >> 5;

    // prologue: stages 0..NSTAGE-2
#pragma unroll
    for (int s = 0; s < NSTAGE - 1; ++s) { issue(s, s); CP_COMMIT(); }

    for (int c = 0; c < NC; ++c) {
        CP_WAIT2();
        __syncthreads();
        uint32_t st = sb + (c & (NSTAGE - 1)) * STAGE_SZ;
#pragma unroll
        for (int h = 0; h < 2; ++h) {
            uint32_t ah[4][4], al[4][4], bh[4][2], bl[4][2];
#pragma unroll
            for (int mi = 0; mi < 4; ++mi) LDSM4(ah[mi], st + aAd[mi][h]);
#pragma unroll
            for (int mi = 0; mi < 4; ++mi) LDSM4(al[mi], st + 8192 + aAd[mi][h]);
#pragma unroll
            for (int np = 0; np < 2; ++np) {
                uint32_t q[4];
                LDSM4(q, st + 16384 + aBd[np][h]);
                bh[2 * np][0] = q[0]; bh[2 * np][1] = q[1];
                bh[2 * np + 1][0] = q[2]; bh[2 * np + 1][1] = q[3];
                LDSM4(q, st + 24576 + aBd[np][h]);
                bl[2 * np][0] = q[0]; bl[2 * np][1] = q[1];
                bl[2 * np + 1][0] = q[2]; bl[2 * np + 1][1] = q[3];
            }
#pragma unroll
            for (int mi = 0; mi < 4; ++mi)
#pragma unroll
                for (int nj = 0; nj < 4; ++nj)
                    MMA16816(acc[mi][nj], ah[mi], bh[nj][0], bh[nj][1]);
#pragma unroll
            for (int mi = 0; mi < 4; ++mi)
#pragma unroll
                for (int nj = 0; nj < 4; ++nj)
                    MMA16816(acc[mi][nj], ah[mi], bl[nj][0], bl[nj][1]);
#pragma unroll
            for (int mi = 0; mi < 4; ++mi)
#pragma unroll
                for (int nj = 0; nj < 4; ++nj)
                    MMA16816(acc[mi][nj], al[mi], bh[nj][0], bh[nj][1]);
        }
        __syncthreads();
        int pf = c + NSTAGE - 1;
        if (pf < NC) issue(pf & (NSTAGE - 1), pf);
        CP_COMMIT();
    }

    // -------- epilogue --------
#pragma unroll
    for (int mi = 0; mi < 4; ++mi) {
        int r0 = rowbase + wm + mi * 16 + (lane >> 2);
#pragma unroll
        for (int nj = 0; nj < 4; ++nj) {
            if (MODE == 0) {
                int col = bn + wn + nj * 8 + (lane & 3) * 2;
                float2 v0 = make_float2(acc[mi][nj][0], acc[mi][nj][1]);
                float2 v1 = make_float2(acc[mi][nj][2], acc[mi][nj][3]);
                *(float2*)(Cf + (size_t)r0 * Nout + col) = v0;
                *(float2*)(Cf + (size_t)(r0 + 8) * Nout + col) = v1;
            } else {
                int oc = ((bn + wn) >> 1) + nj * 4 + (lane & 3);
                float g0 = acc[mi][nj][0], u0 = acc[mi][nj][1];
                float g1 = acc[mi][nj][2], u1 = acc[mi][nj][3];
                float v0 = g0 / (1.f + expf(-g0)) * u0;
                float v1 = g1 / (1.f + expf(-g1)) * u1;
                __nv_bfloat16 h0 = __float2bfloat16(v0);
                __nv_bfloat16 l0 = __float2bfloat16(v0 - __bfloat162float(h0));
                __nv_bfloat16 h1 = __float2bfloat16(v1);
                __nv_bfloat16 l1 = __float2bfloat16(v1 - __bfloat162float(h1));
                Hhi[(size_t)r0 * Nout + oc] = h0;
                Hlo[(size_t)r0 * Nout + oc] = l0;
                Hhi[(size_t)(r0 + 8) * Nout + oc] = h1;
                Hlo[(size_t)(r0 + 8) * Nout + oc] = l1;
            }
        }
    }
}

__global__ void combine_kernel(float* __restrict__ out, int T) {
    int idx = blockIdx.x * blockDim.x + threadIdx.x;
    int total = T * (D_DIM / 4);
    if (idx >= total) return;
    int t = idx >> 8;
    int c = idx & 255;
    int r0 = g_slotRow[2 * t], r1 = g_slotRow[2 * t + 1];
    float w0 = g_topW[2 * t], w1 = g_topW[2 * t + 1];
    float sgt = g_sgate[t];
    const float4* y4 = (const float4*)g_y;
    const float4* s4 = (const float4*)g_ysh;
    float4 a = y4[(size_t)r0 * 256 + c];
    float4 b = y4[(size_t)r1 * 256 + c];
    float4 sh = s4[(size_t)t * 256 + c];
    float4 o;
    o.x = w0 * a.x + w1 * b.x + sgt * sh.x;
    o.y = w0 * a.y + w1 * b.y + sgt * sh.y;
    o.z = w0 * a.z + w1 * b.z + sgt * sh.z;
    o.w = w0 * a.w + w1 * b.w + sgt * sh.w;
    ((float4*)out)[idx] = o;
}

// ---------------- launcher ----------------
extern "C" void kernel_launch(void* const* d_in, const int* in_sizes, int n_in,
                              void* d_out, int out_size) {
    const float* x   = (const float*)d_in[0];
    const float* gw  = (const float*)d_in[1];
    const float* eg  = (const float*)d_in[2];
    const float* eu  = (const float*)d_in[3];
    const float* ed  = (const float*)d_in[4];
    const float* sg  = (const float*)d_in[5];
    const float* su  = (const float*)d_in[6];
    const float* sd  = (const float*)d_in[7];
    const float* sgw = (const float*)d_in[8];
    float* out = (float*)d_out;
    int T = in_sizes[0] / D_DIM;

    __nv_bfloat16 *xsh, *xsl, *hh, *hl, *hsh, *hsl;
    __nv_bfloat16 *bguh, *bgul, *bdh, *bdl, *bgshh, *bgshl, *bdshh, *bdshl;
    float *yb, *ysh;
    int *gtok, *tileE;
    cudaGetSymbolAddress((void**)&xsh, g_xs_hi);   cudaGetSymbolAddress((void**)&xsl, g_xs_lo);
    cudaGetSymbolAddress((void**)&hh, g_h_hi);     cudaGetSymbolAddress((void**)&hl, g_h_lo);
    cudaGetSymbolAddress((void**)&hsh, g_hs_hi);   cudaGetSymbolAddress((void**)&hsl, g_hs_lo);
    cudaGetSymbolAddress((void**)&bguh, g_Bgu_hi); cudaGetSymbolAddress((void**)&bgul, g_Bgu_lo);
    cudaGetSymbolAddress((void**)&bdh, g_Bd_hi);   cudaGetSymbolAddress((void**)&bdl, g_Bd_lo);
    cudaGetSymbolAddress((void**)&bgshh, g_Bgsh_hi); cudaGetSymbolAddress((void**)&bgshl, g_Bgsh_lo);
    cudaGetSymbolAddress((void**)&bdshh, g_Bdsh_hi); cudaGetSymbolAddress((void**)&bdshl, g_Bdsh_lo);
    cudaGetSymbolAddress((void**)&yb, g_y);        cudaGetSymbolAddress((void**)&ysh, g_ysh);
    cudaGetSymbolAddress((void**)&gtok, g_gatherTok);
    cudaGetSymbolAddress((void**)&tileE, g_tileExpert);

    cudaFuncSetAttribute(hgemm<0>, cudaFuncAttributeMaxDynamicSharedMemorySize, SMEM_SZ);
    cudaFuncSetAttribute(hgemm<1>, cudaFuncAttributeMaxDynamicSharedMemorySize, SMEM_SZ);

    int write_logits = (out_size > T * D_DIM) ? 1 : 0;
    float* logits_out = out + (size_t)T * D_DIM;

    zero_meta_kernel<<<(MAXROWS + 255) / 256, 256>>>();
    router_kernel<<<(T * 32 + 255) / 256, 256>>>(x, gw, sgw, logits_out, write_logits, T);
    scan_kernel<<<1, 32>>>();
    gather_kernel<<<(T + 255) / 256, 256>>>(T);
    convx_kernel<<<(T * D_DIM / 2 + 255) / 256, 256>>>(x, xsh, xsl, T * D_DIM / 2);

    // weight prep (transpose + split; gate/up interleaved into even/odd rows)
    wtrans_kernel<<<dim3(IMOE / 32, D_DIM / 32, E_NUM), 256>>>(
        eg, bguh, bgul, D_DIM, IMOE, (long long)D_DIM * IMOE, 2LL * IMOE * D_DIM, 2, 0);
    wtrans_kernel<<<dim3(IMOE / 32, D_DIM / 32, E_NUM), 256>>>(
        eu, bguh, bgul, D_DIM, IMOE, (long long)D_DIM * IMOE, 2LL * IMOE * D_DIM, 2, 1);
    wtrans_kernel<<<dim3(D_DIM / 32, IMOE / 32, E_NUM), 256>>>(
        ed, bdh, bdl, IMOE, D_DIM, (long long)IMOE * D_DIM, (long long)D_DIM * IMOE, 1, 0);
    wtrans_kernel<<<dim3(ISH / 32, D_DIM / 32, 1), 256>>>(
        sg, bgshh, bgshl, D_DIM, ISH, 0, 0, 2, 0);
    wtrans_kernel<<<dim3(ISH / 32, D_DIM / 32, 1), 256>>>(
        su, bgshh, bgshl, D_DIM, ISH, 0, 0, 2, 1);
    wtrans_kernel<<<dim3(D_DIM / 32, ISH / 32, 1), 256>>>(
        sd, bdshh, bdshl, ISH, D_DIM, 0, 0, 1, 0);

    // MoE: gate+up interleaved (N=2048) -> h planes ; down -> y
    hgemm<1><<<dim3(2 * IMOE / 128, MAXTILES), 256, SMEM_SZ>>>(
        xsh, xsl, bguh, bgul, 2LL * IMOE * D_DIM, nullptr, hh, hl, gtok, tileE, D_DIM, IMOE);
    hgemm<0><<<dim3(D_DIM / 128, MAXTILES), 256, SMEM_SZ>>>(
        hh, hl, bdh, bdl, (long long)D_DIM * IMOE, yb, nullptr, nullptr, nullptr, tileE, IMOE, D_DIM);

    // shared expert
    hgemm<1><<<dim3(2 * ISH / 128, T / 128), 256, SMEM_SZ>>>(
        xsh, xsl, bgshh, bgshl, 0, nullptr, hsh, hsl, nullptr, nullptr, D_DIM, ISH);
    hgemm<0><<<dim3(D_DIM / 128, T / 128), 256, SMEM_SZ>>>(
        hsh, hsl, bdshh, bdshl, 0, ysh, nullptr, nullptr, nullptr, nullptr, ISH, D_DIM);

    combine_kernel<<<(T * (D_DIM / 4) + 255) / 256, 256>>>(out, T);
}

// round 6
// speedup vs baseline: 6.5500x; 2.3401x over previous
#include <cuda_runtime.h>
#include <cuda_bf16.h>
#include <cuda_fp16.h>
#include <cstdint>

#define TKN      8192
#define D_DIM    1024
#define E_NUM    8
#define IMOE     1024
#define ISH      4096
#define MAXROWS  17408
#define MAXTILES 136
#define NSTAGE   4
#define STAGE_SZ 24576          // A 8KB + B 16KB
#define SMEM_SZ  (NSTAGE * STAGE_SZ)

// ---------------- helpers ----------------
__device__ __forceinline__ uint32_t smem_u32(const void* p) {
    uint32_t a;
    asm("{ .reg .u64 t; cvta.to.shared.u64 t, %1; cvt.u32.u64 %0, t; }" : "=r"(a) : "l"(p));
    return a;
}
__device__ __forceinline__ void cpa16(uint32_t s, const void* g) {
    asm volatile("cp.async.cg.shared.global [%0], [%1], 16;" :: "r"(s), "l"(g));
}
#define CP_COMMIT() asm volatile("cp.async.commit_group;" ::: "memory")
#define CP_WAIT2()  asm volatile("cp.async.wait_group 2;" ::: "memory")

#define LDSM4(R, addr) \
    asm volatile("ldmatrix.sync.aligned.m8n8.x4.shared.b16 {%0,%1,%2,%3}, [%4];" \
        : "=r"((R)[0]), "=r"((R)[1]), "=r"((R)[2]), "=r"((R)[3]) : "r"(addr))

#define MMAF16(C, A, B0, B1) \
    asm volatile("mma.sync.aligned.m16n8k16.row.col.f32.f16.f16.f32 " \
        "{%0,%1,%2,%3},{%4,%5,%6,%7},{%8,%9},{%0,%1,%2,%3};" \
        : "+f"((C)[0]), "+f"((C)[1]), "+f"((C)[2]), "+f"((C)[3]) \
        : "r"((A)[0]), "r"((A)[1]), "r"((A)[2]), "r"((A)[3]), "r"(B0), "r"(B1))

// swizzled byte offset of 16B chunk (row r, k8-group c8 in [0,4)); pattern
// repeats every 16 rows, conflict-free for both store and ldmatrix phases
__device__ __forceinline__ uint32_t swz(int r, int c8) {
    return (uint32_t)(((r >> 1) * 128) + (((((r & 1) * 4 + c8) ^ ((r >> 1) & 7))) << 4));
}

// ---------------- device scratch ----------------
__device__ __align__(256) __half g_xs [(size_t)TKN * D_DIM];
__device__ __align__(256) __half g_h  [(size_t)MAXROWS * IMOE];
__device__ __align__(256) __half g_hs [(size_t)TKN * ISH];
__device__ __align__(256) float  g_y  [(size_t)MAXROWS * D_DIM];
__device__ __align__(256) float  g_ysh[(size_t)TKN * D_DIM];
__device__ __align__(256) __half g_Bgu [(size_t)E_NUM * 2 * IMOE * D_DIM];
__device__ __align__(256) __half g_Bd  [(size_t)E_NUM * D_DIM * IMOE];
__device__ __align__(256) __half g_Bgsh[(size_t)2 * ISH * D_DIM];
__device__ __align__(256) __half g_Bdsh[(size_t)D_DIM * ISH];

__device__ int   g_counts[E_NUM];
__device__ int   g_fill[E_NUM];
__device__ int   g_offs[E_NUM];
__device__ int   g_topE[2 * TKN];
__device__ float g_topW[2 * TKN];
__device__ float g_sgate[TKN];
__device__ int   g_gatherTok[MAXROWS];
__device__ int   g_slotRow[2 * TKN];
__device__ int   g_tileExpert[MAXTILES];

// ---------------- small kernels ----------------
__global__ void zero_meta_kernel() {
    int i = blockIdx.x * blockDim.x + threadIdx.x;
    if (i < MAXROWS) g_gatherTok[i] = 0;
    if (i < E_NUM) { g_counts[i] = 0; g_fill[i] = 0; }
    if (i < MAXTILES) g_tileExpert[i] = -1;
}

__global__ void router_kernel(const float* __restrict__ x, const float* __restrict__ gw,
                              const float* __restrict__ sgw, float* __restrict__ logits_out,
                              int write_logits, int T) {
    int gwarp = (blockIdx.x * blockDim.x + threadIdx.x) >> 5;
    int lane  = threadIdx.x & 31;
    if (gwarp >= T) return;
    const float* xr = x + (size_t)gwarp * D_DIM;
    float acc[9];
#pragma unroll
    for (int i = 0; i < 9; ++i) acc[i] = 0.f;
    for (int d = lane; d < D_DIM; d += 32) {
        float xv = xr[d];
        const float4* g4 = (const float4*)(gw + (size_t)d * E_NUM);
        float4 w0 = g4[0], w1 = g4[1];
        acc[0] += xv * w0.x; acc[1] += xv * w0.y; acc[2] += xv * w0.z; acc[3] += xv * w0.w;
        acc[4] += xv * w1.x; acc[5] += xv * w1.y; acc[6] += xv * w1.z; acc[7] += xv * w1.w;
        acc[8] += xv * sgw[d];
    }
#pragma unroll
    for (int o = 16; o; o >>= 1)
#pragma unroll
        for (int i = 0; i < 9; ++i) acc[i] += __shfl_xor_sync(0xffffffffu, acc[i], o);
    if (lane == 0) {
        float mx = acc[0];
#pragma unroll
        for (int e = 1; e < E_NUM; ++e) mx = fmaxf(mx, acc[e]);
        float p[E_NUM], s = 0.f;
#pragma unroll
        for (int e = 0; e < E_NUM; ++e) { p[e] = expf(acc[e] - mx); s += p[e]; }
        float inv = 1.f / s;
#pragma unroll
        for (int e = 0; e < E_NUM; ++e) p[e] *= inv;
        int i0 = 0;
#pragma unroll
        for (int e = 1; e < E_NUM; ++e) if (p[e] > p[i0]) i0 = e;
        int i1 = (i0 == 0) ? 1 : 0;
#pragma unroll
        for (int e = 0; e < E_NUM; ++e) if (e != i0 && p[e] > p[i1]) i1 = e;
        float w0 = p[i0], w1 = p[i1];
        float invs = 1.f / fmaxf(w0 + w1, 1e-6f);
        g_topE[2 * gwarp] = i0; g_topE[2 * gwarp + 1] = i1;
        g_topW[2 * gwarp] = w0 * invs; g_topW[2 * gwarp + 1] = w1 * invs;
        g_sgate[gwarp] = 1.f / (1.f + expf(-acc[8]));
        atomicAdd(&g_counts[i0], 1);
        atomicAdd(&g_counts[i1], 1);
        if (write_logits) {
#pragma unroll
            for (int e = 0; e < E_NUM; ++e)
                logits_out[(size_t)gwarp * E_NUM + e] = acc[e];
        }
    }
}

__global__ void scan_kernel() {
    if (threadIdx.x == 0) {
        int s = 0;
        for (int e = 0; e < E_NUM; ++e) {
            g_offs[e] = s;
            int tl = (g_counts[e] + 127) >> 7;
            for (int t = 0; t < tl; ++t) g_tileExpert[(s >> 7) + t] = e;
            s += tl << 7;
        }
    }
}

__global__ void gather_kernel(int T) {
    int t = blockIdx.x * blockDim.x + threadIdx.x;
    if (t >= T) return;
#pragma unroll
    for (int k = 0; k < 2; ++k) {
        int e = g_topE[2 * t + k];
        int p = atomicAdd(&g_fill[e], 1);
        int row = g_offs[e] + p;
        g_gatherTok[row] = t;
        g_slotRow[2 * t + k] = row;
    }
}

__global__ void convx_kernel(const float* __restrict__ x, __half* __restrict__ xo, int n2) {
    int i = blockIdx.x * blockDim.x + threadIdx.x;
    if (i >= n2) return;
    float2 v = ((const float2*)x)[i];
    ((__half2*)xo)[i] = __floats2half2_rn(v.x, v.y);
}

// weights: src[e][k][n] fp32 -> dst[e][n*rowMul+rowAdd][k] fp16 (k-major rows)
__global__ __launch_bounds__(256)
void wtrans_kernel(const float* __restrict__ src, __half* __restrict__ dst,
                   int Ks, int Ns, long long srcE, long long dstE,
                   int rowMul, int rowAdd) {
    src += (long long)blockIdx.z * srcE;
    dst += (long long)blockIdx.z * dstE;
    int tk0 = blockIdx.y * 32, tn0 = blockIdx.x * 32;
    __shared__ float tile[32][33];
    int tx = threadIdx.x & 31, ty = threadIdx.x >> 5;
#pragma unroll
    for (int r = 0; r < 4; ++r) {
        int k = ty + r * 8;
        tile[k][tx] = src[(long long)(tk0 + k) * Ns + tn0 + tx];
    }
    __syncthreads();
    int kk = (threadIdx.x & 7) * 4;
    int nn = threadIdx.x >> 3;
    long long drow = (long long)((tn0 + nn) * rowMul + rowAdd) * Ks + tk0 + kk;
    __align__(8) unsigned short hv[4];
#pragma unroll
    for (int q = 0; q < 4; ++q)
        hv[q] = __half_as_ushort(__float2half(tile[kk + q][nn]));
    *(uint2*)(dst + drow) = *(uint2*)hv;
}

// ---------------- HMMA fp16 GEMM ----------------
// CTA tile 128x256, BK=32, 4-stage cp.async pipeline, 256 threads (8 warps,
// 2x4, warp tile 64x64). Single fp16 pass, fp32 accumulate.
// Stage layout: A @0 (128x32), B @8192 (256x32), both fp16 swizzled.
// MODE 0: Cf[(rowbase+m)*Nout + bn+n] = acc
// MODE 1: adjacent cols (even=gate, odd=up) -> silu(g)*u -> fp16 plane
//         H[(rowbase+m)*Nout + (bn+n)/2]
template <int MODE>
__global__ __launch_bounds__(256, 1)
void hgemm(const __half* __restrict__ A, const __half* __restrict__ B,
           long long bStride, float* __restrict__ Cf, __half* __restrict__ H,
           const int* __restrict__ gTok, const int* __restrict__ tileE,
           int K, int Nout) {
    int e = 0;
    if (tileE) { e = tileE[blockIdx.y]; if (e < 0) return; }
    int rowbase = blockIdx.y * 128;
    int bn = blockIdx.x * 256;
    const char* pA = (const char*)A;
    const char* pB = (const char*)(B + (long long)e * bStride);

    extern __shared__ __align__(1024) char smem[];
    uint32_t sb = smem_u32(smem);
    int tid = threadIdx.x;

    // -------- loader precompute: A 2 chunks, B 4 chunks per thread --------
    size_t aB[2], bB[4];
    uint32_t dA[2], dB[4];
#pragma unroll
    for (int i = 0; i < 2; ++i) {
        int q = tid + 256 * i, r = q >> 2, c8 = q & 3;
        int ar = rowbase + r;
        int tok = gTok ? gTok[ar] : ar;
        aB[i] = ((size_t)tok * K + c8 * 8) * 2;
        dA[i] = swz(r, c8);
    }
#pragma unroll
    for (int i = 0; i < 4; ++i) {
        int q = tid + 256 * i, r = q >> 2, c8 = q & 3;
        bB[i] = ((size_t)(bn + r) * K + c8 * 8) * 2;
        dB[i] = 8192 + swz(r, c8);
    }
    auto issue = [&](int s, int c) {
        uint32_t st = sb + s * STAGE_SZ;
        size_t off = (size_t)c * 64;
#pragma unroll
        for (int i = 0; i < 2; ++i) cpa16(st + dA[i], pA + aB[i] + off);
#pragma unroll
        for (int i = 0; i < 4; ++i) cpa16(st + dB[i], pB + bB[i] + off);
    };

    // -------- compute precompute --------
    int lane = tid & 31, w = tid >> 5;
    int wm = (w & 1) * 64, wn = (w >> 1) * 64;
    uint32_t aAd[4][2], aBd[4][2];
#pragma unroll
    for (int mi = 0; mi < 4; ++mi)
#pragma unroll
        for (int h = 0; h < 2; ++h) {
            int row = wm + mi * 16 + (lane & 15);
            int c8 = 2 * h + (lane >> 4);
            aAd[mi][h] = swz(row, c8);
        }
#pragma unroll
    for (int np = 0; np < 4; ++np)
#pragma unroll
        for (int h = 0; h < 2; ++h) {
            int row = wn + np * 16 + (lane & 7) + ((lane >> 4) << 3);
            int c8 = 2 * h + ((lane >> 3) & 1);
            aBd[np][h] = 8192 + swz(row, c8);
        }

    float acc[4][8][4];
#pragma unroll
    for (int mi = 0; mi < 4; ++mi)
#pragma unroll
        for (int nj = 0; nj < 8; ++nj)
#pragma unroll
            for (int q = 0; q < 4; ++q) acc[mi][nj][q] = 0.f;

    int NC = K >> 5;

#pragma unroll
    for (int s = 0; s < NSTAGE - 1; ++s) { issue(s, s); CP_COMMIT(); }

    for (int c = 0; c < NC; ++c) {
        CP_WAIT2();
        __syncthreads();
        uint32_t st = sb + (c & (NSTAGE - 1)) * STAGE_SZ;
#pragma unroll
        for (int h = 0; h < 2; ++h) {
            uint32_t a[4][4], b[8][2];
#pragma unroll
            for (int mi = 0; mi < 4; ++mi) LDSM4(a[mi], st + aAd[mi][h]);
#pragma unroll
            for (int np = 0; np < 4; ++np) {
                uint32_t q[4];
                LDSM4(q, st + aBd[np][h]);
                b[2 * np][0] = q[0]; b[2 * np][1] = q[1];
                b[2 * np + 1][0] = q[2]; b[2 * np + 1][1] = q[3];
            }
#pragma unroll
            for (int mi = 0; mi < 4; ++mi)
#pragma unroll
                for (int nj = 0; nj < 8; ++nj)
                    MMAF16(acc[mi][nj], a[mi], b[nj][0], b[nj][1]);
        }
        __syncthreads();
        int pf = c + NSTAGE - 1;
        if (pf < NC) issue(pf & (NSTAGE - 1), pf);
        CP_COMMIT();
    }

    // -------- epilogue --------
#pragma unroll
    for (int mi = 0; mi < 4; ++mi) {
        int r0 = rowbase + wm + mi * 16 + (lane >> 2);
#pragma unroll
        for (int nj = 0; nj < 8; ++nj) {
            if (MODE == 0) {
                int col = bn + wn + nj * 8 + (lane & 3) * 2;
                *(float2*)(Cf + (size_t)r0 * Nout + col) =
                    make_float2(acc[mi][nj][0], acc[mi][nj][1]);
                *(float2*)(Cf + (size_t)(r0 + 8) * Nout + col) =
                    make_float2(acc[mi][nj][2], acc[mi][nj][3]);
            } else {
                int oc = ((bn + wn) >> 1) + nj * 4 + (lane & 3);
                float g0 = acc[mi][nj][0], u0 = acc[mi][nj][1];
                float g1 = acc[mi][nj][2], u1 = acc[mi][nj][3];
                float v0 = g0 / (1.f + expf(-g0)) * u0;
                float v1 = g1 / (1.f + expf(-g1)) * u1;
                H[(size_t)r0 * Nout + oc] = __float2half(v0);
                H[(size_t)(r0 + 8) * Nout + oc] = __float2half(v1);
            }
        }
    }
}

__global__ void combine_kernel(float* __restrict__ out, int T) {
    int idx = blockIdx.x * blockDim.x + threadIdx.x;
    int total = T * (D_DIM / 4);
    if (idx >= total) return;
    int t = idx >> 8;
    int c = idx & 255;
    int r0 = g_slotRow[2 * t], r1 = g_slotRow[2 * t + 1];
    float w0 = g_topW[2 * t], w1 = g_topW[2 * t + 1];
    float sgt = g_sgate[t];
    const float4* y4 = (const float4*)g_y;
    const float4* s4 = (const float4*)g_ysh;
    float4 a = y4[(size_t)r0 * 256 + c];
    float4 b = y4[(size_t)r1 * 256 + c];
    float4 sh = s4[(size_t)t * 256 + c];
    float4 o;
    o.x = w0 * a.x + w1 * b.x + sgt * sh.x;
    o.y = w0 * a.y + w1 * b.y + sgt * sh.y;
    o.z = w0 * a.z + w1 * b.z + sgt * sh.z;
    o.w = w0 * a.w + w1 * b.w + sgt * sh.w;
    ((float4*)out)[idx] = o;
}

// ---------------- launcher ----------------
extern "C" void kernel_launch(void* const* d_in, const int* in_sizes, int n_in,
                              void* d_out, int out_size) {
    const float* x   = (const float*)d_in[0];
    const float* gw  = (const float*)d_in[1];
    const float* eg  = (const float*)d_in[2];
    const float* eu  = (const float*)d_in[3];
    const float* ed  = (const float*)d_in[4];
    const float* sg  = (const float*)d_in[5];
    const float* su  = (const float*)d_in[6];
    const float* sd  = (const float*)d_in[7];
    const float* sgw = (const float*)d_in[8];
    float* out = (float*)d_out;
    int T = in_sizes[0] / D_DIM;

    __half *xs, *hh, *hs, *bgu, *bd, *bgsh, *bdsh;
    float *yb, *ysh;
    int *gtok, *tileE;
    cudaGetSymbolAddress((void**)&xs, g_xs);
    cudaGetSymbolAddress((void**)&hh, g_h);
    cudaGetSymbolAddress((void**)&hs, g_hs);
    cudaGetSymbolAddress((void**)&bgu, g_Bgu);
    cudaGetSymbolAddress((void**)&bd, g_Bd);
    cudaGetSymbolAddress((void**)&bgsh, g_Bgsh);
    cudaGetSymbolAddress((void**)&bdsh, g_Bdsh);
    cudaGetSymbolAddress((void**)&yb, g_y);
    cudaGetSymbolAddress((void**)&ysh, g_ysh);
    cudaGetSymbolAddress((void**)&gtok, g_gatherTok);
    cudaGetSymbolAddress((void**)&tileE, g_tileExpert);

    cudaFuncSetAttribute(hgemm<0>, cudaFuncAttributeMaxDynamicSharedMemorySize, SMEM_SZ);
    cudaFuncSetAttribute(hgemm<1>, cudaFuncAttributeMaxDynamicSharedMemorySize, SMEM_SZ);

    int write_logits = (out_size > T * D_DIM) ? 1 : 0;
    float* logits_out = out + (size_t)T * D_DIM;

    zero_meta_kernel<<<(MAXROWS + 255) / 256, 256>>>();
    router_kernel<<<(T * 32 + 255) / 256, 256>>>(x, gw, sgw, logits_out, write_logits, T);
    scan_kernel<<<1, 32>>>();
    gather_kernel<<<(T + 255) / 256, 256>>>(T);
    convx_kernel<<<(T * D_DIM / 2 + 255) / 256, 256>>>(x, xs, T * D_DIM / 2);

    // weight prep (transpose + fp16; gate/up interleaved into even/odd rows)
    wtrans_kernel<<<dim3(IMOE / 32, D_DIM / 32, E_NUM), 256>>>(
        eg, bgu, D_DIM, IMOE, (long long)D_DIM * IMOE, 2LL * IMOE * D_DIM, 2, 0);
    wtrans_kernel<<<dim3(IMOE / 32, D_DIM / 32, E_NUM), 256>>>(
        eu, bgu, D_DIM, IMOE, (long long)D_DIM * IMOE, 2LL * IMOE * D_DIM, 2, 1);
    wtrans_kernel<<<dim3(D_DIM / 32, IMOE / 32, E_NUM), 256>>>(
        ed, bd, IMOE, D_DIM, (long long)IMOE * D_DIM, (long long)D_DIM * IMOE, 1, 0);
    wtrans_kernel<<<dim3(ISH / 32, D_DIM / 32, 1), 256>>>(
        sg, bgsh, D_DIM, ISH, 0, 0, 2, 0);
    wtrans_kernel<<<dim3(ISH / 32, D_DIM / 32, 1), 256>>>(
        su, bgsh, D_DIM, ISH, 0, 0, 2, 1);
    wtrans_kernel<<<dim3(D_DIM / 32, ISH / 32, 1), 256>>>(
        sd, bdsh, ISH, D_DIM, 0, 0, 1, 0);

    // MoE: gate+up interleaved (N=2048) -> h ; down -> y
    hgemm<1><<<dim3(2 * IMOE / 256, MAXTILES), 256, SMEM_SZ>>>(
        xs, bgu, 2LL * IMOE * D_DIM, nullptr, hh, gtok, tileE, D_DIM, IMOE);
    hgemm<0><<<dim3(D_DIM / 256, MAXTILES), 256, SMEM_SZ>>>(
        hh, bd, (long long)D_DIM * IMOE, yb, nullptr, nullptr, tileE, IMOE, D_DIM);

    // shared expert
    hgemm<1><<<dim3(2 * ISH / 256, T / 128), 256, SMEM_SZ>>>(
        xs, bgsh, 0, nullptr, hs, nullptr, nullptr, D_DIM, ISH);
    hgemm<0><<<dim3(D_DIM / 256, T / 128), 256, SMEM_SZ>>>(
        hs, bdsh, 0, ysh, nullptr, nullptr, nullptr, ISH, D_DIM);

    combine_kernel<<<(T * (D_DIM / 4) + 255) / 256, 256>>>(out, T);
}

// round 7
// speedup vs baseline: 7.0855x; 1.0818x over previous
#include <cuda_runtime.h>
#include <cuda_bf16.h>
#include <cuda_fp16.h>
#include <cstdint>

#define TKN      8192
#define D_DIM    1024
#define E_NUM    8
#define IMOE     1024
#define ISH      4096
#define MAXROWS  17408
#define MAXTILES 136
#define NSTAGE   8
#define STAGE_SZ 24576          // A 8KB + B 16KB
#define SMEM_SZ  (NSTAGE * STAGE_SZ)   // 196608

// ---------------- helpers ----------------
__device__ __forceinline__ uint32_t smem_u32(const void* p) {
    uint32_t a;
    asm("{ .reg .u64 t; cvta.to.shared.u64 t, %1; cvt.u32.u64 %0, t; }" : "=r"(a) : "l"(p));
    return a;
}
__device__ __forceinline__ void cpa16(uint32_t s, const void* g) {
    asm volatile("cp.async.cg.shared.global [%0], [%1], 16;" :: "r"(s), "l"(g));
}
#define CP_COMMIT() asm volatile("cp.async.commit_group;" ::: "memory")
#define CP_WAIT6()  asm volatile("cp.async.wait_group 6;" ::: "memory")

#define LDSM4(R, addr) \
    asm volatile("ldmatrix.sync.aligned.m8n8.x4.shared.b16 {%0,%1,%2,%3}, [%4];" \
        : "=r"((R)[0]), "=r"((R)[1]), "=r"((R)[2]), "=r"((R)[3]) : "r"(addr))

#define MMAF16(C, A, B0, B1) \
    asm volatile("mma.sync.aligned.m16n8k16.row.col.f32.f16.f16.f32 " \
        "{%0,%1,%2,%3},{%4,%5,%6,%7},{%8,%9},{%0,%1,%2,%3};" \
        : "+f"((C)[0]), "+f"((C)[1]), "+f"((C)[2]), "+f"((C)[3]) \
        : "r"((A)[0]), "r"((A)[1]), "r"((A)[2]), "r"((A)[3]), "r"(B0), "r"(B1))

// swizzled byte offset of 16B chunk (row r, k8-group c8 in [0,4))
__device__ __forceinline__ uint32_t swz(int r, int c8) {
    return (uint32_t)(((r >> 1) * 128) + (((((r & 1) * 4 + c8) ^ ((r >> 1) & 7))) << 4));
}

// ---------------- device scratch ----------------
__device__ __align__(256) __half g_xs [(size_t)TKN * D_DIM];
__device__ __align__(256) __half g_h  [(size_t)MAXROWS * IMOE];
__device__ __align__(256) __half g_hs [(size_t)TKN * ISH];
__device__ __align__(256) float  g_y  [(size_t)MAXROWS * D_DIM];
__device__ __align__(256) float  g_ysh[(size_t)TKN * D_DIM];
__device__ __align__(256) __half g_Bgu [(size_t)E_NUM * 2 * IMOE * D_DIM];
__device__ __align__(256) __half g_Bd  [(size_t)E_NUM * D_DIM * IMOE];
__device__ __align__(256) __half g_Bgsh[(size_t)2 * ISH * D_DIM];
__device__ __align__(256) __half g_Bdsh[(size_t)D_DIM * ISH];

__device__ int   g_counts[E_NUM];
__device__ int   g_fill[E_NUM];
__device__ int   g_offs[E_NUM];
__device__ int   g_topE[2 * TKN];
__device__ float g_topW[2 * TKN];
__device__ float g_sgate[TKN];
__device__ int   g_gatherTok[MAXROWS];
__device__ int   g_slotRow[2 * TKN];
__device__ int   g_tileExpert[MAXTILES];

// ---------------- small kernels ----------------
__global__ void zero_meta_kernel() {
    int i = blockIdx.x * blockDim.x + threadIdx.x;
    if (i < MAXROWS) g_gatherTok[i] = 0;
    if (i < E_NUM) { g_counts[i] = 0; g_fill[i] = 0; }
    if (i < MAXTILES) g_tileExpert[i] = -1;
}

__global__ void router_kernel(const float* __restrict__ x, const float* __restrict__ gw,
                              const float* __restrict__ sgw, float* __restrict__ logits_out,
                              int write_logits, int T) {
    int gwarp = (blockIdx.x * blockDim.x + threadIdx.x) >> 5;
    int lane  = threadIdx.x & 31;
    if (gwarp >= T) return;
    const float* xr = x + (size_t)gwarp * D_DIM;
    float acc[9];
#pragma unroll
    for (int i = 0; i < 9; ++i) acc[i] = 0.f;
    for (int d = lane; d < D_DIM; d += 32) {
        float xv = xr[d];
        const float4* g4 = (const float4*)(gw + (size_t)d * E_NUM);
        float4 w0 = g4[0], w1 = g4[1];
        acc[0] += xv * w0.x; acc[1] += xv * w0.y; acc[2] += xv * w0.z; acc[3] += xv * w0.w;
        acc[4] += xv * w1.x; acc[5] += xv * w1.y; acc[6] += xv * w1.z; acc[7] += xv * w1.w;
        acc[8] += xv * sgw[d];
    }
#pragma unroll
    for (int o = 16; o; o >>= 1)
#pragma unroll
        for (int i = 0; i < 9; ++i) acc[i] += __shfl_xor_sync(0xffffffffu, acc[i], o);
    if (lane == 0) {
        float mx = acc[0];
#pragma unroll
        for (int e = 1; e < E_NUM; ++e) mx = fmaxf(mx, acc[e]);
        float p[E_NUM], s = 0.f;
#pragma unroll
        for (int e = 0; e < E_NUM; ++e) { p[e] = expf(acc[e] - mx); s += p[e]; }
        float inv = 1.f / s;
#pragma unroll
        for (int e = 0; e < E_NUM; ++e) p[e] *= inv;
        int i0 = 0;
#pragma unroll
        for (int e = 1; e < E_NUM; ++e) if (p[e] > p[i0]) i0 = e;
        int i1 = (i0 == 0) ? 1 : 0;
#pragma unroll
        for (int e = 0; e < E_NUM; ++e) if (e != i0 && p[e] > p[i1]) i1 = e;
        float w0 = p[i0], w1 = p[i1];
        float invs = 1.f / fmaxf(w0 + w1, 1e-6f);
        g_topE[2 * gwarp] = i0; g_topE[2 * gwarp + 1] = i1;
        g_topW[2 * gwarp] = w0 * invs; g_topW[2 * gwarp + 1] = w1 * invs;
        g_sgate[gwarp] = 1.f / (1.f + expf(-acc[8]));
        atomicAdd(&g_counts[i0], 1);
        atomicAdd(&g_counts[i1], 1);
        if (write_logits) {
#pragma unroll
            for (int e = 0; e < E_NUM; ++e)
                logits_out[(size_t)gwarp * E_NUM + e] = acc[e];
        }
    }
}

__global__ void scan_kernel() {
    if (threadIdx.x == 0) {
        int s = 0;
        for (int e = 0; e < E_NUM; ++e) {
            g_offs[e] = s;
            int tl = (g_counts[e] + 127) >> 7;
            for (int t = 0; t < tl; ++t) g_tileExpert[(s >> 7) + t] = e;
            s += tl << 7;
        }
    }
}

__global__ void gather_kernel(int T) {
    int t = blockIdx.x * blockDim.x + threadIdx.x;
    if (t >= T) return;
#pragma unroll
    for (int k = 0; k < 2; ++k) {
        int e = g_topE[2 * t + k];
        int p = atomicAdd(&g_fill[e], 1);
        int row = g_offs[e] + p;
        g_gatherTok[row] = t;
        g_slotRow[2 * t + k] = row;
    }
}

__global__ void convx_kernel(const float* __restrict__ x, __half* __restrict__ xo, int n2) {
    int i = blockIdx.x * blockDim.x + threadIdx.x;
    if (i >= n2) return;
    float2 v = ((const float2*)x)[i];
    ((__half2*)xo)[i] = __floats2half2_rn(v.x, v.y);
}

// weights: src[e][k][n] fp32 -> dst[e][n*rowMul+rowAdd][k] fp16 (k-major rows)
__global__ __launch_bounds__(256)
void wtrans_kernel(const float* __restrict__ src, __half* __restrict__ dst,
                   int Ks, int Ns, long long srcE, long long dstE,
                   int rowMul, int rowAdd) {
    src += (long long)blockIdx.z * srcE;
    dst += (long long)blockIdx.z * dstE;
    int tk0 = blockIdx.y * 32, tn0 = blockIdx.x * 32;
    __shared__ float tile[32][33];
    int tx = threadIdx.x & 31, ty = threadIdx.x >> 5;
#pragma unroll
    for (int r = 0; r < 4; ++r) {
        int k = ty + r * 8;
        tile[k][tx] = src[(long long)(tk0 + k) * Ns + tn0 + tx];
    }
    __syncthreads();
    int kk = (threadIdx.x & 7) * 4;
    int nn = threadIdx.x >> 3;
    long long drow = (long long)((tn0 + nn) * rowMul + rowAdd) * Ks + tk0 + kk;
    __align__(8) unsigned short hv[4];
#pragma unroll
    for (int q = 0; q < 4; ++q)
        hv[q] = __half_as_ushort(__float2half(tile[kk + q][nn]));
    *(uint2*)(dst + drow) = *(uint2*)hv;
}

// ---------------- HMMA fp16 GEMM ----------------
// CTA tile 128x256, BK=32, 8-stage cp.async pipeline, single barrier per iter
// (issue-next-before-compute), 256 threads (8 warps, 2x4, warp tile 64x64).
// MODE 0: Cf[(rowbase+m)*Nout + bn+n] = acc
// MODE 1: adjacent cols (even=gate, odd=up) -> silu(g)*u -> fp16 plane H
template <int MODE>
__global__ __launch_bounds__(256, 1)
void hgemm(const __half* __restrict__ A, const __half* __restrict__ B,
           long long bStride, float* __restrict__ Cf, __half* __restrict__ H,
           const int* __restrict__ gTok, const int* __restrict__ tileE,
           int K, int Nout) {
    int e = 0;
    if (tileE) { e = tileE[blockIdx.y]; if (e < 0) return; }
    int rowbase = blockIdx.y * 128;
    int bn = blockIdx.x * 256;
    const char* pA = (const char*)A;
    const char* pB = (const char*)(B + (long long)e * bStride);

    extern __shared__ __align__(1024) char smem[];
    uint32_t sb = smem_u32(smem);
    int tid = threadIdx.x;

    // loader precompute: A 2 chunks, B 4 chunks per thread
    size_t aB[2], bB[4];
    uint32_t dA[2], dB[4];
#pragma unroll
    for (int i = 0; i < 2; ++i) {
        int q = tid + 256 * i, r = q >> 2, c8 = q & 3;
        int ar = rowbase + r;
        int tok = gTok ? gTok[ar] : ar;
        aB[i] = ((size_t)tok * K + c8 * 8) * 2;
        dA[i] = swz(r, c8);
    }
#pragma unroll
    for (int i = 0; i < 4; ++i) {
        int q = tid + 256 * i, r = q >> 2, c8 = q & 3;
        bB[i] = ((size_t)(bn + r) * K + c8 * 8) * 2;
        dB[i] = 8192 + swz(r, c8);
    }
    auto issue = [&](int s, int c) {
        uint32_t st = sb + s * STAGE_SZ;
        size_t off = (size_t)c * 64;
#pragma unroll
        for (int i = 0; i < 2; ++i) cpa16(st + dA[i], pA + aB[i] + off);
#pragma unroll
        for (int i = 0; i < 4; ++i) cpa16(st + dB[i], pB + bB[i] + off);
    };

    // compute precompute
    int lane = tid & 31, w = tid >> 5;
    int wm = (w & 1) * 64, wn = (w >> 1) * 64;
    uint32_t aAd[4][2], aBd[4][2];
#pragma unroll
    for (int mi = 0; mi < 4; ++mi)
#pragma unroll
        for (int h = 0; h < 2; ++h) {
            int row = wm + mi * 16 + (lane & 15);
            int c8 = 2 * h + (lane >> 4);
            aAd[mi][h] = swz(row, c8);
        }
#pragma unroll
    for (int np = 0; np < 4; ++np)
#pragma unroll
        for (int h = 0; h < 2; ++h) {
            int row = wn + np * 16 + (lane & 7) + ((lane >> 4) << 3);
            int c8 = 2 * h + ((lane >> 3) & 1);
            aBd[np][h] = 8192 + swz(row, c8);
        }

    float acc[4][8][4];
#pragma unroll
    for (int mi = 0; mi < 4; ++mi)
#pragma unroll
        for (int nj = 0; nj < 8; ++nj)
#pragma unroll
            for (int q = 0; q < 4; ++q) acc[mi][nj][q] = 0.f;

    int NC = K >> 5;

#pragma unroll
    for (int s = 0; s < NSTAGE - 1; ++s) { issue(s, s); CP_COMMIT(); }

    for (int c = 0; c < NC; ++c) {
        CP_WAIT6();
        __syncthreads();
        // prefetch into stage (c-1)%8: safe — all warps finished reading it
        // in iter c-1 (they passed the barrier above).
        int pf = c + NSTAGE - 1;
        if (pf < NC) issue(pf & (NSTAGE - 1), pf);
        CP_COMMIT();
        uint32_t st = sb + (c & (NSTAGE - 1)) * STAGE_SZ;
#pragma unroll
        for (int h = 0; h < 2; ++h) {
            uint32_t a[4][4], b[8][2];
#pragma unroll
            for (int mi = 0; mi < 4; ++mi) LDSM4(a[mi], st + aAd[mi][h]);
#pragma unroll
            for (int np = 0; np < 4; ++np) {
                uint32_t q[4];
                LDSM4(q, st + aBd[np][h]);
                b[2 * np][0] = q[0]; b[2 * np][1] = q[1];
                b[2 * np + 1][0] = q[2]; b[2 * np + 1][1] = q[3];
            }
#pragma unroll
            for (int mi = 0; mi < 4; ++mi)
#pragma unroll
                for (int nj = 0; nj < 8; ++nj)
                    MMAF16(acc[mi][nj], a[mi], b[nj][0], b[nj][1]);
        }
    }

    // epilogue
#pragma unroll
    for (int mi = 0; mi < 4; ++mi) {
        int r0 = rowbase + wm + mi * 16 + (lane >> 2);
#pragma unroll
        for (int nj = 0; nj < 8; ++nj) {
            if (MODE == 0) {
                int col = bn + wn + nj * 8 + (lane & 3) * 2;
                *(float2*)(Cf + (size_t)r0 * Nout + col) =
                    make_float2(acc[mi][nj][0], acc[mi][nj][1]);
                *(float2*)(Cf + (size_t)(r0 + 8) * Nout + col) =
                    make_float2(acc[mi][nj][2], acc[mi][nj][3]);
            } else {
                int oc = ((bn + wn) >> 1) + nj * 4 + (lane & 3);
                float g0 = acc[mi][nj][0], u0 = acc[mi][nj][1];
                float g1 = acc[mi][nj][2], u1 = acc[mi][nj][3];
                float v0 = g0 / (1.f + expf(-g0)) * u0;
                float v1 = g1 / (1.f + expf(-g1)) * u1;
                H[(size_t)r0 * Nout + oc] = __float2half(v0);
                H[(size_t)(r0 + 8) * Nout + oc] = __float2half(v1);
            }
        }
    }
}

__global__ void combine_kernel(float* __restrict__ out, int T) {
    int idx = blockIdx.x * blockDim.x + threadIdx.x;
    int total = T * (D_DIM / 4);
    if (idx >= total) return;
    int t = idx >> 8;
    int c = idx & 255;
    int r0 = g_slotRow[2 * t], r1 = g_slotRow[2 * t + 1];
    float w0 = g_topW[2 * t], w1 = g_topW[2 * t + 1];
    float sgt = g_sgate[t];
    const float4* y4 = (const float4*)g_y;
    const float4* s4 = (const float4*)g_ysh;
    float4 a = y4[(size_t)r0 * 256 + c];
    float4 b = y4[(size_t)r1 * 256 + c];
    float4 sh = s4[(size_t)t * 256 + c];
    float4 o;
    o.x = w0 * a.x + w1 * b.x + sgt * sh.x;
    o.y = w0 * a.y + w1 * b.y + sgt * sh.y;
    o.z = w0 * a.z + w1 * b.z + sgt * sh.z;
    o.w = w0 * a.w + w1 * b.w + sgt * sh.w;
    ((float4*)out)[idx] = o;
}

// ---------------- launcher (fork/join capture-legal overlap) ----------------
extern "C" void kernel_launch(void* const* d_in, const int* in_sizes, int n_in,
                              void* d_out, int out_size) {
    const float* x   = (const float*)d_in[0];
    const float* gw  = (const float*)d_in[1];
    const float* eg  = (const float*)d_in[2];
    const float* eu  = (const float*)d_in[3];
    const float* ed  = (const float*)d_in[4];
    const float* sg  = (const float*)d_in[5];
    const float* su  = (const float*)d_in[6];
    const float* sd  = (const float*)d_in[7];
    const float* sgw = (const float*)d_in[8];
    float* out = (float*)d_out;
    int T = in_sizes[0] / D_DIM;

    __half *xs, *hh, *hs, *bgu, *bd, *bgsh, *bdsh;
    float *yb, *ysh;
    int *gtok, *tileE;
    cudaGetSymbolAddress((void**)&xs, g_xs);
    cudaGetSymbolAddress((void**)&hh, g_h);
    cudaGetSymbolAddress((void**)&hs, g_hs);
    cudaGetSymbolAddress((void**)&bgu, g_Bgu);
    cudaGetSymbolAddress((void**)&bd, g_Bd);
    cudaGetSymbolAddress((void**)&bgsh, g_Bgsh);
    cudaGetSymbolAddress((void**)&bdsh, g_Bdsh);
    cudaGetSymbolAddress((void**)&yb, g_y);
    cudaGetSymbolAddress((void**)&ysh, g_ysh);
    cudaGetSymbolAddress((void**)&gtok, g_gatherTok);
    cudaGetSymbolAddress((void**)&tileE, g_tileExpert);

    cudaFuncSetAttribute(hgemm<0>, cudaFuncAttributeMaxDynamicSharedMemorySize, SMEM_SZ);
    cudaFuncSetAttribute(hgemm<1>, cudaFuncAttributeMaxDynamicSharedMemorySize, SMEM_SZ);

    int write_logits = (out_size > T * D_DIM) ? 1 : 0;
    float* logits_out = out + (size_t)T * D_DIM;

    // Fork/join: shared-expert chain on a side stream. Streams/events are
    // host objects (no device allocs); intentionally not destroyed — host
    // code only runs during correctness + capture, not during replay.
    cudaStream_t sA = 0;
    cudaEvent_t evRoot = 0, evX = 0, evA = 0;
    bool ok = (cudaStreamCreateWithFlags(&sA, cudaStreamNonBlocking) == cudaSuccess);
    ok = ok && (cudaEventCreateWithFlags(&evRoot, cudaEventDisableTiming) == cudaSuccess);
    ok = ok && (cudaEventCreateWithFlags(&evX,   cudaEventDisableTiming) == cudaSuccess);
    ok = ok && (cudaEventCreateWithFlags(&evA,   cudaEventDisableTiming) == cudaSuccess);
    if (!ok) sA = 0;

    if (ok) { cudaEventRecord(evRoot, 0); cudaStreamWaitEvent(sA, evRoot, 0); }

    // -------- side stream: convx + shared-expert chain --------
    convx_kernel<<<(T * D_DIM / 2 + 255) / 256, 256, 0, sA>>>(x, xs, T * D_DIM / 2);
    if (ok) cudaEventRecord(evX, sA);
    wtrans_kernel<<<dim3(ISH / 32, D_DIM / 32, 1), 256, 0, sA>>>(
        sg, bgsh, D_DIM, ISH, 0, 0, 2, 0);
    wtrans_kernel<<<dim3(ISH / 32, D_DIM / 32, 1), 256, 0, sA>>>(
        su, bgsh, D_DIM, ISH, 0, 0, 2, 1);
    wtrans_kernel<<<dim3(D_DIM / 32, ISH / 32, 1), 256, 0, sA>>>(
        sd, bdsh, ISH, D_DIM, 0, 0, 1, 0);
    hgemm<1><<<dim3(2 * ISH / 256, T / 128), 256, SMEM_SZ, sA>>>(
        xs, bgsh, 0, nullptr, hs, nullptr, nullptr, D_DIM, ISH);
    hgemm<0><<<dim3(D_DIM / 256, T / 128), 256, SMEM_SZ, sA>>>(
        hs, bdsh, 0, ysh, nullptr, nullptr, nullptr, ISH, D_DIM);
    if (ok) cudaEventRecord(evA, sA);

    // -------- main stream: MoE metadata + weights + GEMMs --------
    zero_meta_kernel<<<(MAXROWS + 255) / 256, 256>>>();
    router_kernel<<<(T * 32 + 255) / 256, 256>>>(x, gw, sgw, logits_out, write_logits, T);
    scan_kernel<<<1, 32>>>();
    gather_kernel<<<(T + 255) / 256, 256>>>(T);
    wtrans_kernel<<<dim3(IMOE / 32, D_DIM / 32, E_NUM), 256>>>(
        eg, bgu, D_DIM, IMOE, (long long)D_DIM * IMOE, 2LL * IMOE * D_DIM, 2, 0);
    wtrans_kernel<<<dim3(IMOE / 32, D_DIM / 32, E_NUM), 256>>>(
        eu, bgu, D_DIM, IMOE, (long long)D_DIM * IMOE, 2LL * IMOE * D_DIM, 2, 1);
    wtrans_kernel<<<dim3(D_DIM / 32, IMOE / 32, E_NUM), 256>>>(
        ed, bd, IMOE, D_DIM, (long long)IMOE * D_DIM, (long long)D_DIM * IMOE, 1, 0);

    if (ok) cudaStreamWaitEvent(0, evX, 0);   // xs ready
    hgemm<1><<<dim3(2 * IMOE / 256, MAXTILES), 256, SMEM_SZ>>>(
        xs, bgu, 2LL * IMOE * D_DIM, nullptr, hh, gtok, tileE, D_DIM, IMOE);
    hgemm<0><<<dim3(D_DIM / 256, MAXTILES), 256, SMEM_SZ>>>(
        hh, bd, (long long)D_DIM * IMOE, yb, nullptr, nullptr, tileE, IMOE, D_DIM);

    if (ok) cudaStreamWaitEvent(0, evA, 0);   // ysh ready
    combine_kernel<<<(T * (D_DIM / 4) + 255) / 256, 256>>>(out, T);
}

// round 8
// speedup vs baseline: 7.9583x; 1.1232x over previous
#include <cuda_runtime.h>
#include <cuda_bf16.h>
#include <cuda_fp16.h>
#include <cstdint>

#define TKN      8192
#define D_DIM    1024
#define E_NUM    8
#define IMOE     1024
#define ISH      4096
#define MAXROWS  17408
#define MAXTILES 136
#define NSTAGE   4
#define STAGE_SZ 49152          // A 16KB + B 32KB  (BK=64)
#define SMEM_SZ  (NSTAGE * STAGE_SZ)   // 196608

// ---------------- helpers ----------------
__device__ __forceinline__ uint32_t smem_u32(const void* p) {
    uint32_t a;
    asm("{ .reg .u64 t; cvta.to.shared.u64 t, %1; cvt.u32.u64 %0, t; }" : "=r"(a) : "l"(p));
    return a;
}
__device__ __forceinline__ void cpa16(uint32_t s, const void* g) {
    asm volatile("cp.async.cg.shared.global [%0], [%1], 16;" :: "r"(s), "l"(g));
}
#define CP_COMMIT() asm volatile("cp.async.commit_group;" ::: "memory")
#define CP_WAIT2()  asm volatile("cp.async.wait_group 2;" ::: "memory")

#define LDSM4(R, addr) \
    asm volatile("ldmatrix.sync.aligned.m8n8.x4.shared.b16 {%0,%1,%2,%3}, [%4];" \
        : "=r"((R)[0]), "=r"((R)[1]), "=r"((R)[2]), "=r"((R)[3]) : "r"(addr))

#define MMAF16(C, A, B0, B1) \
    asm volatile("mma.sync.aligned.m16n8k16.row.col.f32.f16.f16.f32 " \
        "{%0,%1,%2,%3},{%4,%5,%6,%7},{%8,%9},{%0,%1,%2,%3};" \
        : "+f"((C)[0]), "+f"((C)[1]), "+f"((C)[2]), "+f"((C)[3]) \
        : "r"((A)[0]), "r"((A)[1]), "r"((A)[2]), "r"((A)[3]), "r"(B0), "r"(B1))

// canonical SW128 swizzle: 128B rows, 8 x 16B groups, XOR by row&7
__device__ __forceinline__ uint32_t swz64(int r, int c8) {
    return (uint32_t)(r * 128 + ((c8 ^ (r & 7)) << 4));
}

// ---------------- device scratch ----------------
__device__ __align__(256) __half g_xs [(size_t)TKN * D_DIM];
__device__ __align__(256) __half g_h  [(size_t)MAXROWS * IMOE];
__device__ __align__(256) __half g_hs [(size_t)TKN * ISH];
__device__ __align__(256) float  g_y  [(size_t)MAXROWS * D_DIM];
__device__ __align__(256) float  g_ysh[(size_t)TKN * D_DIM];
__device__ __align__(256) __half g_Bgu [(size_t)E_NUM * 2 * IMOE * D_DIM];
__device__ __align__(256) __half g_Bd  [(size_t)E_NUM * D_DIM * IMOE];
__device__ __align__(256) __half g_Bgsh[(size_t)2 * ISH * D_DIM];
__device__ __align__(256) __half g_Bdsh[(size_t)D_DIM * ISH];

__device__ int   g_counts[E_NUM];
__device__ int   g_fill[E_NUM];
__device__ int   g_offs[E_NUM];
__device__ int   g_topE[2 * TKN];
__device__ float g_topW[2 * TKN];
__device__ float g_sgate[TKN];
__device__ int   g_gatherTok[MAXROWS];
__device__ int   g_slotRow[2 * TKN];
__device__ int   g_tileExpert[MAXTILES];

// ---------------- small kernels ----------------
__global__ void zero_meta_kernel() {
    int i = blockIdx.x * blockDim.x + threadIdx.x;
    if (i < MAXROWS) g_gatherTok[i] = 0;
    if (i < E_NUM) { g_counts[i] = 0; g_fill[i] = 0; }
    if (i < MAXTILES) g_tileExpert[i] = -1;
}

__global__ void router_kernel(const float* __restrict__ x, const float* __restrict__ gw,
                              const float* __restrict__ sgw, float* __restrict__ logits_out,
                              int write_logits, int T) {
    int gwarp = (blockIdx.x * blockDim.x + threadIdx.x) >> 5;
    int lane  = threadIdx.x & 31;
    if (gwarp >= T) return;
    const float* xr = x + (size_t)gwarp * D_DIM;
    float acc[9];
#pragma unroll
    for (int i = 0; i < 9; ++i) acc[i] = 0.f;
    for (int d = lane; d < D_DIM; d += 32) {
        float xv = xr[d];
        const float4* g4 = (const float4*)(gw + (size_t)d * E_NUM);
        float4 w0 = g4[0], w1 = g4[1];
        acc[0] += xv * w0.x; acc[1] += xv * w0.y; acc[2] += xv * w0.z; acc[3] += xv * w0.w;
        acc[4] += xv * w1.x; acc[5] += xv * w1.y; acc[6] += xv * w1.z; acc[7] += xv * w1.w;
        acc[8] += xv * sgw[d];
    }
#pragma unroll
    for (int o = 16; o; o >>= 1)
#pragma unroll
        for (int i = 0; i < 9; ++i) acc[i] += __shfl_xor_sync(0xffffffffu, acc[i], o);
    if (lane == 0) {
        float mx = acc[0];
#pragma unroll
        for (int e = 1; e < E_NUM; ++e) mx = fmaxf(mx, acc[e]);
        float p[E_NUM], s = 0.f;
#pragma unroll
        for (int e = 0; e < E_NUM; ++e) { p[e] = expf(acc[e] - mx); s += p[e]; }
        float inv = 1.f / s;
#pragma unroll
        for (int e = 0; e < E_NUM; ++e) p[e] *= inv;
        int i0 = 0;
#pragma unroll
        for (int e = 1; e < E_NUM; ++e) if (p[e] > p[i0]) i0 = e;
        int i1 = (i0 == 0) ? 1 : 0;
#pragma unroll
        for (int e = 0; e < E_NUM; ++e) if (e != i0 && p[e] > p[i1]) i1 = e;
        float w0 = p[i0], w1 = p[i1];
        float invs = 1.f / fmaxf(w0 + w1, 1e-6f);
        g_topE[2 * gwarp] = i0; g_topE[2 * gwarp + 1] = i1;
        g_topW[2 * gwarp] = w0 * invs; g_topW[2 * gwarp + 1] = w1 * invs;
        g_sgate[gwarp] = 1.f / (1.f + expf(-acc[8]));
        atomicAdd(&g_counts[i0], 1);
        atomicAdd(&g_counts[i1], 1);
        if (write_logits) {
#pragma unroll
            for (int e = 0; e < E_NUM; ++e)
                logits_out[(size_t)gwarp * E_NUM + e] = acc[e];
        }
    }
}

__global__ void scan_kernel() {
    if (threadIdx.x == 0) {
        int s = 0;
        for (int e = 0; e < E_NUM; ++e) {
            g_offs[e] = s;
            int tl = (g_counts[e] + 127) >> 7;
            for (int t = 0; t < tl; ++t) g_tileExpert[(s >> 7) + t] = e;
            s += tl << 7;
        }
    }
}

__global__ void gather_kernel(int T) {
    int t = blockIdx.x * blockDim.x + threadIdx.x;
    if (t >= T) return;
#pragma unroll
    for (int k = 0; k < 2; ++k) {
        int e = g_topE[2 * t + k];
        int p = atomicAdd(&g_fill[e], 1);
        int row = g_offs[e] + p;
        g_gatherTok[row] = t;
        g_slotRow[2 * t + k] = row;
    }
}

__global__ void convx_kernel(const float* __restrict__ x, __half* __restrict__ xo, int n2) {
    int i = blockIdx.x * blockDim.x + threadIdx.x;
    if (i >= n2) return;
    float2 v = ((const float2*)x)[i];
    ((__half2*)xo)[i] = __floats2half2_rn(v.x, v.y);
}

// weights: src[e][k][n] fp32 -> dst[e][n*rowMul+rowAdd][k] fp16 (k-major rows)
__global__ __launch_bounds__(256)
void wtrans_kernel(const float* __restrict__ src, __half* __restrict__ dst,
                   int Ks, int Ns, long long srcE, long long dstE,
                   int rowMul, int rowAdd) {
    src += (long long)blockIdx.z * srcE;
    dst += (long long)blockIdx.z * dstE;
    int tk0 = blockIdx.y * 32, tn0 = blockIdx.x * 32;
    __shared__ float tile[32][33];
    int tx = threadIdx.x & 31, ty = threadIdx.x >> 5;
#pragma unroll
    for (int r = 0; r < 4; ++r) {
        int k = ty + r * 8;
        tile[k][tx] = src[(long long)(tk0 + k) * Ns + tn0 + tx];
    }
    __syncthreads();
    int kk = (threadIdx.x & 7) * 4;
    int nn = threadIdx.x >> 3;
    long long drow = (long long)((tn0 + nn) * rowMul + rowAdd) * Ks + tk0 + kk;
    __align__(8) unsigned short hv[4];
#pragma unroll
    for (int q = 0; q < 4; ++q)
        hv[q] = __half_as_ushort(__float2half(tile[kk + q][nn]));
    *(uint2*)(dst + drow) = *(uint2*)hv;
}

// ---------------- HMMA fp16 GEMM ----------------
// CTA tile 128x256, BK=64, 4-stage cp.async pipeline, single barrier per iter,
// 256 threads (8 warps, 2x4, warp tile 64x64). fp32 accumulate.
// MODE 0: Cf[(rowbase+m)*Nout + bn+n] = acc
// MODE 1: adjacent cols (even=gate, odd=up) -> silu(g)*u -> fp16 plane H
template <int MODE>
__global__ __launch_bounds__(256, 1)
void hgemm(const __half* __restrict__ A, const __half* __restrict__ B,
           long long bStride, float* __restrict__ Cf, __half* __restrict__ H,
           const int* __restrict__ gTok, const int* __restrict__ tileE,
           int K, int Nout) {
    int e = 0;
    if (tileE) { e = tileE[blockIdx.y]; if (e < 0) return; }
    int rowbase = blockIdx.y * 128;
    int bn = blockIdx.x * 256;
    const char* pA = (const char*)A;
    const char* pB = (const char*)(B + (long long)e * bStride);

    extern __shared__ __align__(1024) char smem[];
    uint32_t sb = smem_u32(smem);
    int tid = threadIdx.x;

    // loader precompute: A rows 128 x 8 chunks = 1024 (4/thread),
    //                    B rows 256 x 8 chunks = 2048 (8/thread)
    size_t aB[4], bB[8];
    uint32_t dA[4], dB[8];
#pragma unroll
    for (int i = 0; i < 4; ++i) {
        int q = tid + 256 * i, r = q >> 3, c8 = q & 7;
        int ar = rowbase + r;
        int tok = gTok ? gTok[ar] : ar;
        aB[i] = ((size_t)tok * K + c8 * 8) * 2;
        dA[i] = swz64(r, c8);
    }
#pragma unroll
    for (int i = 0; i < 8; ++i) {
        int q = tid + 256 * i, r = q >> 3, c8 = q & 7;
        bB[i] = ((size_t)(bn + r) * K + c8 * 8) * 2;
        dB[i] = 16384 + swz64(r, c8);
    }
    auto issue = [&](int s, int c) {
        uint32_t st = sb + s * STAGE_SZ;
        size_t off = (size_t)c * 128;
#pragma unroll
        for (int i = 0; i < 4; ++i) cpa16(st + dA[i], pA + aB[i] + off);
#pragma unroll
        for (int i = 0; i < 8; ++i) cpa16(st + dB[i], pB + bB[i] + off);
    };

    // compute precompute
    int lane = tid & 31, w = tid >> 5;
    int wm = (w & 1) * 64, wn = (w >> 1) * 64;
    uint32_t aAd[4][4], aBd[4][4];
#pragma unroll
    for (int mi = 0; mi < 4; ++mi)
#pragma unroll
        for (int h = 0; h < 4; ++h) {
            int row = wm + mi * 16 + (lane & 15);
            int c8 = 2 * h + (lane >> 4);
            aAd[mi][h] = swz64(row, c8);
        }
#pragma unroll
    for (int np = 0; np < 4; ++np)
#pragma unroll
        for (int h = 0; h < 4; ++h) {
            int row = wn + np * 16 + (lane & 7) + ((lane >> 4) << 3);
            int c8 = 2 * h + ((lane >> 3) & 1);
            aBd[np][h] = 16384 + swz64(row, c8);
        }

    float acc[4][8][4];
#pragma unroll
    for (int mi = 0; mi < 4; ++mi)
#pragma unroll
        for (int nj = 0; nj < 8; ++nj)
#pragma unroll
            for (int q = 0; q < 4; ++q) acc[mi][nj][q] = 0.f;

    int NC = K >> 6;

#pragma unroll
    for (int s = 0; s < NSTAGE - 1; ++s) { issue(s, s); CP_COMMIT(); }

    for (int c = 0; c < NC; ++c) {
        CP_WAIT2();
        __syncthreads();
        // prefetch into the stage consumed in iter c-1 (all warps are past it)
        int pf = c + NSTAGE - 1;
        if (pf < NC) issue(pf & (NSTAGE - 1), pf);
        CP_COMMIT();
        uint32_t st = sb + (c & (NSTAGE - 1)) * STAGE_SZ;
#pragma unroll
        for (int h = 0; h < 4; ++h) {
            uint32_t a[4][4], b[8][2];
#pragma unroll
            for (int mi = 0; mi < 4; ++mi) LDSM4(a[mi], st + aAd[mi][h]);
#pragma unroll
            for (int np = 0; np < 4; ++np) {
                uint32_t q[4];
                LDSM4(q, st + aBd[np][h]);
                b[2 * np][0] = q[0]; b[2 * np][1] = q[1];
                b[2 * np + 1][0] = q[2]; b[2 * np + 1][1] = q[3];
            }
#pragma unroll
            for (int mi = 0; mi < 4; ++mi)
#pragma unroll
                for (int nj = 0; nj < 8; ++nj)
                    MMAF16(acc[mi][nj], a[mi], b[nj][0], b[nj][1]);
        }
    }

    // epilogue
#pragma unroll
    for (int mi = 0; mi < 4; ++mi) {
        int r0 = rowbase + wm + mi * 16 + (lane >> 2);
#pragma unroll
        for (int nj = 0; nj < 8; ++nj) {
            if (MODE == 0) {
                int col = bn + wn + nj * 8 + (lane & 3) * 2;
                *(float2*)(Cf + (size_t)r0 * Nout + col) =
                    make_float2(acc[mi][nj][0], acc[mi][nj][1]);
                *(float2*)(Cf + (size_t)(r0 + 8) * Nout + col) =
                    make_float2(acc[mi][nj][2], acc[mi][nj][3]);
            } else {
                int oc = ((bn + wn) >> 1) + nj * 4 + (lane & 3);
                float g0 = acc[mi][nj][0], u0 = acc[mi][nj][1];
                float g1 = acc[mi][nj][2], u1 = acc[mi][nj][3];
                float v0 = g0 / (1.f + expf(-g0)) * u0;
                float v1 = g1 / (1.f + expf(-g1)) * u1;
                H[(size_t)r0 * Nout + oc] = __float2half(v0);
                H[(size_t)(r0 + 8) * Nout + oc] = __float2half(v1);
            }
        }
    }
}

__global__ void combine_kernel(float* __restrict__ out, int T) {
    int idx = blockIdx.x * blockDim.x + threadIdx.x;
    int total = T * (D_DIM / 4);
    if (idx >= total) return;
    int t = idx >> 8;
    int c = idx & 255;
    int r0 = g_slotRow[2 * t], r1 = g_slotRow[2 * t + 1];
    float w0 = g_topW[2 * t], w1 = g_topW[2 * t + 1];
    float sgt = g_sgate[t];
    const float4* y4 = (const float4*)g_y;
    const float4* s4 = (const float4*)g_ysh;
    float4 a = y4[(size_t)r0 * 256 + c];
    float4 b = y4[(size_t)r1 * 256 + c];
    float4 sh = s4[(size_t)t * 256 + c];
    float4 o;
    o.x = w0 * a.x + w1 * b.x + sgt * sh.x;
    o.y = w0 * a.y + w1 * b.y + sgt * sh.y;
    o.z = w0 * a.z + w1 * b.z + sgt * sh.z;
    o.w = w0 * a.w + w1 * b.w + sgt * sh.w;
    ((float4*)out)[idx] = o;
}

// ---------------- launcher (fork/join capture-legal overlap) ----------------
extern "C" void kernel_launch(void* const* d_in, const int* in_sizes, int n_in,
                              void* d_out, int out_size) {
    const float* x   = (const float*)d_in[0];
    const float* gw  = (const float*)d_in[1];
    const float* eg  = (const float*)d_in[2];
    const float* eu  = (const float*)d_in[3];
    const float* ed  = (const float*)d_in[4];
    const float* sg  = (const float*)d_in[5];
    const float* su  = (const float*)d_in[6];
    const float* sd  = (const float*)d_in[7];
    const float* sgw = (const float*)d_in[8];
    float* out = (float*)d_out;
    int T = in_sizes[0] / D_DIM;

    __half *xs, *hh, *hs, *bgu, *bd, *bgsh, *bdsh;
    float *yb, *ysh;
    int *gtok, *tileE;
    cudaGetSymbolAddress((void**)&xs, g_xs);
    cudaGetSymbolAddress((void**)&hh, g_h);
    cudaGetSymbolAddress((void**)&hs, g_hs);
    cudaGetSymbolAddress((void**)&bgu, g_Bgu);
    cudaGetSymbolAddress((void**)&bd, g_Bd);
    cudaGetSymbolAddress((void**)&bgsh, g_Bgsh);
    cudaGetSymbolAddress((void**)&bdsh, g_Bdsh);
    cudaGetSymbolAddress((void**)&yb, g_y);
    cudaGetSymbolAddress((void**)&ysh, g_ysh);
    cudaGetSymbolAddress((void**)&gtok, g_gatherTok);
    cudaGetSymbolAddress((void**)&tileE, g_tileExpert);

    cudaFuncSetAttribute(hgemm<0>, cudaFuncAttributeMaxDynamicSharedMemorySize, SMEM_SZ);
    cudaFuncSetAttribute(hgemm<1>, cudaFuncAttributeMaxDynamicSharedMemorySize, SMEM_SZ);

    int write_logits = (out_size > T * D_DIM) ? 1 : 0;
    float* logits_out = out + (size_t)T * D_DIM;

    // Fork/join: shared-expert chain on a side stream (capture-legal).
    cudaStream_t sA = 0;
    cudaEvent_t evRoot = 0, evX = 0, evA = 0;
    bool ok = (cudaStreamCreateWithFlags(&sA, cudaStreamNonBlocking) == cudaSuccess);
    ok = ok && (cudaEventCreateWithFlags(&evRoot, cudaEventDisableTiming) == cudaSuccess);
    ok = ok && (cudaEventCreateWithFlags(&evX,   cudaEventDisableTiming) == cudaSuccess);
    ok = ok && (cudaEventCreateWithFlags(&evA,   cudaEventDisableTiming) == cudaSuccess);
    if (!ok) sA = 0;

    if (ok) { cudaEventRecord(evRoot, 0); cudaStreamWaitEvent(sA, evRoot, 0); }

    // -------- side stream: convx + shared-expert chain --------
    convx_kernel<<<(T * D_DIM / 2 + 255) / 256, 256, 0, sA>>>(x, xs, T * D_DIM / 2);
    if (ok) cudaEventRecord(evX, sA);
    wtrans_kernel<<<dim3(ISH / 32, D_DIM / 32, 1), 256, 0, sA>>>(
        sg, bgsh, D_DIM, ISH, 0, 0, 2, 0);
    wtrans_kernel<<<dim3(ISH / 32, D_DIM / 32, 1), 256, 0, sA>>>(
        su, bgsh, D_DIM, ISH, 0, 0, 2, 1);
    wtrans_kernel<<<dim3(D_DIM / 32, ISH / 32, 1), 256, 0, sA>>>(
        sd, bdsh, ISH, D_DIM, 0, 0, 1, 0);
    hgemm<1><<<dim3(2 * ISH / 256, T / 128), 256, SMEM_SZ, sA>>>(
        xs, bgsh, 0, nullptr, hs, nullptr, nullptr, D_DIM, ISH);
    hgemm<0><<<dim3(D_DIM / 256, T / 128), 256, SMEM_SZ, sA>>>(
        hs, bdsh, 0, ysh, nullptr, nullptr, nullptr, ISH, D_DIM);
    if (ok) cudaEventRecord(evA, sA);

    // -------- main stream: MoE metadata + weights + GEMMs --------
    zero_meta_kernel<<<(MAXROWS + 255) / 256, 256>>>();
    router_kernel<<<(T * 32 + 255) / 256, 256>>>(x, gw, sgw, logits_out, write_logits, T);
    scan_kernel<<<1, 32>>>();
    gather_kernel<<<(T + 255) / 256, 256>>>(T);
    wtrans_kernel<<<dim3(IMOE / 32, D_DIM / 32, E_NUM), 256>>>(
        eg, bgu, D_DIM, IMOE, (long long)D_DIM * IMOE, 2LL * IMOE * D_DIM, 2, 0);
    wtrans_kernel<<<dim3(IMOE / 32, D_DIM / 32, E_NUM), 256>>>(
        eu, bgu, D_DIM, IMOE, (long long)D_DIM * IMOE, 2LL * IMOE * D_DIM, 2, 1);
    wtrans_kernel<<<dim3(D_DIM / 32, IMOE / 32, E_NUM), 256>>>(
        ed, bd, IMOE, D_DIM, (long long)IMOE * D_DIM, (long long)D_DIM * IMOE, 1, 0);

    if (ok) cudaStreamWaitEvent(0, evX, 0);   // xs ready
    hgemm<1><<<dim3(2 * IMOE / 256, MAXTILES), 256, SMEM_SZ>>>(
        xs, bgu, 2LL * IMOE * D_DIM, nullptr, hh, gtok, tileE, D_DIM, IMOE);
    hgemm<0><<<dim3(D_DIM / 256, MAXTILES), 256, SMEM_SZ>>>(
        hh, bd, (long long)D_DIM * IMOE, yb, nullptr, nullptr, tileE, IMOE, D_DIM);

    if (ok) cudaStreamWaitEvent(0, evA, 0);   // ysh ready
    combine_kernel<<<(T * (D_DIM / 4) + 255) / 256, 256>>>(out, T);
}

// round 10
// speedup vs baseline: 8.1443x; 1.0234x over previous
#include <cuda_runtime.h>
#include <cuda_bf16.h>
#include <cuda_fp16.h>
#include <cstdint>

#define TKN      8192
#define D_DIM    1024
#define E_NUM    8
#define IMOE     1024
#define ISH      4096
#define MAXROWS  17408
#define MAXTILES 136
#define HTILES   68            // MAXTILES/2
#define NSTAGE   4
#define STAGE_SZ 49152          // A 16KB + B 32KB  (BK=64)
#define SMEM_SZ  (NSTAGE * STAGE_SZ)   // 196608

// ---------------- helpers ----------------
__device__ __forceinline__ uint32_t smem_u32(const void* p) {
    uint32_t a;
    asm("{ .reg .u64 t; cvta.to.shared.u64 t, %1; cvt.u32.u64 %0, t; }" : "=r"(a) : "l"(p));
    return a;
}
__device__ __forceinline__ void cpa16(uint32_t s, const void* g) {
    asm volatile("cp.async.cg.shared.global [%0], [%1], 16;" :: "r"(s), "l"(g));
}
#define CP_COMMIT() asm volatile("cp.async.commit_group;" ::: "memory")
#define CP_WAIT2()  asm volatile("cp.async.wait_group 2;" ::: "memory")

#define LDSM4(R, addr) \
    asm volatile("ldmatrix.sync.aligned.m8n8.x4.shared.b16 {%0,%1,%2,%3}, [%4];" \
        : "=r"((R)[0]), "=r"((R)[1]), "=r"((R)[2]), "=r"((R)[3]) : "r"(addr))

#define MMAF16(C, A, B0, B1) \
    asm volatile("mma.sync.aligned.m16n8k16.row.col.f32.f16.f16.f32 " \
        "{%0,%1,%2,%3},{%4,%5,%6,%7},{%8,%9},{%0,%1,%2,%3};" \
        : "+f"((C)[0]), "+f"((C)[1]), "+f"((C)[2]), "+f"((C)[3]) \
        : "r"((A)[0]), "r"((A)[1]), "r"((A)[2]), "r"((A)[3]), "r"(B0), "r"(B1))

// canonical SW128 swizzle: 128B rows, 8 x 16B groups, XOR by row&7
__device__ __forceinline__ uint32_t swz64(int r, int c8) {
    return (uint32_t)(r * 128 + ((c8 ^ (r & 7)) << 4));
}

// ---------------- device scratch ----------------
__device__ __align__(256) __half g_xs [(size_t)TKN * D_DIM];
__device__ __align__(256) __half g_h  [(size_t)MAXROWS * IMOE];
__device__ __align__(256) __half g_hs [(size_t)TKN * ISH];
__device__ __align__(256) float  g_y  [(size_t)MAXROWS * D_DIM];
__device__ __align__(256) float  g_ysh[(size_t)TKN * D_DIM];
__device__ __align__(256) __half g_Bgu [(size_t)E_NUM * 2 * IMOE * D_DIM];
__device__ __align__(256) __half g_Bd  [(size_t)E_NUM * D_DIM * IMOE];
__device__ __align__(256) __half g_Bgsh[(size_t)2 * ISH * D_DIM];
__device__ __align__(256) __half g_Bdsh[(size_t)D_DIM * ISH];

__device__ int   g_counts[E_NUM];
__device__ int   g_fill[E_NUM];
__device__ int   g_offs[E_NUM];
__device__ int   g_topE[2 * TKN];
__device__ float g_topW[2 * TKN];
__device__ float g_sgate[TKN];
__device__ int   g_gatherTok[MAXROWS];
__device__ int   g_slotRow[2 * TKN];
__device__ int   g_tileExpert[MAXTILES];

// ---------------- small kernels ----------------
__global__ void zero_meta_kernel() {
    int i = blockIdx.x * blockDim.x + threadIdx.x;
    if (i < MAXROWS) g_gatherTok[i] = 0;
    if (i < E_NUM) { g_counts[i] = 0; g_fill[i] = 0; }
    if (i < MAXTILES) g_tileExpert[i] = -1;
}

__global__ void router_kernel(const float* __restrict__ x, const float* __restrict__ gw,
                              const float* __restrict__ sgw, float* __restrict__ logits_out,
                              int write_logits, int T) {
    int gwarp = (blockIdx.x * blockDim.x + threadIdx.x) >> 5;
    int lane  = threadIdx.x & 31;
    if (gwarp >= T) return;
    const float* xr = x + (size_t)gwarp * D_DIM;
    float acc[9];
#pragma unroll
    for (int i = 0; i < 9; ++i) acc[i] = 0.f;
    for (int d = lane; d < D_DIM; d += 32) {
        float xv = xr[d];
        const float4* g4 = (const float4*)(gw + (size_t)d * E_NUM);
        float4 w0 = g4[0], w1 = g4[1];
        acc[0] += xv * w0.x; acc[1] += xv * w0.y; acc[2] += xv * w0.z; acc[3] += xv * w0.w;
        acc[4] += xv * w1.x; acc[5] += xv * w1.y; acc[6] += xv * w1.z; acc[7] += xv * w1.w;
        acc[8] += xv * sgw[d];
    }
#pragma unroll
    for (int o = 16; o; o >>= 1)
#pragma unroll
        for (int i = 0; i < 9; ++i) acc[i] += __shfl_xor_sync(0xffffffffu, acc[i], o);
    if (lane == 0) {
        float mx = acc[0];
#pragma unroll
        for (int e = 1; e < E_NUM; ++e) mx = fmaxf(mx, acc[e]);
        float p[E_NUM], s = 0.f;
#pragma unroll
        for (int e = 0; e < E_NUM; ++e) { p[e] = expf(acc[e] - mx); s += p[e]; }
        float inv = 1.f / s;
#pragma unroll
        for (int e = 0; e < E_NUM; ++e) p[e] *= inv;
        int i0 = 0;
#pragma unroll
        for (int e = 1; e < E_NUM; ++e) if (p[e] > p[i0]) i0 = e;
        int i1 = (i0 == 0) ? 1 : 0;
#pragma unroll
        for (int e = 0; e < E_NUM; ++e) if (e != i0 && p[e] > p[i1]) i1 = e;
        float w0 = p[i0], w1 = p[i1];
        float invs = 1.f / fmaxf(w0 + w1, 1e-6f);
        g_topE[2 * gwarp] = i0; g_topE[2 * gwarp + 1] = i1;
        g_topW[2 * gwarp] = w0 * invs; g_topW[2 * gwarp + 1] = w1 * invs;
        g_sgate[gwarp] = 1.f / (1.f + expf(-acc[8]));
        atomicAdd(&g_counts[i0], 1);
        atomicAdd(&g_counts[i1], 1);
        if (write_logits) {
#pragma unroll
            for (int e = 0; e < E_NUM; ++e)
                logits_out[(size_t)gwarp * E_NUM + e] = acc[e];
        }
    }
}

__global__ void scan_kernel() {
    if (threadIdx.x == 0) {
        int s = 0;
        for (int e = 0; e < E_NUM; ++e) {
            g_offs[e] = s;
            int tl = (g_counts[e] + 127) >> 7;
            for (int t = 0; t < tl; ++t) g_tileExpert[(s >> 7) + t] = e;
            s += tl << 7;
        }
    }
}

__global__ void gather_kernel(int T) {
    int t = blockIdx.x * blockDim.x + threadIdx.x;
    if (t >= T) return;
#pragma unroll
    for (int k = 0; k < 2; ++k) {
        int e = g_topE[2 * t + k];
        int p = atomicAdd(&g_fill[e], 1);
        int row = g_offs[e] + p;
        g_gatherTok[row] = t;
        g_slotRow[2 * t + k] = row;
    }
}

__global__ void convx_kernel(const float* __restrict__ x, __half* __restrict__ xo, int n2) {
    int i = blockIdx.x * blockDim.x + threadIdx.x;
    if (i >= n2) return;
    float2 v = ((const float2*)x)[i];
    ((__half2*)xo)[i] = __floats2half2_rn(v.x, v.y);
}

// weights: src[e][k][n] fp32 -> dst[e][n*rowMul+rowAdd][k] fp16 (k-major rows)
__global__ __launch_bounds__(256)
void wtrans_kernel(const float* __restrict__ src, __half* __restrict__ dst,
                   int Ks, int Ns, long long srcE, long long dstE,
                   int rowMul, int rowAdd) {
    src += (long long)blockIdx.z * srcE;
    dst += (long long)blockIdx.z * dstE;
    int tk0 = blockIdx.y * 32, tn0 = blockIdx.x * 32;
    __shared__ float tile[32][33];
    int tx = threadIdx.x & 31, ty = threadIdx.x >> 5;
#pragma unroll
    for (int r = 0; r < 4; ++r) {
        int k = ty + r * 8;
        tile[k][tx] = src[(long long)(tk0 + k) * Ns + tn0 + tx];
    }
    __syncthreads();
    int kk = (threadIdx.x & 7) * 4;
    int nn = threadIdx.x >> 3;
    long long drow = (long long)((tn0 + nn) * rowMul + rowAdd) * Ks + tk0 + kk;
    __align__(8) unsigned short hv[4];
#pragma unroll
    for (int q = 0; q < 4; ++q)
        hv[q] = __half_as_ushort(__float2half(tile[kk + q][nn]));
    *(uint2*)(dst + drow) = *(uint2*)hv;
}

// ---------------- HMMA fp16 GEMM ----------------
// CTA tile 128x256, BK=64, 4-stage cp.async pipeline, single barrier per iter,
// 256 threads (8 warps, 2x4, warp tile 64x64). fp32 accumulate.
// MODE 0: Cf[(rowbase+m)*Nout + bn+n] = acc
// MODE 1: adjacent cols (even=gate, odd=up) -> silu(g)*u -> fp16 plane H
template <int MODE>
__global__ __launch_bounds__(256, 1)
void hgemm(const __half* __restrict__ A, const __half* __restrict__ B,
           long long bStride, float* __restrict__ Cf, __half* __restrict__ H,
           const int* __restrict__ gTok, const int* __restrict__ tileE,
           int K, int Nout) {
    int e = 0;
    if (tileE) { e = tileE[blockIdx.y]; if (e < 0) return; }
    int rowbase = blockIdx.y * 128;
    int bn = blockIdx.x * 256;
    const char* pA = (const char*)A;
    const char* pB = (const char*)(B + (long long)e * bStride);

    extern __shared__ __align__(1024) char smem[];
    uint32_t sb = smem_u32(smem);
    int tid = threadIdx.x;

    // loader precompute
    size_t aB[4], bB[8];
    uint32_t dA[4], dB[8];
#pragma unroll
    for (int i = 0; i < 4; ++i) {
        int q = tid + 256 * i, r = q >> 3, c8 = q & 7;
        int ar = rowbase + r;
        int tok = gTok ? gTok[ar] : ar;
        aB[i] = ((size_t)tok * K + c8 * 8) * 2;
        dA[i] = swz64(r, c8);
    }
#pragma unroll
    for (int i = 0; i < 8; ++i) {
        int q = tid + 256 * i, r = q >> 3, c8 = q & 7;
        bB[i] = ((size_t)(bn + r) * K + c8 * 8) * 2;
        dB[i] = 16384 + swz64(r, c8);
    }
    auto issue = [&](int s, int c) {
        uint32_t st = sb + s * STAGE_SZ;
        size_t off = (size_t)c * 128;
#pragma unroll
        for (int i = 0; i < 4; ++i) cpa16(st + dA[i], pA + aB[i] + off);
#pragma unroll
        for (int i = 0; i < 8; ++i) cpa16(st + dB[i], pB + bB[i] + off);
    };

    // compute precompute
    int lane = tid & 31, w = tid >> 5;
    int wm = (w & 1) * 64, wn = (w >> 1) * 64;
    uint32_t aAd[4][4], aBd[4][4];
#pragma unroll
    for (int mi = 0; mi < 4; ++mi)
#pragma unroll
        for (int h = 0; h < 4; ++h) {
            int row = wm + mi * 16 + (lane & 15);
            int c8 = 2 * h + (lane >> 4);
            aAd[mi][h] = swz64(row, c8);
        }
#pragma unroll
    for (int np = 0; np < 4; ++np)
#pragma unroll
        for (int h = 0; h < 4; ++h) {
            int row = wn + np * 16 + (lane & 7) + ((lane >> 4) << 3);
            int c8 = 2 * h + ((lane >> 3) & 1);
            aBd[np][h] = 16384 + swz64(row, c8);
        }

    float acc[4][8][4];
#pragma unroll
    for (int mi = 0; mi < 4; ++mi)
#pragma unroll
        for (int nj = 0; nj < 8; ++nj)
#pragma unroll
            for (int q = 0; q < 4; ++q) acc[mi][nj][q] = 0.f;

    int NC = K >> 6;

#pragma unroll
    for (int s = 0; s < NSTAGE - 1; ++s) { issue(s, s); CP_COMMIT(); }

    for (int c = 0; c < NC; ++c) {
        CP_WAIT2();
        __syncthreads();
        int pf = c + NSTAGE - 1;
        if (pf < NC) issue(pf & (NSTAGE - 1), pf);
        CP_COMMIT();
        uint32_t st = sb + (c & (NSTAGE - 1)) * STAGE_SZ;
#pragma unroll
        for (int h = 0; h < 4; ++h) {
            uint32_t a[4][4], b[8][2];
#pragma unroll
            for (int mi = 0; mi < 4; ++mi) LDSM4(a[mi], st + aAd[mi][h]);
#pragma unroll
            for (int np = 0; np < 4; ++np) {
                uint32_t q[4];
                LDSM4(q, st + aBd[np][h]);
                b[2 * np][0] = q[0]; b[2 * np][1] = q[1];
                b[2 * np + 1][0] = q[2]; b[2 * np + 1][1] = q[3];
            }
#pragma unroll
            for (int mi = 0; mi < 4; ++mi)
#pragma unroll
                for (int nj = 0; nj < 8; ++nj)
                    MMAF16(acc[mi][nj], a[mi], b[nj][0], b[nj][1]);
        }
    }

    // epilogue
#pragma unroll
    for (int mi = 0; mi < 4; ++mi) {
        int r0 = rowbase + wm + mi * 16 + (lane >> 2);
#pragma unroll
        for (int nj = 0; nj < 8; ++nj) {
            if (MODE == 0) {
                int col = bn + wn + nj * 8 + (lane & 3) * 2;
                *(float2*)(Cf + (size_t)r0 * Nout + col) =
                    make_float2(acc[mi][nj][0], acc[mi][nj][1]);
                *(float2*)(Cf + (size_t)(r0 + 8) * Nout + col) =
                    make_float2(acc[mi][nj][2], acc[mi][nj][3]);
            } else {
                int oc = ((bn + wn) >> 1) + nj * 4 + (lane & 3);
                float g0 = acc[mi][nj][0], u0 = acc[mi][nj][1];
                float g1 = acc[mi][nj][2], u1 = acc[mi][nj][3];
                float v0 = g0 / (1.f + expf(-g0)) * u0;
                float v1 = g1 / (1.f + expf(-g1)) * u1;
                H[(size_t)r0 * Nout + oc] = __float2half(v0);
                H[(size_t)(r0 + 8) * Nout + oc] = __float2half(v1);
            }
        }
    }
}

__global__ void combine_kernel(float* __restrict__ out, int T) {
    int idx = blockIdx.x * blockDim.x + threadIdx.x;
    int total = T * (D_DIM / 4);
    if (idx >= total) return;
    int t = idx >> 8;
    int c = idx & 255;
    int r0 = g_slotRow[2 * t], r1 = g_slotRow[2 * t + 1];
    float w0 = g_topW[2 * t], w1 = g_topW[2 * t + 1];
    float sgt = g_sgate[t];
    const float4* y4 = (const float4*)g_y;
    const float4* s4 = (const float4*)g_ysh;
    float4 a = y4[(size_t)r0 * 256 + c];
    float4 b = y4[(size_t)r1 * 256 + c];
    float4 sh = s4[(size_t)t * 256 + c];
    float4 o;
    o.x = w0 * a.x + w1 * b.x + sgt * sh.x;
    o.y = w0 * a.y + w1 * b.y + sgt * sh.y;
    o.z = w0 * a.z + w1 * b.z + sgt * sh.z;
    o.w = w0 * a.w + w1 * b.w + sgt * sh.w;
    ((float4*)out)[idx] = o;
}

// ---------------- launcher: 4-stream fork/join, row-halved chains ----------------
// Streams/events are created ONCE (first call = correctness run) and reused on
// every subsequent call — creating them per call exhausted the driver's stream
// pool on the capture call and tripped the device-memory guard (R9 failure).
// The captured graph is identical on every capture. If creation fails, all
// work goes to stream 0 in an order that is sequentially correct.
static cudaStream_t s_sA = 0, s_sB = 0, s_sC = 0;
static cudaEvent_t s_evRoot = 0, s_evX = 0, s_evWsh = 0, s_evMeta = 0,
                   s_evW = 0, s_evA = 0, s_evB = 0, s_evC = 0;
static int s_init_state = 0;   // 0 = not tried, 1 = ok, -1 = failed

extern "C" void kernel_launch(void* const* d_in, const int* in_sizes, int n_in,
                              void* d_out, int out_size) {
    const float* x   = (const float*)d_in[0];
    const float* gw  = (const float*)d_in[1];
    const float* eg  = (const float*)d_in[2];
    const float* eu  = (const float*)d_in[3];
    const float* ed  = (const float*)d_in[4];
    const float* sg  = (const float*)d_in[5];
    const float* su  = (const float*)d_in[6];
    const float* sd  = (const float*)d_in[7];
    const float* sgw = (const float*)d_in[8];
    float* out = (float*)d_out;
    int T = in_sizes[0] / D_DIM;
    int Th = T / 2;

    __half *xs, *hh, *hs, *bgu, *bd, *bgsh, *bdsh;
    float *yb, *ysh;
    int *gtok, *tileE;
    cudaGetSymbolAddress((void**)&xs, g_xs);
    cudaGetSymbolAddress((void**)&hh, g_h);
    cudaGetSymbolAddress((void**)&hs, g_hs);
    cudaGetSymbolAddress((void**)&bgu, g_Bgu);
    cudaGetSymbolAddress((void**)&bd, g_Bd);
    cudaGetSymbolAddress((void**)&bgsh, g_Bgsh);
    cudaGetSymbolAddress((void**)&bdsh, g_Bdsh);
    cudaGetSymbolAddress((void**)&yb, g_y);
    cudaGetSymbolAddress((void**)&ysh, g_ysh);
    cudaGetSymbolAddress((void**)&gtok, g_gatherTok);
    cudaGetSymbolAddress((void**)&tileE, g_tileExpert);

    cudaFuncSetAttribute(hgemm<0>, cudaFuncAttributeMaxDynamicSharedMemorySize, SMEM_SZ);
    cudaFuncSetAttribute(hgemm<1>, cudaFuncAttributeMaxDynamicSharedMemorySize, SMEM_SZ);

    int write_logits = (out_size > T * D_DIM) ? 1 : 0;
    float* logits_out = out + (size_t)T * D_DIM;

    if (s_init_state == 0) {
        bool o = true;
        o = o && (cudaStreamCreateWithFlags(&s_sA, cudaStreamNonBlocking) == cudaSuccess);
        o = o && (cudaStreamCreateWithFlags(&s_sB, cudaStreamNonBlocking) == cudaSuccess);
        o = o && (cudaStreamCreateWithFlags(&s_sC, cudaStreamNonBlocking) == cudaSuccess);
        o = o && (cudaEventCreateWithFlags(&s_evRoot, cudaEventDisableTiming) == cudaSuccess);
        o = o && (cudaEventCreateWithFlags(&s_evX,    cudaEventDisableTiming) == cudaSuccess);
        o = o && (cudaEventCreateWithFlags(&s_evWsh,  cudaEventDisableTiming) == cudaSuccess);
        o = o && (cudaEventCreateWithFlags(&s_evMeta, cudaEventDisableTiming) == cudaSuccess);
        o = o && (cudaEventCreateWithFlags(&s_evW,    cudaEventDisableTiming) == cudaSuccess);
        o = o && (cudaEventCreateWithFlags(&s_evA,    cudaEventDisableTiming) == cudaSuccess);
        o = o && (cudaEventCreateWithFlags(&s_evB,    cudaEventDisableTiming) == cudaSuccess);
        o = o && (cudaEventCreateWithFlags(&s_evC,    cudaEventDisableTiming) == cudaSuccess);
        s_init_state = o ? 1 : -1;
    }
    bool ok = (s_init_state == 1);
    cudaStream_t sA = ok ? s_sA : 0, sB = ok ? s_sB : 0, sC = ok ? s_sC : 0;

    if (ok) {
        cudaEventRecord(s_evRoot, 0);
        cudaStreamWaitEvent(sA, s_evRoot, 0);
        cudaStreamWaitEvent(sB, s_evRoot, 0);
        cudaStreamWaitEvent(sC, s_evRoot, 0);
    }

    // ---- sA: convx ----
    convx_kernel<<<(T * D_DIM / 2 + 255) / 256, 256, 0, sA>>>(x, xs, T * D_DIM / 2);
    if (ok) cudaEventRecord(s_evX, sA);

    // ---- sB: MoE metadata chain ----
    zero_meta_kernel<<<(MAXROWS + 255) / 256, 256, 0, sB>>>();
    router_kernel<<<(T * 32 + 255) / 256, 256, 0, sB>>>(x, gw, sgw, logits_out,
                                                        write_logits, T);
    scan_kernel<<<1, 32, 0, sB>>>();
    gather_kernel<<<(T + 255) / 256, 256, 0, sB>>>(T);
    if (ok) cudaEventRecord(s_evMeta, sB);

    // ---- sA: shared-expert weight transposes ----
    wtrans_kernel<<<dim3(ISH / 32, D_DIM / 32, 1), 256, 0, sA>>>(
        sg, bgsh, D_DIM, ISH, 0, 0, 2, 0);
    wtrans_kernel<<<dim3(ISH / 32, D_DIM / 32, 1), 256, 0, sA>>>(
        su, bgsh, D_DIM, ISH, 0, 0, 2, 1);
    wtrans_kernel<<<dim3(D_DIM / 32, ISH / 32, 1), 256, 0, sA>>>(
        sd, bdsh, ISH, D_DIM, 0, 0, 1, 0);
    if (ok) cudaEventRecord(s_evWsh, sA);

    // ---- s0: MoE weight transposes ----
    wtrans_kernel<<<dim3(IMOE / 32, D_DIM / 32, E_NUM), 256>>>(
        eg, bgu, D_DIM, IMOE, (long long)D_DIM * IMOE, 2LL * IMOE * D_DIM, 2, 0);
    wtrans_kernel<<<dim3(IMOE / 32, D_DIM / 32, E_NUM), 256>>>(
        eu, bgu, D_DIM, IMOE, (long long)D_DIM * IMOE, 2LL * IMOE * D_DIM, 2, 1);
    wtrans_kernel<<<dim3(D_DIM / 32, IMOE / 32, E_NUM), 256>>>(
        ed, bd, IMOE, D_DIM, (long long)IMOE * D_DIM, (long long)D_DIM * IMOE, 1, 0);
    if (ok) cudaEventRecord(s_evW, 0);

    // ---- GU GEMMs (4 half-chains) ----
    hgemm<1><<<dim3(2 * ISH / 256, Th / 128), 256, SMEM_SZ, sA>>>(
        xs, bgsh, 0, nullptr, hs, nullptr, nullptr, D_DIM, ISH);
    if (ok) cudaStreamWaitEvent(sC, s_evWsh, 0);   // implies convx done (sA order)
    hgemm<1><<<dim3(2 * ISH / 256, Th / 128), 256, SMEM_SZ, sC>>>(
        xs + (size_t)Th * D_DIM, bgsh, 0, nullptr, hs + (size_t)Th * ISH,
        nullptr, nullptr, D_DIM, ISH);
    if (ok) { cudaStreamWaitEvent(0, s_evMeta, 0); cudaStreamWaitEvent(0, s_evX, 0); }
    hgemm<1><<<dim3(2 * IMOE / 256, HTILES), 256, SMEM_SZ>>>(
        xs, bgu, 2LL * IMOE * D_DIM, nullptr, hh, gtok, tileE, D_DIM, IMOE);
    if (ok) { cudaStreamWaitEvent(sB, s_evW, 0); cudaStreamWaitEvent(sB, s_evX, 0); }
    hgemm<1><<<dim3(2 * IMOE / 256, HTILES), 256, SMEM_SZ, sB>>>(
        xs, bgu, 2LL * IMOE * D_DIM, nullptr, hh + (size_t)HTILES * 128 * IMOE,
        gtok + HTILES * 128, tileE + HTILES, D_DIM, IMOE);

    // ---- down GEMMs (4 half-chains) ----
    hgemm<0><<<dim3(D_DIM / 256, Th / 128), 256, SMEM_SZ, sA>>>(
        hs, bdsh, 0, ysh, nullptr, nullptr, nullptr, ISH, D_DIM);
    if (ok) cudaEventRecord(s_evA, sA);
    hgemm<0><<<dim3(D_DIM / 256, Th / 128), 256, SMEM_SZ, sC>>>(
        hs + (size_t)Th * ISH, bdsh, 0, ysh + (size_t)Th * D_DIM,
        nullptr, nullptr, nullptr, ISH, D_DIM);
    if (ok) cudaEventRecord(s_evC, sC);
    hgemm<0><<<dim3(D_DIM / 256, HTILES), 256, SMEM_SZ>>>(
        hh, bd, (long long)D_DIM * IMOE, yb, nullptr, nullptr, tileE, IMOE, D_DIM);
    hgemm<0><<<dim3(D_DIM / 256, HTILES), 256, SMEM_SZ, sB>>>(
        hh + (size_t)HTILES * 128 * IMOE, bd, (long long)D_DIM * IMOE,
        yb + (size_t)HTILES * 128 * D_DIM, nullptr, nullptr, tileE + HTILES,
        IMOE, D_DIM);
    if (ok) cudaEventRecord(s_evB, sB);

    // ---- join + combine on s0 ----
    if (ok) {
        cudaStreamWaitEvent(0, s_evA, 0);
        cudaStreamWaitEvent(0, s_evB, 0);
        cudaStreamWaitEvent(0, s_evC, 0);
    }
    combine_kernel<<<(T * (D_DIM / 4) + 255) / 256, 256>>>(out, T);
}

// round 11
// speedup vs baseline: 9.2385x; 1.1343x over previous
#include <cuda_runtime.h>
#include <cuda_bf16.h>
#include <cuda_fp16.h>
#include <cstdint>

#define TKN      8192
#define D_DIM    1024
#define E_NUM    8
#define IMOE     1024
#define ISH      4096
#define MAXROWS  17408
#define MAXTILES 136
#define HTILES   68            // MAXTILES/2
#define NSTAGE   3
#define STAGE_SZ 32768          // A 16KB + B 16KB  (tile 128x128, BK=64)
#define SMEM_SZ  (NSTAGE * STAGE_SZ)   // 98304 -> 2 CTAs/SM

// ---------------- helpers ----------------
__device__ __forceinline__ uint32_t smem_u32(const void* p) {
    uint32_t a;
    asm("{ .reg .u64 t; cvta.to.shared.u64 t, %1; cvt.u32.u64 %0, t; }" : "=r"(a) : "l"(p));
    return a;
}
__device__ __forceinline__ void cpa16(uint32_t s, const void* g) {
    asm volatile("cp.async.cg.shared.global [%0], [%1], 16;" :: "r"(s), "l"(g));
}
#define CP_COMMIT() asm volatile("cp.async.commit_group;" ::: "memory")
#define CP_WAIT1()  asm volatile("cp.async.wait_group 1;" ::: "memory")

#define LDSM4(R, addr) \
    asm volatile("ldmatrix.sync.aligned.m8n8.x4.shared.b16 {%0,%1,%2,%3}, [%4];" \
        : "=r"((R)[0]), "=r"((R)[1]), "=r"((R)[2]), "=r"((R)[3]) : "r"(addr))

#define MMAF16(C, A, B0, B1) \
    asm volatile("mma.sync.aligned.m16n8k16.row.col.f32.f16.f16.f32 " \
        "{%0,%1,%2,%3},{%4,%5,%6,%7},{%8,%9},{%0,%1,%2,%3};" \
        : "+f"((C)[0]), "+f"((C)[1]), "+f"((C)[2]), "+f"((C)[3]) \
        : "r"((A)[0]), "r"((A)[1]), "r"((A)[2]), "r"((A)[3]), "r"(B0), "r"(B1))

// canonical SW128 swizzle: 128B rows, 8 x 16B groups, XOR by row&7
__device__ __forceinline__ uint32_t swz64(int r, int c8) {
    return (uint32_t)(r * 128 + ((c8 ^ (r & 7)) << 4));
}

// ---------------- device scratch ----------------
__device__ __align__(256) __half g_xs [(size_t)TKN * D_DIM];
__device__ __align__(256) __half g_h  [(size_t)MAXROWS * IMOE];
__device__ __align__(256) __half g_hs [(size_t)TKN * ISH];
__device__ __align__(256) float  g_y  [(size_t)MAXROWS * D_DIM];
__device__ __align__(256) float  g_ysh[(size_t)TKN * D_DIM];
__device__ __align__(256) __half g_Bgu [(size_t)E_NUM * 2 * IMOE * D_DIM];
__device__ __align__(256) __half g_Bd  [(size_t)E_NUM * D_DIM * IMOE];
__device__ __align__(256) __half g_Bgsh[(size_t)2 * ISH * D_DIM];
__device__ __align__(256) __half g_Bdsh[(size_t)D_DIM * ISH];

__device__ int   g_counts[E_NUM];
__device__ int   g_fill[E_NUM];
__device__ int   g_offs[E_NUM];
__device__ int   g_topE[2 * TKN];
__device__ float g_topW[2 * TKN];
__device__ float g_sgate[TKN];
__device__ int   g_gatherTok[MAXROWS];
__device__ int   g_slotRow[2 * TKN];
__device__ int   g_tileExpert[MAXTILES];

// ---------------- small kernels ----------------
__global__ void zero_meta_kernel() {
    int i = blockIdx.x * blockDim.x + threadIdx.x;
    if (i < MAXROWS) g_gatherTok[i] = 0;
    if (i < E_NUM) { g_counts[i] = 0; g_fill[i] = 0; }
    if (i < MAXTILES) g_tileExpert[i] = -1;
}

__global__ void router_kernel(const float* __restrict__ x, const float* __restrict__ gw,
                              const float* __restrict__ sgw, float* __restrict__ logits_out,
                              int write_logits, int T) {
    int gwarp = (blockIdx.x * blockDim.x + threadIdx.x) >> 5;
    int lane  = threadIdx.x & 31;
    if (gwarp >= T) return;
    const float* xr = x + (size_t)gwarp * D_DIM;
    float acc[9];
#pragma unroll
    for (int i = 0; i < 9; ++i) acc[i] = 0.f;
    for (int d = lane; d < D_DIM; d += 32) {
        float xv = xr[d];
        const float4* g4 = (const float4*)(gw + (size_t)d * E_NUM);
        float4 w0 = g4[0], w1 = g4[1];
        acc[0] += xv * w0.x; acc[1] += xv * w0.y; acc[2] += xv * w0.z; acc[3] += xv * w0.w;
        acc[4] += xv * w1.x; acc[5] += xv * w1.y; acc[6] += xv * w1.z; acc[7] += xv * w1.w;
        acc[8] += xv * sgw[d];
    }
#pragma unroll
    for (int o = 16; o; o >>= 1)
#pragma unroll
        for (int i = 0; i < 9; ++i) acc[i] += __shfl_xor_sync(0xffffffffu, acc[i], o);
    if (lane == 0) {
        float mx = acc[0];
#pragma unroll
        for (int e = 1; e < E_NUM; ++e) mx = fmaxf(mx, acc[e]);
        float p[E_NUM], s = 0.f;
#pragma unroll
        for (int e = 0; e < E_NUM; ++e) { p[e] = expf(acc[e] - mx); s += p[e]; }
        float inv = 1.f / s;
#pragma unroll
        for (int e = 0; e < E_NUM; ++e) p[e] *= inv;
        int i0 = 0;
#pragma unroll
        for (int e = 1; e < E_NUM; ++e) if (p[e] > p[i0]) i0 = e;
        int i1 = (i0 == 0) ? 1 : 0;
#pragma unroll
        for (int e = 0; e < E_NUM; ++e) if (e != i0 && p[e] > p[i1]) i1 = e;
        float w0 = p[i0], w1 = p[i1];
        float invs = 1.f / fmaxf(w0 + w1, 1e-6f);
        g_topE[2 * gwarp] = i0; g_topE[2 * gwarp + 1] = i1;
        g_topW[2 * gwarp] = w0 * invs; g_topW[2 * gwarp + 1] = w1 * invs;
        g_sgate[gwarp] = 1.f / (1.f + expf(-acc[8]));
        atomicAdd(&g_counts[i0], 1);
        atomicAdd(&g_counts[i1], 1);
        if (write_logits) {
#pragma unroll
            for (int e = 0; e < E_NUM; ++e)
                logits_out[(size_t)gwarp * E_NUM + e] = acc[e];
        }
    }
}

__global__ void scan_kernel() {
    if (threadIdx.x == 0) {
        int s = 0;
        for (int e = 0; e < E_NUM; ++e) {
            g_offs[e] = s;
            int tl = (g_counts[e] + 127) >> 7;
            for (int t = 0; t < tl; ++t) g_tileExpert[(s >> 7) + t] = e;
            s += tl << 7;
        }
    }
}

__global__ void gather_kernel(int T) {
    int t = blockIdx.x * blockDim.x + threadIdx.x;
    if (t >= T) return;
#pragma unroll
    for (int k = 0; k < 2; ++k) {
        int e = g_topE[2 * t + k];
        int p = atomicAdd(&g_fill[e], 1);
        int row = g_offs[e] + p;
        g_gatherTok[row] = t;
        g_slotRow[2 * t + k] = row;
    }
}

__global__ void convx_kernel(const float* __restrict__ x, __half* __restrict__ xo, int n2) {
    int i = blockIdx.x * blockDim.x + threadIdx.x;
    if (i >= n2) return;
    float2 v = ((const float2*)x)[i];
    ((__half2*)xo)[i] = __floats2half2_rn(v.x, v.y);
}

// weights: src[e][k][n] fp32 -> dst[e][n*rowMul+rowAdd][k] fp16 (k-major rows)
__global__ __launch_bounds__(256)
void wtrans_kernel(const float* __restrict__ src, __half* __restrict__ dst,
                   int Ks, int Ns, long long srcE, long long dstE,
                   int rowMul, int rowAdd) {
    src += (long long)blockIdx.z * srcE;
    dst += (long long)blockIdx.z * dstE;
    int tk0 = blockIdx.y * 32, tn0 = blockIdx.x * 32;
    __shared__ float tile[32][33];
    int tx = threadIdx.x & 31, ty = threadIdx.x >> 5;
#pragma unroll
    for (int r = 0; r < 4; ++r) {
        int k = ty + r * 8;
        tile[k][tx] = src[(long long)(tk0 + k) * Ns + tn0 + tx];
    }
    __syncthreads();
    int kk = (threadIdx.x & 7) * 4;
    int nn = threadIdx.x >> 3;
    long long drow = (long long)((tn0 + nn) * rowMul + rowAdd) * Ks + tk0 + kk;
    __align__(8) unsigned short hv[4];
#pragma unroll
    for (int q = 0; q < 4; ++q)
        hv[q] = __half_as_ushort(__float2half(tile[kk + q][nn]));
    *(uint2*)(dst + drow) = *(uint2*)hv;
}

// ---------------- HMMA fp16 GEMM ----------------
// CTA tile 128x128, BK=64, 3-stage cp.async pipeline, 256 threads
// (8 warps 2x4, warp tile 64x32), 2 CTAs/SM. fp32 accumulate.
// MODE 0: Cf[(rowbase+m)*Nout + bn+n] = acc
// MODE 1: adjacent cols (even=gate, odd=up) -> silu(g)*u -> fp16 plane H
template <int MODE>
__global__ __launch_bounds__(256, 2)
void hgemm(const __half* __restrict__ A, const __half* __restrict__ B,
           long long bStride, float* __restrict__ Cf, __half* __restrict__ H,
           const int* __restrict__ gTok, const int* __restrict__ tileE,
           int K, int Nout) {
    int e = 0;
    if (tileE) { e = tileE[blockIdx.y]; if (e < 0) return; }
    int rowbase = blockIdx.y * 128;
    int bn = blockIdx.x * 128;
    const char* pA = (const char*)A;
    const char* pB = (const char*)(B + (long long)e * bStride);

    extern __shared__ __align__(1024) char smem[];
    uint32_t sb = smem_u32(smem);
    int tid = threadIdx.x;

    // loader precompute: A 4 chunks + B 4 chunks per thread (16B each),
    // 32-bit base offsets (all operand buffers < 256 MB)
    uint32_t aB[4], bB[4], dA[4], dB[4];
#pragma unroll
    for (int i = 0; i < 4; ++i) {
        int q = tid + 256 * i, r = q >> 3, c8 = q & 7;
        int ar = rowbase + r;
        int tok = gTok ? gTok[ar] : ar;
        aB[i] = (uint32_t)((tok * K + c8 * 8) * 2);
        dA[i] = swz64(r, c8);
        bB[i] = (uint32_t)(((bn + r) * K + c8 * 8) * 2);
        dB[i] = 16384 + swz64(r, c8);
    }
    auto issue = [&](int s, int c) {
        uint32_t st = sb + s * STAGE_SZ;
        uint32_t off = (uint32_t)c * 128;
#pragma unroll
        for (int i = 0; i < 4; ++i) cpa16(st + dA[i], pA + aB[i] + off);
#pragma unroll
        for (int i = 0; i < 4; ++i) cpa16(st + dB[i], pB + bB[i] + off);
    };

    // compute precompute: only h-indexed bases; mi/np folded as +2048*idx
    // (row+16 keeps row&7, so swz64(row+16,c8) = swz64(row,c8)+2048)
    int lane = tid & 31, w = tid >> 5;
    int wm = (w & 1) * 64, wn = (w >> 1) * 32;
    uint32_t aA0[4], aB0[4];
    {
        int rowA = wm + (lane & 15);
        int rowB = wn + (lane & 7) + ((lane >> 4) << 3);
#pragma unroll
        for (int h = 0; h < 4; ++h) {
            aA0[h] = swz64(rowA, 2 * h + (lane >> 4));
            aB0[h] = 16384 + swz64(rowB, 2 * h + ((lane >> 3) & 1));
        }
    }

    float acc[4][4][4];
#pragma unroll
    for (int mi = 0; mi < 4; ++mi)
#pragma unroll
        for (int nj = 0; nj < 4; ++nj)
#pragma unroll
            for (int q = 0; q < 4; ++q) acc[mi][nj][q] = 0.f;

    int NC = K >> 6;

    issue(0, 0); CP_COMMIT();
    issue(1, 1); CP_COMMIT();

    int s = 0, ps = 2;
    for (int c = 0; c < NC; ++c) {
        CP_WAIT1();
        __syncthreads();
        // prefetch into the stage consumed in iter c-1 (all warps are past it)
        int pf = c + 2;
        if (pf < NC) issue(ps, pf);
        CP_COMMIT();
        uint32_t st = sb + s * STAGE_SZ;
#pragma unroll
        for (int h = 0; h < 4; ++h) {
            uint32_t a[4][4], q0[4], q1[4];
#pragma unroll
            for (int mi = 0; mi < 4; ++mi) LDSM4(a[mi], st + aA0[h] + mi * 2048);
            LDSM4(q0, st + aB0[h]);
            LDSM4(q1, st + aB0[h] + 2048);
#pragma unroll
            for (int mi = 0; mi < 4; ++mi) {
                MMAF16(acc[mi][0], a[mi], q0[0], q0[1]);
                MMAF16(acc[mi][1], a[mi], q0[2], q0[3]);
                MMAF16(acc[mi][2], a[mi], q1[0], q1[1]);
                MMAF16(acc[mi][3], a[mi], q1[2], q1[3]);
            }
        }
        s = (s == 2) ? 0 : s + 1;
        ps = (ps == 2) ? 0 : ps + 1;
    }

    // epilogue
#pragma unroll
    for (int mi = 0; mi < 4; ++mi) {
        int r0 = rowbase + wm + mi * 16 + (lane >> 2);
#pragma unroll
        for (int nj = 0; nj < 4; ++nj) {
            if (MODE == 0) {
                int col = bn + wn + nj * 8 + (lane & 3) * 2;
                *(float2*)(Cf + (size_t)r0 * Nout + col) =
                    make_float2(acc[mi][nj][0], acc[mi][nj][1]);
                *(float2*)(Cf + (size_t)(r0 + 8) * Nout + col) =
                    make_float2(acc[mi][nj][2], acc[mi][nj][3]);
            } else {
                int oc = ((bn + wn) >> 1) + nj * 4 + (lane & 3);
                float g0 = acc[mi][nj][0], u0 = acc[mi][nj][1];
                float g1 = acc[mi][nj][2], u1 = acc[mi][nj][3];
                float v0 = g0 / (1.f + expf(-g0)) * u0;
                float v1 = g1 / (1.f + expf(-g1)) * u1;
                H[(size_t)r0 * Nout + oc] = __float2half(v0);
                H[(size_t)(r0 + 8) * Nout + oc] = __float2half(v1);
            }
        }
    }
}

__global__ void combine_kernel(float* __restrict__ out, int T) {
    int idx = blockIdx.x * blockDim.x + threadIdx.x;
    int total = T * (D_DIM / 4);
    if (idx >= total) return;
    int t = idx >> 8;
    int c = idx & 255;
    int r0 = g_slotRow[2 * t], r1 = g_slotRow[2 * t + 1];
    float w0 = g_topW[2 * t], w1 = g_topW[2 * t + 1];
    float sgt = g_sgate[t];
    const float4* y4 = (const float4*)g_y;
    const float4* s4 = (const float4*)g_ysh;
    float4 a = y4[(size_t)r0 * 256 + c];
    float4 b = y4[(size_t)r1 * 256 + c];
    float4 sh = s4[(size_t)t * 256 + c];
    float4 o;
    o.x = w0 * a.x + w1 * b.x + sgt * sh.x;
    o.y = w0 * a.y + w1 * b.y + sgt * sh.y;
    o.z = w0 * a.z + w1 * b.z + sgt * sh.z;
    o.w = w0 * a.w + w1 * b.w + sgt * sh.w;
    ((float4*)out)[idx] = o;
}

// ---------------- launcher: 4-stream fork/join, row-halved chains ----------------
// Streams/events created ONCE and reused (per-call creation tripped the
// device-memory guard in R9). Fallback: all on stream 0 in sequentially
// correct order.
static cudaStream_t s_sA = 0, s_sB = 0, s_sC = 0;
static cudaEvent_t s_evRoot = 0, s_evX = 0, s_evWsh = 0, s_evMeta = 0,
                   s_evW = 0, s_evA = 0, s_evB = 0, s_evC = 0;
static int s_init_state = 0;

extern "C" void kernel_launch(void* const* d_in, const int* in_sizes, int n_in,
                              void* d_out, int out_size) {
    const float* x   = (const float*)d_in[0];
    const float* gw  = (const float*)d_in[1];
    const float* eg  = (const float*)d_in[2];
    const float* eu  = (const float*)d_in[3];
    const float* ed  = (const float*)d_in[4];
    const float* sg  = (const float*)d_in[5];
    const float* su  = (const float*)d_in[6];
    const float* sd  = (const float*)d_in[7];
    const float* sgw = (const float*)d_in[8];
    float* out = (float*)d_out;
    int T = in_sizes[0] / D_DIM;
    int Th = T / 2;

    __half *xs, *hh, *hs, *bgu, *bd, *bgsh, *bdsh;
    float *yb, *ysh;
    int *gtok, *tileE;
    cudaGetSymbolAddress((void**)&xs, g_xs);
    cudaGetSymbolAddress((void**)&hh, g_h);
    cudaGetSymbolAddress((void**)&hs, g_hs);
    cudaGetSymbolAddress((void**)&bgu, g_Bgu);
    cudaGetSymbolAddress((void**)&bd, g_Bd);
    cudaGetSymbolAddress((void**)&bgsh, g_Bgsh);
    cudaGetSymbolAddress((void**)&bdsh, g_Bdsh);
    cudaGetSymbolAddress((void**)&yb, g_y);
    cudaGetSymbolAddress((void**)&ysh, g_ysh);
    cudaGetSymbolAddress((void**)&gtok, g_gatherTok);
    cudaGetSymbolAddress((void**)&tileE, g_tileExpert);

    cudaFuncSetAttribute(hgemm<0>, cudaFuncAttributeMaxDynamicSharedMemorySize, SMEM_SZ);
    cudaFuncSetAttribute(hgemm<1>, cudaFuncAttributeMaxDynamicSharedMemorySize, SMEM_SZ);

    int write_logits = (out_size > T * D_DIM) ? 1 : 0;
    float* logits_out = out + (size_t)T * D_DIM;

    if (s_init_state == 0) {
        bool o = true;
        o = o && (cudaStreamCreateWithFlags(&s_sA, cudaStreamNonBlocking) == cudaSuccess);
        o = o && (cudaStreamCreateWithFlags(&s_sB, cudaStreamNonBlocking) == cudaSuccess);
        o = o && (cudaStreamCreateWithFlags(&s_sC, cudaStreamNonBlocking) == cudaSuccess);
        o = o && (cudaEventCreateWithFlags(&s_evRoot, cudaEventDisableTiming) == cudaSuccess);
        o = o && (cudaEventCreateWithFlags(&s_evX,    cudaEventDisableTiming) == cudaSuccess);
        o = o && (cudaEventCreateWithFlags(&s_evWsh,  cudaEventDisableTiming) == cudaSuccess);
        o = o && (cudaEventCreateWithFlags(&s_evMeta, cudaEventDisableTiming) == cudaSuccess);
        o = o && (cudaEventCreateWithFlags(&s_evW,    cudaEventDisableTiming) == cudaSuccess);
        o = o && (cudaEventCreateWithFlags(&s_evA,    cudaEventDisableTiming) == cudaSuccess);
        o = o && (cudaEventCreateWithFlags(&s_evB,    cudaEventDisableTiming) == cudaSuccess);
        o = o && (cudaEventCreateWithFlags(&s_evC,    cudaEventDisableTiming) == cudaSuccess);
        s_init_state = o ? 1 : -1;
    }
    bool ok = (s_init_state == 1);
    cudaStream_t sA = ok ? s_sA : 0, sB = ok ? s_sB : 0, sC = ok ? s_sC : 0;

    if (ok) {
        cudaEventRecord(s_evRoot, 0);
        cudaStreamWaitEvent(sA, s_evRoot, 0);
        cudaStreamWaitEvent(sB, s_evRoot, 0);
        cudaStreamWaitEvent(sC, s_evRoot, 0);
    }

    // ---- sA: convx ----
    convx_kernel<<<(T * D_DIM / 2 + 255) / 256, 256, 0, sA>>>(x, xs, T * D_DIM / 2);
    if (ok) cudaEventRecord(s_evX, sA);

    // ---- sB: MoE metadata chain ----
    zero_meta_kernel<<<(MAXROWS + 255) / 256, 256, 0, sB>>>();
    router_kernel<<<(T * 32 + 255) / 256, 256, 0, sB>>>(x, gw, sgw, logits_out,
                                                        write_logits, T);
    scan_kernel<<<1, 32, 0, sB>>>();
    gather_kernel<<<(T + 255) / 256, 256, 0, sB>>>(T);
    if (ok) cudaEventRecord(s_evMeta, sB);

    // ---- sA: shared-expert weight transposes ----
    wtrans_kernel<<<dim3(ISH / 32, D_DIM / 32, 1), 256, 0, sA>>>(
        sg, bgsh, D_DIM, ISH, 0, 0, 2, 0);
    wtrans_kernel<<<dim3(ISH / 32, D_DIM / 32, 1), 256, 0, sA>>>(
        su, bgsh, D_DIM, ISH, 0, 0, 2, 1);
    wtrans_kernel<<<dim3(D_DIM / 32, ISH / 32, 1), 256, 0, sA>>>(
        sd, bdsh, ISH, D_DIM, 0, 0, 1, 0);
    if (ok) cudaEventRecord(s_evWsh, sA);

    // ---- s0: MoE weight transposes ----
    wtrans_kernel<<<dim3(IMOE / 32, D_DIM / 32, E_NUM), 256>>>(
        eg, bgu, D_DIM, IMOE, (long long)D_DIM * IMOE, 2LL * IMOE * D_DIM, 2, 0);
    wtrans_kernel<<<dim3(IMOE / 32, D_DIM / 32, E_NUM), 256>>>(
        eu, bgu, D_DIM, IMOE, (long long)D_DIM * IMOE, 2LL * IMOE * D_DIM, 2, 1);
    wtrans_kernel<<<dim3(D_DIM / 32, IMOE / 32, E_NUM), 256>>>(
        ed, bd, IMOE, D_DIM, (long long)IMOE * D_DIM, (long long)D_DIM * IMOE, 1, 0);
    if (ok) cudaEventRecord(s_evW, 0);

    // ---- GU GEMMs (4 half-chains, tile N=128) ----
    hgemm<1><<<dim3(2 * ISH / 128, Th / 128), 256, SMEM_SZ, sA>>>(
        xs, bgsh, 0, nullptr, hs, nullptr, nullptr, D_DIM, ISH);
    if (ok) cudaStreamWaitEvent(sC, s_evWsh, 0);   // implies convx done (sA order)
    hgemm<1><<<dim3(2 * ISH / 128, Th / 128), 256, SMEM_SZ, sC>>>(
        xs + (size_t)Th * D_DIM, bgsh, 0, nullptr, hs + (size_t)Th * ISH,
        nullptr, nullptr, D_DIM, ISH);
    if (ok) { cudaStreamWaitEvent(0, s_evMeta, 0); cudaStreamWaitEvent(0, s_evX, 0); }
    hgemm<1><<<dim3(2 * IMOE / 128, HTILES), 256, SMEM_SZ>>>(
        xs, bgu, 2LL * IMOE * D_DIM, nullptr, hh, gtok, tileE, D_DIM, IMOE);
    if (ok) { cudaStreamWaitEvent(sB, s_evW, 0); cudaStreamWaitEvent(sB, s_evX, 0); }
    hgemm<1><<<dim3(2 * IMOE / 128, HTILES), 256, SMEM_SZ, sB>>>(
        xs, bgu, 2LL * IMOE * D_DIM, nullptr, hh + (size_t)HTILES * 128 * IMOE,
        gtok + HTILES * 128, tileE + HTILES, D_DIM, IMOE);

    // ---- down GEMMs (4 half-chains) ----
    hgemm<0><<<dim3(D_DIM / 128, Th / 128), 256, SMEM_SZ, sA>>>(
        hs, bdsh, 0, ysh, nullptr, nullptr, nullptr, ISH, D_DIM);
    if (ok) cudaEventRecord(s_evA, sA);
    hgemm<0><<<dim3(D_DIM / 128, Th / 128), 256, SMEM_SZ, sC>>>(
        hs + (size_t)Th * ISH, bdsh, 0, ysh + (size_t)Th * D_DIM,
        nullptr, nullptr, nullptr, ISH, D_DIM);
    if (ok) cudaEventRecord(s_evC, sC);
    hgemm<0><<<dim3(D_DIM / 128, HTILES), 256, SMEM_SZ>>>(
        hh, bd, (long long)D_DIM * IMOE, yb, nullptr, nullptr, tileE, IMOE, D_DIM);
    hgemm<0><<<dim3(D_DIM / 128, HTILES), 256, SMEM_SZ, sB>>>(
        hh + (size_t)HTILES * 128 * IMOE, bd, (long long)D_DIM * IMOE,
        yb + (size_t)HTILES * 128 * D_DIM, nullptr, nullptr, tileE + HTILES,
        IMOE, D_DIM);
    if (ok) cudaEventRecord(s_evB, sB);

    // ---- join + combine on s0 ----
    if (ok) {
        cudaStreamWaitEvent(0, s_evA, 0);
        cudaStreamWaitEvent(0, s_evB, 0);
        cudaStreamWaitEvent(0, s_evC, 0);
    }
    combine_kernel<<<(T * (D_DIM / 4) + 255) / 256, 256>>>(out, T);
}

// round 12
// speedup vs baseline: 9.3004x; 1.0067x over previous
#include <cuda_runtime.h>
#include <cuda_bf16.h>
#include <cuda_fp16.h>
#include <cstdint>

#define TKN      8192
#define D_DIM    1024
#define E_NUM    8
#define IMOE     1024
#define ISH      4096
#define MAXROWS  17408
#define MAXTILES 136
#define HTILES   68            // MAXTILES/2
#define NSTAGE   3
#define STAGE_SZ 32768          // A 16KB + B 16KB  (tile 128x128, BK=64)
#define SMEM_SZ  (NSTAGE * STAGE_SZ)   // 98304 -> 2 CTAs/SM

// ---------------- helpers ----------------
__device__ __forceinline__ uint32_t smem_u32(const void* p) {
    uint32_t a;
    asm("{ .reg .u64 t; cvta.to.shared.u64 t, %1; cvt.u32.u64 %0, t; }" : "=r"(a) : "l"(p));
    return a;
}
__device__ __forceinline__ void cpa16(uint32_t s, const void* g) {
    asm volatile("cp.async.cg.shared.global [%0], [%1], 16;" :: "r"(s), "l"(g));
}
#define CP_COMMIT() asm volatile("cp.async.commit_group;" ::: "memory")
#define CP_WAIT1()  asm volatile("cp.async.wait_group 1;" ::: "memory")

#define LDSM4(R, addr) \
    asm volatile("ldmatrix.sync.aligned.m8n8.x4.shared.b16 {%0,%1,%2,%3}, [%4];" \
        : "=r"((R)[0]), "=r"((R)[1]), "=r"((R)[2]), "=r"((R)[3]) : "r"(addr))

#define MMAF16(C, A, B0, B1) \
    asm volatile("mma.sync.aligned.m16n8k16.row.col.f32.f16.f16.f32 " \
        "{%0,%1,%2,%3},{%4,%5,%6,%7},{%8,%9},{%0,%1,%2,%3};" \
        : "+f"((C)[0]), "+f"((C)[1]), "+f"((C)[2]), "+f"((C)[3]) \
        : "r"((A)[0]), "r"((A)[1]), "r"((A)[2]), "r"((A)[3]), "r"(B0), "r"(B1))

// canonical SW128 swizzle: 128B rows, 8 x 16B groups, XOR by row&7
__device__ __forceinline__ uint32_t swz64(int r, int c8) {
    return (uint32_t)(r * 128 + ((c8 ^ (r & 7)) << 4));
}

// ---------------- device scratch ----------------
__device__ __align__(256) __half g_xs [(size_t)TKN * D_DIM];
__device__ __align__(256) __half g_h  [(size_t)MAXROWS * IMOE];
__device__ __align__(256) __half g_hs [(size_t)TKN * ISH];
__device__ __align__(256) float  g_y  [(size_t)MAXROWS * D_DIM];
__device__ __align__(256) float  g_ysh[(size_t)TKN * D_DIM];
__device__ __align__(256) __half g_Bgu [(size_t)E_NUM * 2 * IMOE * D_DIM];
__device__ __align__(256) __half g_Bd  [(size_t)E_NUM * D_DIM * IMOE];
__device__ __align__(256) __half g_Bgsh[(size_t)2 * ISH * D_DIM];
__device__ __align__(256) __half g_Bdsh[(size_t)D_DIM * ISH];

__device__ int   g_counts[E_NUM];
__device__ int   g_fill[E_NUM];
__device__ int   g_offs[E_NUM];
__device__ int   g_topE[2 * TKN];
__device__ float g_topW[2 * TKN];
__device__ float g_sgate[TKN];
__device__ int   g_gatherTok[MAXROWS];
__device__ int   g_slotRow[2 * TKN];
__device__ int   g_tileExpert[MAXTILES];

// ---------------- small kernels ----------------
__global__ void zero_meta_kernel() {
    int i = blockIdx.x * blockDim.x + threadIdx.x;
    if (i < MAXROWS) g_gatherTok[i] = 0;
    if (i < E_NUM) { g_counts[i] = 0; g_fill[i] = 0; }
    if (i < MAXTILES) g_tileExpert[i] = -1;
}

__global__ void router_kernel(const float* __restrict__ x, const float* __restrict__ gw,
                              const float* __restrict__ sgw, float* __restrict__ logits_out,
                              int write_logits, int T) {
    int gwarp = (blockIdx.x * blockDim.x + threadIdx.x) >> 5;
    int lane  = threadIdx.x & 31;
    if (gwarp >= T) return;
    const float* xr = x + (size_t)gwarp * D_DIM;
    float acc[9];
#pragma unroll
    for (int i = 0; i < 9; ++i) acc[i] = 0.f;
    for (int d = lane; d < D_DIM; d += 32) {
        float xv = xr[d];
        const float4* g4 = (const float4*)(gw + (size_t)d * E_NUM);
        float4 w0 = g4[0], w1 = g4[1];
        acc[0] += xv * w0.x; acc[1] += xv * w0.y; acc[2] += xv * w0.z; acc[3] += xv * w0.w;
        acc[4] += xv * w1.x; acc[5] += xv * w1.y; acc[6] += xv * w1.z; acc[7] += xv * w1.w;
        acc[8] += xv * sgw[d];
    }
#pragma unroll
    for (int o = 16; o; o >>= 1)
#pragma unroll
        for (int i = 0; i < 9; ++i) acc[i] += __shfl_xor_sync(0xffffffffu, acc[i], o);
    if (lane == 0) {
        float mx = acc[0];
#pragma unroll
        for (int e = 1; e < E_NUM; ++e) mx = fmaxf(mx, acc[e]);
        float p[E_NUM], s = 0.f;
#pragma unroll
        for (int e = 0; e < E_NUM; ++e) { p[e] = expf(acc[e] - mx); s += p[e]; }
        float inv = 1.f / s;
#pragma unroll
        for (int e = 0; e < E_NUM; ++e) p[e] *= inv;
        int i0 = 0;
#pragma unroll
        for (int e = 1; e < E_NUM; ++e) if (p[e] > p[i0]) i0 = e;
        int i1 = (i0 == 0) ? 1 : 0;
#pragma unroll
        for (int e = 0; e < E_NUM; ++e) if (e != i0 && p[e] > p[i1]) i1 = e;
        float w0 = p[i0], w1 = p[i1];
        float invs = 1.f / fmaxf(w0 + w1, 1e-6f);
        g_topE[2 * gwarp] = i0; g_topE[2 * gwarp + 1] = i1;
        g_topW[2 * gwarp] = w0 * invs; g_topW[2 * gwarp + 1] = w1 * invs;
        g_sgate[gwarp] = 1.f / (1.f + expf(-acc[8]));
        atomicAdd(&g_counts[i0], 1);
        atomicAdd(&g_counts[i1], 1);
        if (write_logits) {
#pragma unroll
            for (int e = 0; e < E_NUM; ++e)
                logits_out[(size_t)gwarp * E_NUM + e] = acc[e];
        }
    }
}

__global__ void scan_kernel() {
    if (threadIdx.x == 0) {
        int s = 0;
        for (int e = 0; e < E_NUM; ++e) {
            g_offs[e] = s;
            int tl = (g_counts[e] + 127) >> 7;
            for (int t = 0; t < tl; ++t) g_tileExpert[(s >> 7) + t] = e;
            s += tl << 7;
        }
    }
}

__global__ void gather_kernel(int T) {
    int t = blockIdx.x * blockDim.x + threadIdx.x;
    if (t >= T) return;
#pragma unroll
    for (int k = 0; k < 2; ++k) {
        int e = g_topE[2 * t + k];
        int p = atomicAdd(&g_fill[e], 1);
        int row = g_offs[e] + p;
        g_gatherTok[row] = t;
        g_slotRow[2 * t + k] = row;
    }
}

__global__ void convx_kernel(const float* __restrict__ x, __half* __restrict__ xo, int n2) {
    int i = blockIdx.x * blockDim.x + threadIdx.x;
    if (i >= n2) return;
    float2 v = ((const float2*)x)[i];
    ((__half2*)xo)[i] = __floats2half2_rn(v.x, v.y);
}

// weights: src[e][k][n] fp32 -> dst[e][n*rowMul+rowAdd][k] fp16 (k-major rows)
__global__ __launch_bounds__(256)
void wtrans_kernel(const float* __restrict__ src, __half* __restrict__ dst,
                   int Ks, int Ns, long long srcE, long long dstE,
                   int rowMul, int rowAdd) {
    src += (long long)blockIdx.z * srcE;
    dst += (long long)blockIdx.z * dstE;
    int tk0 = blockIdx.y * 32, tn0 = blockIdx.x * 32;
    __shared__ float tile[32][33];
    int tx = threadIdx.x & 31, ty = threadIdx.x >> 5;
#pragma unroll
    for (int r = 0; r < 4; ++r) {
        int k = ty + r * 8;
        tile[k][tx] = src[(long long)(tk0 + k) * Ns + tn0 + tx];
    }
    __syncthreads();
    int kk = (threadIdx.x & 7) * 4;
    int nn = threadIdx.x >> 3;
    long long drow = (long long)((tn0 + nn) * rowMul + rowAdd) * Ks + tk0 + kk;
    __align__(8) unsigned short hv[4];
#pragma unroll
    for (int q = 0; q < 4; ++q)
        hv[q] = __half_as_ushort(__float2half(tile[kk + q][nn]));
    *(uint2*)(dst + drow) = *(uint2*)hv;
}

// ---------------- HMMA fp16 GEMM ----------------
// CTA tile 128x128, BK=64, 3-stage cp.async pipeline, 128 threads
// (4 warps 2x2, warp tile 64x64), 2 CTAs/SM. fp32 accumulate.
// 64x64 warp tile doubles MMA-per-LDSM vs 64x32, relieving the smem port
// (the R11 bottleneck: ~125 B/cyc vs the 128 B/cyc crossbar cap).
// MODE 0: Cf[(rowbase+m)*Nout + bn+n] = acc
// MODE 1: adjacent cols (even=gate, odd=up) -> silu(g)*u -> fp16 plane H
template <int MODE>
__global__ __launch_bounds__(128, 2)
void hgemm(const __half* __restrict__ A, const __half* __restrict__ B,
           long long bStride, float* __restrict__ Cf, __half* __restrict__ H,
           const int* __restrict__ gTok, const int* __restrict__ tileE,
           int K, int Nout) {
    int e = 0;
    if (tileE) { e = tileE[blockIdx.y]; if (e < 0) return; }
    int rowbase = blockIdx.y * 128;
    int bn = blockIdx.x * 128;
    const char* pA = (const char*)A;
    const char* pB = (const char*)(B + (long long)e * bStride);

    extern __shared__ __align__(1024) char smem[];
    uint32_t sb = smem_u32(smem);
    int tid = threadIdx.x;

    // loader precompute: A 8 chunks + B 8 chunks per thread (16B each),
    // 32-bit base offsets (all operand buffers < 256 MB)
    uint32_t aB[8], bB[8], dA[8], dB[8];
#pragma unroll
    for (int i = 0; i < 8; ++i) {
        int q = tid + 128 * i, r = q >> 3, c8 = q & 7;
        int ar = rowbase + r;
        int tok = gTok ? gTok[ar] : ar;
        aB[i] = (uint32_t)((tok * K + c8 * 8) * 2);
        dA[i] = swz64(r, c8);
        bB[i] = (uint32_t)(((bn + r) * K + c8 * 8) * 2);
        dB[i] = 16384 + swz64(r, c8);
    }
    auto issue = [&](int s, int c) {
        uint32_t st = sb + s * STAGE_SZ;
        uint32_t off = (uint32_t)c * 128;
#pragma unroll
        for (int i = 0; i < 8; ++i) cpa16(st + dA[i], pA + aB[i] + off);
#pragma unroll
        for (int i = 0; i < 8; ++i) cpa16(st + dB[i], pB + bB[i] + off);
    };

    // compute precompute: h-indexed bases; mi/np folded as +2048*idx
    // (row+16 keeps row&7, so swz64(row+16,c8) = swz64(row,c8)+2048)
    int lane = tid & 31, w = tid >> 5;
    int wm = (w & 1) * 64, wn = (w >> 1) * 64;
    uint32_t aA0[4], aB0[4];
    {
        int rowA = wm + (lane & 15);
        int rowB = wn + (lane & 7) + ((lane >> 4) << 3);
#pragma unroll
        for (int h = 0; h < 4; ++h) {
            aA0[h] = swz64(rowA, 2 * h + (lane >> 4));
            aB0[h] = 16384 + swz64(rowB, 2 * h + ((lane >> 3) & 1));
        }
    }

    float acc[4][8][4];
#pragma unroll
    for (int mi = 0; mi < 4; ++mi)
#pragma unroll
        for (int nj = 0; nj < 8; ++nj)
#pragma unroll
            for (int q = 0; q < 4; ++q) acc[mi][nj][q] = 0.f;

    int NC = K >> 6;

    issue(0, 0); CP_COMMIT();
    issue(1, 1); CP_COMMIT();

    int s = 0, ps = 2;
    for (int c = 0; c < NC; ++c) {
        CP_WAIT1();
        __syncthreads();
        // prefetch into the stage consumed in iter c-1 (all warps are past it)
        int pf = c + 2;
        if (pf < NC) issue(ps, pf);
        CP_COMMIT();
        uint32_t st = sb + s * STAGE_SZ;
#pragma unroll
        for (int h = 0; h < 4; ++h) {
            uint32_t a[4][4], b[8][2];
#pragma unroll
            for (int mi = 0; mi < 4; ++mi) LDSM4(a[mi], st + aA0[h] + mi * 2048);
#pragma unroll
            for (int np = 0; np < 4; ++np) {
                uint32_t q[4];
                LDSM4(q, st + aB0[h] + np * 2048);
                b[2 * np][0] = q[0]; b[2 * np][1] = q[1];
                b[2 * np + 1][0] = q[2]; b[2 * np + 1][1] = q[3];
            }
#pragma unroll
            for (int mi = 0; mi < 4; ++mi)
#pragma unroll
                for (int nj = 0; nj < 8; ++nj)
                    MMAF16(acc[mi][nj], a[mi], b[nj][0], b[nj][1]);
        }
        s = (s == 2) ? 0 : s + 1;
        ps = (ps == 2) ? 0 : ps + 1;
    }

    // epilogue
#pragma unroll
    for (int mi = 0; mi < 4; ++mi) {
        int r0 = rowbase + wm + mi * 16 + (lane >> 2);
#pragma unroll
        for (int nj = 0; nj < 8; ++nj) {
            if (MODE == 0) {
                int col = bn + wn + nj * 8 + (lane & 3) * 2;
                *(float2*)(Cf + (size_t)r0 * Nout + col) =
                    make_float2(acc[mi][nj][0], acc[mi][nj][1]);
                *(float2*)(Cf + (size_t)(r0 + 8) * Nout + col) =
                    make_float2(acc[mi][nj][2], acc[mi][nj][3]);
            } else {
                int oc = ((bn + wn) >> 1) + nj * 4 + (lane & 3);
                float g0 = acc[mi][nj][0], u0 = acc[mi][nj][1];
                float g1 = acc[mi][nj][2], u1 = acc[mi][nj][3];
                float v0 = g0 / (1.f + expf(-g0)) * u0;
                float v1 = g1 / (1.f + expf(-g1)) * u1;
                H[(size_t)r0 * Nout + oc] = __float2half(v0);
                H[(size_t)(r0 + 8) * Nout + oc] = __float2half(v1);
            }
        }
    }
}

__global__ void combine_kernel(float* __restrict__ out, int T) {
    int idx = blockIdx.x * blockDim.x + threadIdx.x;
    int total = T * (D_DIM / 4);
    if (idx >= total) return;
    int t = idx >> 8;
    int c = idx & 255;
    int r0 = g_slotRow[2 * t], r1 = g_slotRow[2 * t + 1];
    float w0 = g_topW[2 * t], w1 = g_topW[2 * t + 1];
    float sgt = g_sgate[t];
    const float4* y4 = (const float4*)g_y;
    const float4* s4 = (const float4*)g_ysh;
    float4 a = y4[(size_t)r0 * 256 + c];
    float4 b = y4[(size_t)r1 * 256 + c];
    float4 sh = s4[(size_t)t * 256 + c];
    float4 o;
    o.x = w0 * a.x + w1 * b.x + sgt * sh.x;
    o.y = w0 * a.y + w1 * b.y + sgt * sh.y;
    o.z = w0 * a.z + w1 * b.z + sgt * sh.z;
    o.w = w0 * a.w + w1 * b.w + sgt * sh.w;
    ((float4*)out)[idx] = o;
}

// ---------------- launcher: 4-stream fork/join, row-halved chains ----------------
// Streams/events created ONCE and reused (per-call creation tripped the
// device-memory guard in R9). Fallback: all on stream 0 in sequentially
// correct order.
static cudaStream_t s_sA = 0, s_sB = 0, s_sC = 0;
static cudaEvent_t s_evRoot = 0, s_evX = 0, s_evWsh = 0, s_evMeta = 0,
                   s_evW = 0, s_evA = 0, s_evB = 0, s_evC = 0;
static int s_init_state = 0;

extern "C" void kernel_launch(void* const* d_in, const int* in_sizes, int n_in,
                              void* d_out, int out_size) {
    const float* x   = (const float*)d_in[0];
    const float* gw  = (const float*)d_in[1];
    const float* eg  = (const float*)d_in[2];
    const float* eu  = (const float*)d_in[3];
    const float* ed  = (const float*)d_in[4];
    const float* sg  = (const float*)d_in[5];
    const float* su  = (const float*)d_in[6];
    const float* sd  = (const float*)d_in[7];
    const float* sgw = (const float*)d_in[8];
    float* out = (float*)d_out;
    int T = in_sizes[0] / D_DIM;
    int Th = T / 2;

    __half *xs, *hh, *hs, *bgu, *bd, *bgsh, *bdsh;
    float *yb, *ysh;
    int *gtok, *tileE;
    cudaGetSymbolAddress((void**)&xs, g_xs);
    cudaGetSymbolAddress((void**)&hh, g_h);
    cudaGetSymbolAddress((void**)&hs, g_hs);
    cudaGetSymbolAddress((void**)&bgu, g_Bgu);
    cudaGetSymbolAddress((void**)&bd, g_Bd);
    cudaGetSymbolAddress((void**)&bgsh, g_Bgsh);
    cudaGetSymbolAddress((void**)&bdsh, g_Bdsh);
    cudaGetSymbolAddress((void**)&yb, g_y);
    cudaGetSymbolAddress((void**)&ysh, g_ysh);
    cudaGetSymbolAddress((void**)&gtok, g_gatherTok);
    cudaGetSymbolAddress((void**)&tileE, g_tileExpert);

    cudaFuncSetAttribute(hgemm<0>, cudaFuncAttributeMaxDynamicSharedMemorySize, SMEM_SZ);
    cudaFuncSetAttribute(hgemm<1>, cudaFuncAttributeMaxDynamicSharedMemorySize, SMEM_SZ);

    int write_logits = (out_size > T * D_DIM) ? 1 : 0;
    float* logits_out = out + (size_t)T * D_DIM;

    if (s_init_state == 0) {
        bool o = true;
        o = o && (cudaStreamCreateWithFlags(&s_sA, cudaStreamNonBlocking) == cudaSuccess);
        o = o && (cudaStreamCreateWithFlags(&s_sB, cudaStreamNonBlocking) == cudaSuccess);
        o = o && (cudaStreamCreateWithFlags(&s_sC, cudaStreamNonBlocking) == cudaSuccess);
        o = o && (cudaEventCreateWithFlags(&s_evRoot, cudaEventDisableTiming) == cudaSuccess);
        o = o && (cudaEventCreateWithFlags(&s_evX,    cudaEventDisableTiming) == cudaSuccess);
        o = o && (cudaEventCreateWithFlags(&s_evWsh,  cudaEventDisableTiming) == cudaSuccess);
        o = o && (cudaEventCreateWithFlags(&s_evMeta, cudaEventDisableTiming) == cudaSuccess);
        o = o && (cudaEventCreateWithFlags(&s_evW,    cudaEventDisableTiming) == cudaSuccess);
        o = o && (cudaEventCreateWithFlags(&s_evA,    cudaEventDisableTiming) == cudaSuccess);
        o = o && (cudaEventCreateWithFlags(&s_evB,    cudaEventDisableTiming) == cudaSuccess);
        o = o && (cudaEventCreateWithFlags(&s_evC,    cudaEventDisableTiming) == cudaSuccess);
        s_init_state = o ? 1 : -1;
    }
    bool ok = (s_init_state == 1);
    cudaStream_t sA = ok ? s_sA : 0, sB = ok ? s_sB : 0, sC = ok ? s_sC : 0;

    if (ok) {
        cudaEventRecord(s_evRoot, 0);
        cudaStreamWaitEvent(sA, s_evRoot, 0);
        cudaStreamWaitEvent(sB, s_evRoot, 0);
        cudaStreamWaitEvent(sC, s_evRoot, 0);
    }

    // ---- sA: convx ----
    convx_kernel<<<(T * D_DIM / 2 + 255) / 256, 256, 0, sA>>>(x, xs, T * D_DIM / 2);
    if (ok) cudaEventRecord(s_evX, sA);

    // ---- sB: MoE metadata chain ----
    zero_meta_kernel<<<(MAXROWS + 255) / 256, 256, 0, sB>>>();
    router_kernel<<<(T * 32 + 255) / 256, 256, 0, sB>>>(x, gw, sgw, logits_out,
                                                        write_logits, T);
    scan_kernel<<<1, 32, 0, sB>>>();
    gather_kernel<<<(T + 255) / 256, 256, 0, sB>>>(T);
    if (ok) cudaEventRecord(s_evMeta, sB);

    // ---- sA: shared-expert weight transposes ----
    wtrans_kernel<<<dim3(ISH / 32, D_DIM / 32, 1), 256, 0, sA>>>(
        sg, bgsh, D_DIM, ISH, 0, 0, 2, 0);
    wtrans_kernel<<<dim3(ISH / 32, D_DIM / 32, 1), 256, 0, sA>>>(
        su, bgsh, D_DIM, ISH, 0, 0, 2, 1);
    wtrans_kernel<<<dim3(D_DIM / 32, ISH / 32, 1), 256, 0, sA>>>(
        sd, bdsh, ISH, D_DIM, 0, 0, 1, 0);
    if (ok) cudaEventRecord(s_evWsh, sA);

    // ---- s0: MoE weight transposes ----
    wtrans_kernel<<<dim3(IMOE / 32, D_DIM / 32, E_NUM), 256>>>(
        eg, bgu, D_DIM, IMOE, (long long)D_DIM * IMOE, 2LL * IMOE * D_DIM, 2, 0);
    wtrans_kernel<<<dim3(IMOE / 32, D_DIM / 32, E_NUM), 256>>>(
        eu, bgu, D_DIM, IMOE, (long long)D_DIM * IMOE, 2LL * IMOE * D_DIM, 2, 1);
    wtrans_kernel<<<dim3(D_DIM / 32, IMOE / 32, E_NUM), 256>>>(
        ed, bd, IMOE, D_DIM, (long long)IMOE * D_DIM, (long long)D_DIM * IMOE, 1, 0);
    if (ok) cudaEventRecord(s_evW, 0);

    // ---- GU GEMMs (4 half-chains, tile N=128, 128 threads) ----
    hgemm<1><<<dim3(2 * ISH / 128, Th / 128), 128, SMEM_SZ, sA>>>(
        xs, bgsh, 0, nullptr, hs, nullptr, nullptr, D_DIM, ISH);
    if (ok) cudaStreamWaitEvent(sC, s_evWsh, 0);   // implies convx done (sA order)
    hgemm<1><<<dim3(2 * ISH / 128, Th / 128), 128, SMEM_SZ, sC>>>(
        xs + (size_t)Th * D_DIM, bgsh, 0, nullptr, hs + (size_t)Th * ISH,
        nullptr, nullptr, D_DIM, ISH);
    if (ok) { cudaStreamWaitEvent(0, s_evMeta, 0); cudaStreamWaitEvent(0, s_evX, 0); }
    hgemm<1><<<dim3(2 * IMOE / 128, HTILES), 128, SMEM_SZ>>>(
        xs, bgu, 2LL * IMOE * D_DIM, nullptr, hh, gtok, tileE, D_DIM, IMOE);
    if (ok) { cudaStreamWaitEvent(sB, s_evW, 0); cudaStreamWaitEvent(sB, s_evX, 0); }
    hgemm<1><<<dim3(2 * IMOE / 128, HTILES), 128, SMEM_SZ, sB>>>(
        xs, bgu, 2LL * IMOE * D_DIM, nullptr, hh + (size_t)HTILES * 128 * IMOE,
        gtok + HTILES * 128, tileE + HTILES, D_DIM, IMOE);

    // ---- down GEMMs (4 half-chains) ----
    hgemm<0><<<dim3(D_DIM / 128, Th / 128), 128, SMEM_SZ, sA>>>(
        hs, bdsh, 0, ysh, nullptr, nullptr, nullptr, ISH, D_DIM);
    if (ok) cudaEventRecord(s_evA, sA);
    hgemm<0><<<dim3(D_DIM / 128, Th / 128), 128, SMEM_SZ, sC>>>(
        hs + (size_t)Th * ISH, bdsh, 0, ysh + (size_t)Th * D_DIM,
        nullptr, nullptr, nullptr, ISH, D_DIM);
    if (ok) cudaEventRecord(s_evC, sC);
    hgemm<0><<<dim3(D_DIM / 128, HTILES), 128, SMEM_SZ>>>(
        hh, bd, (long long)D_DIM * IMOE, yb, nullptr, nullptr, tileE, IMOE, D_DIM);
    hgemm<0><<<dim3(D_DIM / 128, HTILES), 128, SMEM_SZ, sB>>>(
        hh + (size_t)HTILES * 128 * IMOE, bd, (long long)D_DIM * IMOE,
        yb + (size_t)HTILES * 128 * D_DIM, nullptr, nullptr, tileE + HTILES,
        IMOE, D_DIM);
    if (ok) cudaEventRecord(s_evB, sB);

    // ---- join + combine on s0 ----
    if (ok) {
        cudaStreamWaitEvent(0, s_evA, 0);
        cudaStreamWaitEvent(0, s_evB, 0);
        cudaStreamWaitEvent(0, s_evC, 0);
    }
    combine_kernel<<<(T * (D_DIM / 4) + 255) / 256, 256>>>(out, T);
}

// round 13
// speedup vs baseline: 9.3662x; 1.0071x over previous
#include <cuda_runtime.h>
#include <cuda_bf16.h>
#include <cuda_fp16.h>
#include <cstdint>

#define TKN      8192
#define D_DIM    1024
#define E_NUM    8
#define IMOE     1024
#define ISH      4096
#define MAXROWS  17408
#define MAXTILES 136
#define HTILES   68            // MAXTILES/2
#define NSTAGE   3
#define STAGE_SZ 32768          // A 16KB + B 16KB  (tile 128x128, BK=64)
#define SMEM_SZ  (NSTAGE * STAGE_SZ)   // 98304 -> 2 CTAs/SM

// ---------------- helpers ----------------
__device__ __forceinline__ uint32_t smem_u32(const void* p) {
    uint32_t a;
    asm("{ .reg .u64 t; cvta.to.shared.u64 t, %1; cvt.u32.u64 %0, t; }" : "=r"(a) : "l"(p));
    return a;
}
__device__ __forceinline__ void cpa16(uint32_t s, const void* g) {
    asm volatile("cp.async.cg.shared.global [%0], [%1], 16;" :: "r"(s), "l"(g));
}
__device__ __forceinline__ void redadd(float* p, float v) {
    asm volatile("red.global.add.f32 [%0], %1;" :: "l"(p), "f"(v) : "memory");
}
#define CP_COMMIT() asm volatile("cp.async.commit_group;" ::: "memory")
#define CP_WAIT1()  asm volatile("cp.async.wait_group 1;" ::: "memory")

#define LDSM4(R, addr) \
    asm volatile("ldmatrix.sync.aligned.m8n8.x4.shared.b16 {%0,%1,%2,%3}, [%4];" \
        : "=r"((R)[0]), "=r"((R)[1]), "=r"((R)[2]), "=r"((R)[3]) : "r"(addr))

#define MMAF16(C, A, B0, B1) \
    asm volatile("mma.sync.aligned.m16n8k16.row.col.f32.f16.f16.f32 " \
        "{%0,%1,%2,%3},{%4,%5,%6,%7},{%8,%9},{%0,%1,%2,%3};" \
        : "+f"((C)[0]), "+f"((C)[1]), "+f"((C)[2]), "+f"((C)[3]) \
        : "r"((A)[0]), "r"((A)[1]), "r"((A)[2]), "r"((A)[3]), "r"(B0), "r"(B1))

// canonical SW128 swizzle: 128B rows, 8 x 16B groups, XOR by row&7
__device__ __forceinline__ uint32_t swz64(int r, int c8) {
    return (uint32_t)(r * 128 + ((c8 ^ (r & 7)) << 4));
}

// ---------------- device scratch ----------------
__device__ __align__(256) __half g_xs [(size_t)TKN * D_DIM];
__device__ __align__(256) __half g_h  [(size_t)MAXROWS * IMOE];
__device__ __align__(256) __half g_hs [(size_t)TKN * ISH];
__device__ __align__(256) __half g_Bgu [(size_t)E_NUM * 2 * IMOE * D_DIM];
__device__ __align__(256) __half g_Bd  [(size_t)E_NUM * D_DIM * IMOE];
__device__ __align__(256) __half g_Bgsh[(size_t)2 * ISH * D_DIM];
__device__ __align__(256) __half g_Bdsh[(size_t)D_DIM * ISH];

__device__ int   g_counts[E_NUM];
__device__ int   g_fill[E_NUM];
__device__ int   g_offs[E_NUM];
__device__ int   g_topE[2 * TKN];
__device__ float g_topW[2 * TKN];
__device__ float g_sgate[TKN];
__device__ int   g_gatherTok[MAXROWS];
__device__ float g_rowW[MAXROWS];
__device__ int   g_tileExpert[MAXTILES];

// ---------------- small kernels ----------------
__global__ void zero_meta_kernel() {
    int i = blockIdx.x * blockDim.x + threadIdx.x;
    if (i < MAXROWS) { g_gatherTok[i] = 0; g_rowW[i] = 0.f; }
    if (i < E_NUM) { g_counts[i] = 0; g_fill[i] = 0; }
    if (i < MAXTILES) g_tileExpert[i] = -1;
}

__global__ void zero_out_kernel(float4* __restrict__ o, int n4) {
    int i = blockIdx.x * blockDim.x + threadIdx.x;
    if (i < n4) o[i] = make_float4(0.f, 0.f, 0.f, 0.f);
}

__global__ void fin_kernel() {}

__global__ void router_kernel(const float* __restrict__ x, const float* __restrict__ gw,
                              const float* __restrict__ sgw, float* __restrict__ logits_out,
                              int write_logits, int T) {
    int gwarp = (blockIdx.x * blockDim.x + threadIdx.x) >> 5;
    int lane  = threadIdx.x & 31;
    if (gwarp >= T) return;
    const float* xr = x + (size_t)gwarp * D_DIM;
    float acc[9];
#pragma unroll
    for (int i = 0; i < 9; ++i) acc[i] = 0.f;
    for (int d = lane; d < D_DIM; d += 32) {
        float xv = xr[d];
        const float4* g4 = (const float4*)(gw + (size_t)d * E_NUM);
        float4 w0 = g4[0], w1 = g4[1];
        acc[0] += xv * w0.x; acc[1] += xv * w0.y; acc[2] += xv * w0.z; acc[3] += xv * w0.w;
        acc[4] += xv * w1.x; acc[5] += xv * w1.y; acc[6] += xv * w1.z; acc[7] += xv * w1.w;
        acc[8] += xv * sgw[d];
    }
#pragma unroll
    for (int o = 16; o; o >>= 1)
#pragma unroll
        for (int i = 0; i < 9; ++i) acc[i] += __shfl_xor_sync(0xffffffffu, acc[i], o);
    if (lane == 0) {
        float mx = acc[0];
#pragma unroll
        for (int e = 1; e < E_NUM; ++e) mx = fmaxf(mx, acc[e]);
        float p[E_NUM], s = 0.f;
#pragma unroll
        for (int e = 0; e < E_NUM; ++e) { p[e] = expf(acc[e] - mx); s += p[e]; }
        float inv = 1.f / s;
#pragma unroll
        for (int e = 0; e < E_NUM; ++e) p[e] *= inv;
        int i0 = 0;
#pragma unroll
        for (int e = 1; e < E_NUM; ++e) if (p[e] > p[i0]) i0 = e;
        int i1 = (i0 == 0) ? 1 : 0;
#pragma unroll
        for (int e = 0; e < E_NUM; ++e) if (e != i0 && p[e] > p[i1]) i1 = e;
        float w0 = p[i0], w1 = p[i1];
        float invs = 1.f / fmaxf(w0 + w1, 1e-6f);
        g_topE[2 * gwarp] = i0; g_topE[2 * gwarp + 1] = i1;
        g_topW[2 * gwarp] = w0 * invs; g_topW[2 * gwarp + 1] = w1 * invs;
        g_sgate[gwarp] = 1.f / (1.f + expf(-acc[8]));
        atomicAdd(&g_counts[i0], 1);
        atomicAdd(&g_counts[i1], 1);
        if (write_logits) {
#pragma unroll
            for (int e = 0; e < E_NUM; ++e)
                logits_out[(size_t)gwarp * E_NUM + e] = acc[e];
        }
    }
}

__global__ void scan_kernel() {
    if (threadIdx.x == 0) {
        int s = 0;
        for (int e = 0; e < E_NUM; ++e) {
            g_offs[e] = s;
            int tl = (g_counts[e] + 127) >> 7;
            for (int t = 0; t < tl; ++t) g_tileExpert[(s >> 7) + t] = e;
            s += tl << 7;
        }
    }
}

__global__ void gather_kernel(int T) {
    int t = blockIdx.x * blockDim.x + threadIdx.x;
    if (t >= T) return;
#pragma unroll
    for (int k = 0; k < 2; ++k) {
        int e = g_topE[2 * t + k];
        int p = atomicAdd(&g_fill[e], 1);
        int row = g_offs[e] + p;
        g_gatherTok[row] = t;
        g_rowW[row] = g_topW[2 * t + k];
    }
}

__global__ void convx_kernel(const float* __restrict__ x, __half* __restrict__ xo, int n2) {
    int i = blockIdx.x * blockDim.x + threadIdx.x;
    if (i >= n2) return;
    float2 v = ((const float2*)x)[i];
    ((__half2*)xo)[i] = __floats2half2_rn(v.x, v.y);
}

// weights: src[e][k][n] fp32 -> dst[e][n*rowMul+rowAdd][k] fp16 (k-major rows)
__global__ __launch_bounds__(256)
void wtrans_kernel(const float* __restrict__ src, __half* __restrict__ dst,
                   int Ks, int Ns, long long srcE, long long dstE,
                   int rowMul, int rowAdd) {
    src += (long long)blockIdx.z * srcE;
    dst += (long long)blockIdx.z * dstE;
    int tk0 = blockIdx.y * 32, tn0 = blockIdx.x * 32;
    __shared__ float tile[32][33];
    int tx = threadIdx.x & 31, ty = threadIdx.x >> 5;
#pragma unroll
    for (int r = 0; r < 4; ++r) {
        int k = ty + r * 8;
        tile[k][tx] = src[(long long)(tk0 + k) * Ns + tn0 + tx];
    }
    __syncthreads();
    int kk = (threadIdx.x & 7) * 4;
    int nn = threadIdx.x >> 3;
    long long drow = (long long)((tn0 + nn) * rowMul + rowAdd) * Ks + tk0 + kk;
    __align__(8) unsigned short hv[4];
#pragma unroll
    for (int q = 0; q < 4; ++q)
        hv[q] = __half_as_ushort(__float2half(tile[kk + q][nn]));
    *(uint2*)(dst + drow) = *(uint2*)hv;
}

// ---------------- HMMA fp16 GEMM ----------------
// CTA tile 128x128, BK=64, 3-stage cp.async pipeline, 128 threads
// (4 warps 2x2, warp tile 64x64), 2 CTAs/SM. fp32 accumulate.
// MODE 1: adjacent cols (even=gate, odd=up) -> silu(g)*u -> fp16 plane H
// MODE 2: fused combine: red.global.add out[tok*Nout+col] += w*acc
//         (tok via oTok[row] or row; w via rowW[row]; pad rows have w=0)
template <int MODE>
__global__ __launch_bounds__(128, 2)
void hgemm(const __half* __restrict__ A, const __half* __restrict__ B,
           long long bStride, float* __restrict__ Cf, __half* __restrict__ H,
           const int* __restrict__ gTok,   // loader A-row gather (or null)
           const int* __restrict__ oTok,   // epilogue row->token (or null)
           const float* __restrict__ rowW, // epilogue row weight (MODE 2)
           const int* __restrict__ tileE,
           int K, int Nout) {
    int e = 0;
    if (tileE) { e = tileE[blockIdx.y]; if (e < 0) return; }
    int rowbase = blockIdx.y * 128;
    int bn = blockIdx.x * 128;
    const char* pA = (const char*)A;
    const char* pB = (const char*)(B + (long long)e * bStride);

    extern __shared__ __align__(1024) char smem[];
    uint32_t sb = smem_u32(smem);
    int tid = threadIdx.x;

    // loader precompute: A 8 chunks + B 8 chunks per thread (16B each)
    uint32_t aB[8], bB[8], dA[8], dB[8];
#pragma unroll
    for (int i = 0; i < 8; ++i) {
        int q = tid + 128 * i, r = q >> 3, c8 = q & 7;
        int ar = rowbase + r;
        int tok = gTok ? gTok[ar] : ar;
        aB[i] = (uint32_t)((tok * K + c8 * 8) * 2);
        dA[i] = swz64(r, c8);
        bB[i] = (uint32_t)(((bn + r) * K + c8 * 8) * 2);
        dB[i] = 16384 + swz64(r, c8);
    }
    auto issue = [&](int s, int c) {
        uint32_t st = sb + s * STAGE_SZ;
        uint32_t off = (uint32_t)c * 128;
#pragma unroll
        for (int i = 0; i < 8; ++i) cpa16(st + dA[i], pA + aB[i] + off);
#pragma unroll
        for (int i = 0; i < 8; ++i) cpa16(st + dB[i], pB + bB[i] + off);
    };

    // compute precompute: h-indexed bases; mi/np folded as +2048*idx
    int lane = tid & 31, w = tid >> 5;
    int wm = (w & 1) * 64, wn = (w >> 1) * 64;
    uint32_t aA0[4], aB0[4];
    {
        int rowA = wm + (lane & 15);
        int rowB = wn + (lane & 7) + ((lane >> 4) << 3);
#pragma unroll
        for (int h = 0; h < 4; ++h) {
            aA0[h] = swz64(rowA, 2 * h + (lane >> 4));
            aB0[h] = 16384 + swz64(rowB, 2 * h + ((lane >> 3) & 1));
        }
    }

    float acc[4][8][4];
#pragma unroll
    for (int mi = 0; mi < 4; ++mi)
#pragma unroll
        for (int nj = 0; nj < 8; ++nj)
#pragma unroll
            for (int q = 0; q < 4; ++q) acc[mi][nj][q] = 0.f;

    int NC = K >> 6;

    issue(0, 0); CP_COMMIT();
    issue(1, 1); CP_COMMIT();

    int s = 0, ps = 2;
    for (int c = 0; c < NC; ++c) {
        CP_WAIT1();
        __syncthreads();
        int pf = c + 2;
        if (pf < NC) issue(ps, pf);
        CP_COMMIT();
        uint32_t st = sb + s * STAGE_SZ;
#pragma unroll
        for (int h = 0; h < 4; ++h) {
            uint32_t a[4][4], b[8][2];
#pragma unroll
            for (int mi = 0; mi < 4; ++mi) LDSM4(a[mi], st + aA0[h] + mi * 2048);
#pragma unroll
            for (int np = 0; np < 4; ++np) {
                uint32_t q[4];
                LDSM4(q, st + aB0[h] + np * 2048);
                b[2 * np][0] = q[0]; b[2 * np][1] = q[1];
                b[2 * np + 1][0] = q[2]; b[2 * np + 1][1] = q[3];
            }
#pragma unroll
            for (int mi = 0; mi < 4; ++mi)
#pragma unroll
                for (int nj = 0; nj < 8; ++nj)
                    MMAF16(acc[mi][nj], a[mi], b[nj][0], b[nj][1]);
        }
        s = (s == 2) ? 0 : s + 1;
        ps = (ps == 2) ? 0 : ps + 1;
    }

    // epilogue
#pragma unroll
    for (int mi = 0; mi < 4; ++mi) {
        int rA = rowbase + wm + mi * 16 + (lane >> 2);
        int rB = rA + 8;
        if (MODE == 1) {
#pragma unroll
            for (int nj = 0; nj < 8; ++nj) {
                int oc = ((bn + wn) >> 1) + nj * 4 + (lane & 3);
                float g0 = acc[mi][nj][0], u0 = acc[mi][nj][1];
                float g1 = acc[mi][nj][2], u1 = acc[mi][nj][3];
                float v0 = g0 / (1.f + expf(-g0)) * u0;
                float v1 = g1 / (1.f + expf(-g1)) * u1;
                H[(size_t)rA * Nout + oc] = __float2half(v0);
                H[(size_t)rB * Nout + oc] = __float2half(v1);
            }
        } else { // MODE 2: fused weighted scatter-add into out
            int tokA = oTok ? oTok[rA] : rA;
            int tokB = oTok ? oTok[rB] : rB;
            float wA = rowW[rA], wB = rowW[rB];
            float* oA = Cf + (size_t)tokA * Nout;
            float* oB = Cf + (size_t)tokB * Nout;
#pragma unroll
            for (int nj = 0; nj < 8; ++nj) {
                int col = bn + wn + nj * 8 + (lane & 3) * 2;
                redadd(oA + col,     wA * acc[mi][nj][0]);
                redadd(oA + col + 1, wA * acc[mi][nj][1]);
                redadd(oB + col,     wB * acc[mi][nj][2]);
                redadd(oB + col + 1, wB * acc[mi][nj][3]);
            }
        }
    }
}

// ---------------- launcher: 4-stream fork/join, fused-combine leaves ----------------
// Streams/events created ONCE and reused (per-call creation tripped the
// device-memory guard in R9). Fallback: all on stream 0 in sequentially
// correct order.
static cudaStream_t s_sA = 0, s_sB = 0, s_sC = 0;
static cudaEvent_t s_evRoot = 0, s_evX = 0, s_evWsh = 0, s_evMeta = 0,
                   s_evW = 0, s_evZ = 0, s_evA = 0, s_evB = 0, s_evC = 0;
static int s_init_state = 0;

extern "C" void kernel_launch(void* const* d_in, const int* in_sizes, int n_in,
                              void* d_out, int out_size) {
    const float* x   = (const float*)d_in[0];
    const float* gw  = (const float*)d_in[1];
    const float* eg  = (const float*)d_in[2];
    const float* eu  = (const float*)d_in[3];
    const float* ed  = (const float*)d_in[4];
    const float* sg  = (const float*)d_in[5];
    const float* su  = (const float*)d_in[6];
    const float* sd  = (const float*)d_in[7];
    const float* sgw = (const float*)d_in[8];
    float* out = (float*)d_out;
    int T = in_sizes[0] / D_DIM;
    int Th = T / 2;

    __half *xs, *hh, *hs, *bgu, *bd, *bgsh, *bdsh;
    int *gtok, *tileE;
    float *roww, *sgate;
    cudaGetSymbolAddress((void**)&xs, g_xs);
    cudaGetSymbolAddress((void**)&hh, g_h);
    cudaGetSymbolAddress((void**)&hs, g_hs);
    cudaGetSymbolAddress((void**)&bgu, g_Bgu);
    cudaGetSymbolAddress((void**)&bd, g_Bd);
    cudaGetSymbolAddress((void**)&bgsh, g_Bgsh);
    cudaGetSymbolAddress((void**)&bdsh, g_Bdsh);
    cudaGetSymbolAddress((void**)&gtok, g_gatherTok);
    cudaGetSymbolAddress((void**)&roww, g_rowW);
    cudaGetSymbolAddress((void**)&sgate, g_sgate);
    cudaGetSymbolAddress((void**)&tileE, g_tileExpert);

    cudaFuncSetAttribute(hgemm<1>, cudaFuncAttributeMaxDynamicSharedMemorySize, SMEM_SZ);
    cudaFuncSetAttribute(hgemm<2>, cudaFuncAttributeMaxDynamicSharedMemorySize, SMEM_SZ);

    int write_logits = (out_size > T * D_DIM) ? 1 : 0;
    float* logits_out = out + (size_t)T * D_DIM;

    if (s_init_state == 0) {
        bool o = true;
        o = o && (cudaStreamCreateWithFlags(&s_sA, cudaStreamNonBlocking) == cudaSuccess);
        o = o && (cudaStreamCreateWithFlags(&s_sB, cudaStreamNonBlocking) == cudaSuccess);
        o = o && (cudaStreamCreateWithFlags(&s_sC, cudaStreamNonBlocking) == cudaSuccess);
        o = o && (cudaEventCreateWithFlags(&s_evRoot, cudaEventDisableTiming) == cudaSuccess);
        o = o && (cudaEventCreateWithFlags(&s_evX,    cudaEventDisableTiming) == cudaSuccess);
        o = o && (cudaEventCreateWithFlags(&s_evWsh,  cudaEventDisableTiming) == cudaSuccess);
        o = o && (cudaEventCreateWithFlags(&s_evMeta, cudaEventDisableTiming) == cudaSuccess);
        o = o && (cudaEventCreateWithFlags(&s_evW,    cudaEventDisableTiming) == cudaSuccess);
        o = o && (cudaEventCreateWithFlags(&s_evZ,    cudaEventDisableTiming) == cudaSuccess);
        o = o && (cudaEventCreateWithFlags(&s_evA,    cudaEventDisableTiming) == cudaSuccess);
        o = o && (cudaEventCreateWithFlags(&s_evB,    cudaEventDisableTiming) == cudaSuccess);
        o = o && (cudaEventCreateWithFlags(&s_evC,    cudaEventDisableTiming) == cudaSuccess);
        s_init_state = o ? 1 : -1;
    }
    bool ok = (s_init_state == 1);
    cudaStream_t sA = ok ? s_sA : 0, sB = ok ? s_sB : 0, sC = ok ? s_sC : 0;

    if (ok) {
        cudaEventRecord(s_evRoot, 0);
        cudaStreamWaitEvent(sA, s_evRoot, 0);
        cudaStreamWaitEvent(sB, s_evRoot, 0);
        cudaStreamWaitEvent(sC, s_evRoot, 0);
    }

    // ---- s0: zero output token region (REDG target) ----
    zero_out_kernel<<<(T * D_DIM / 4 + 255) / 256, 256>>>((float4*)out, T * D_DIM / 4);
    if (ok) cudaEventRecord(s_evZ, 0);

    // ---- sA: convx ----
    convx_kernel<<<(T * D_DIM / 2 + 255) / 256, 256, 0, sA>>>(x, xs, T * D_DIM / 2);
    if (ok) cudaEventRecord(s_evX, sA);

    // ---- sB: MoE metadata chain ----
    zero_meta_kernel<<<(MAXROWS + 255) / 256, 256, 0, sB>>>();
    router_kernel<<<(T * 32 + 255) / 256, 256, 0, sB>>>(x, gw, sgw, logits_out,
                                                        write_logits, T);
    scan_kernel<<<1, 32, 0, sB>>>();
    gather_kernel<<<(T + 255) / 256, 256, 0, sB>>>(T);
    if (ok) cudaEventRecord(s_evMeta, sB);

    // ---- sA: shared-expert weight transposes ----
    wtrans_kernel<<<dim3(ISH / 32, D_DIM / 32, 1), 256, 0, sA>>>(
        sg, bgsh, D_DIM, ISH, 0, 0, 2, 0);
    wtrans_kernel<<<dim3(ISH / 32, D_DIM / 32, 1), 256, 0, sA>>>(
        su, bgsh, D_DIM, ISH, 0, 0, 2, 1);
    wtrans_kernel<<<dim3(D_DIM / 32, ISH / 32, 1), 256, 0, sA>>>(
        sd, bdsh, ISH, D_DIM, 0, 0, 1, 0);
    if (ok) cudaEventRecord(s_evWsh, sA);

    // ---- s0: MoE weight transposes ----
    wtrans_kernel<<<dim3(IMOE / 32, D_DIM / 32, E_NUM), 256>>>(
        eg, bgu, D_DIM, IMOE, (long long)D_DIM * IMOE, 2LL * IMOE * D_DIM, 2, 0);
    wtrans_kernel<<<dim3(IMOE / 32, D_DIM / 32, E_NUM), 256>>>(
        eu, bgu, D_DIM, IMOE, (long long)D_DIM * IMOE, 2LL * IMOE * D_DIM, 2, 1);
    wtrans_kernel<<<dim3(D_DIM / 32, IMOE / 32, E_NUM), 256>>>(
        ed, bd, IMOE, D_DIM, (long long)IMOE * D_DIM, (long long)D_DIM * IMOE, 1, 0);
    if (ok) cudaEventRecord(s_evW, 0);

    // ---- GU GEMMs (4 half-chains, tile N=128, 128 threads) ----
    hgemm<1><<<dim3(2 * ISH / 128, Th / 128), 128, SMEM_SZ, sA>>>(
        xs, bgsh, 0, nullptr, hs, nullptr, nullptr, nullptr, nullptr, D_DIM, ISH);
    if (ok) cudaStreamWaitEvent(sC, s_evWsh, 0);   // implies convx done (sA order)
    hgemm<1><<<dim3(2 * ISH / 128, Th / 128), 128, SMEM_SZ, sC>>>(
        xs + (size_t)Th * D_DIM, bgsh, 0, nullptr, hs + (size_t)Th * ISH,
        nullptr, nullptr, nullptr, nullptr, D_DIM, ISH);
    if (ok) { cudaStreamWaitEvent(0, s_evMeta, 0); cudaStreamWaitEvent(0, s_evX, 0); }
    hgemm<1><<<dim3(2 * IMOE / 128, HTILES), 128, SMEM_SZ>>>(
        xs, bgu, 2LL * IMOE * D_DIM, nullptr, hh, gtok, nullptr, nullptr,
        tileE, D_DIM, IMOE);
    if (ok) { cudaStreamWaitEvent(sB, s_evW, 0); cudaStreamWaitEvent(sB, s_evX, 0); }
    hgemm<1><<<dim3(2 * IMOE / 128, HTILES), 128, SMEM_SZ, sB>>>(
        xs, bgu, 2LL * IMOE * D_DIM, nullptr, hh + (size_t)HTILES * 128 * IMOE,
        gtok + HTILES * 128, nullptr, nullptr, tileE + HTILES, D_DIM, IMOE);

    // ---- down GEMMs (4 half-chains, fused weighted scatter-add into out) ----
    if (ok) cudaStreamWaitEvent(sA, s_evZ, 0);
    hgemm<2><<<dim3(D_DIM / 128, Th / 128), 128, SMEM_SZ, sA>>>(
        hs, bdsh, 0, out, nullptr, nullptr, nullptr, sgate, nullptr, ISH, D_DIM);
    if (ok) cudaEventRecord(s_evA, sA);
    if (ok) cudaStreamWaitEvent(sC, s_evZ, 0);
    hgemm<2><<<dim3(D_DIM / 128, Th / 128), 128, SMEM_SZ, sC>>>(
        hs + (size_t)Th * ISH, bdsh, 0, out + (size_t)Th * D_DIM, nullptr,
        nullptr, nullptr, sgate + Th, nullptr, ISH, D_DIM);
    if (ok) cudaEventRecord(s_evC, sC);
    hgemm<2><<<dim3(D_DIM / 128, HTILES), 128, SMEM_SZ>>>(
        hh, bd, (long long)D_DIM * IMOE, out, nullptr,
        nullptr, gtok, roww, tileE, IMOE, D_DIM);
    if (ok) cudaStreamWaitEvent(sB, s_evZ, 0);
    hgemm<2><<<dim3(D_DIM / 128, HTILES), 128, SMEM_SZ, sB>>>(
        hh + (size_t)HTILES * 128 * IMOE, bd, (long long)D_DIM * IMOE, out, nullptr,
        nullptr, gtok + HTILES * 128, roww + HTILES * 128, tileE + HTILES,
        IMOE, D_DIM);
    if (ok) cudaEventRecord(s_evB, sB);

    // ---- join back to s0 (graph-capture requires rejoining side streams) ----
    if (ok) {
        cudaStreamWaitEvent(0, s_evA, 0);
        cudaStreamWaitEvent(0, s_evB, 0);
        cudaStreamWaitEvent(0, s_evC, 0);
    }
    fin_kernel<<<1, 32>>>();
}